// round 1
// baseline (speedup 1.0000x reference)
#include <cuda_runtime.h>
#include <cuda_bf16.h>
#include <math.h>
#include <stdint.h>

// ---------------- static scratch (no allocations allowed) ----------------
#define MAXN 131072
#define DD 256
__device__ float g_x  [(size_t)MAXN * DD];   // reused: preLN out -> ln out -> xo
__device__ float g_xs [(size_t)MAXN * DD];   // serialized features (residual stream)
__device__ float g_qkv[(size_t)MAXN * 768];  // qkv -> mlp hidden -> gate
__device__ float g_o  [(size_t)MAXN * DD];   // attn out -> gg hidden -> fuse hidden/out
__device__ float g_key[MAXN];
__device__ int   g_idx[MAXN];
__device__ float g_gt [4 * DD];
__device__ float g_ggb[4 * DD];
__device__ float g_fb [4 * DD];
__device__ float g_stats[4 * 12];

// ---------------- per-cloud coord stats ----------------
__global__ void stats_kernel(const float* __restrict__ coord, float* __restrict__ stats, int Lc) {
    int c = blockIdx.x, tid = threadIdx.x;
    float sum[3] = {0,0,0}, mn[3] = {1e30f,1e30f,1e30f}, mx[3] = {-1e30f,-1e30f,-1e30f};
    for (int i = tid; i < Lc; i += blockDim.x) {
        const float* cp = coord + (size_t)(c * Lc + i) * 3;
        #pragma unroll
        for (int d = 0; d < 3; d++) {
            float v = cp[d];
            sum[d] += v; mn[d] = fminf(mn[d], v); mx[d] = fmaxf(mx[d], v);
        }
    }
    __shared__ float red[1024];
    for (int d = 0; d < 3; d++) {
        red[tid] = sum[d]; __syncthreads();
        for (int s = 512; s > 0; s >>= 1) { if (tid < s) red[tid] += red[tid + s]; __syncthreads(); }
        float tot = red[0]; __syncthreads();
        red[tid] = mn[d]; __syncthreads();
        for (int s = 512; s > 0; s >>= 1) { if (tid < s) red[tid] = fminf(red[tid], red[tid + s]); __syncthreads(); }
        float tmn = red[0]; __syncthreads();
        red[tid] = mx[d]; __syncthreads();
        for (int s = 512; s > 0; s >>= 1) { if (tid < s) red[tid] = fmaxf(red[tid], red[tid + s]); __syncthreads(); }
        float tmx = red[0]; __syncthreads();
        if (tid == 0) {
            float mean = tot / (float)Lc;
            stats[c*12 + d]     = mean;
            stats[c*12 + 3 + d] = fmaxf(fmaxf(tmx - mean, mean - tmn), 1e-6f);
            stats[c*12 + 6 + d] = tmn;
            stats[c*12 + 9 + d] = 1.f / fmaxf(tmx - tmn, 1e-6f);
        }
        __syncthreads();
    }
}

// ---------------- PE + pre-LN + serialization key ----------------
__global__ void __launch_bounds__(256) pe_ln_key_kernel(
    const float* __restrict__ feats, const float* __restrict__ coord,
    const float* __restrict__ w1, const float* __restrict__ b1,
    const float* __restrict__ w2, const float* __restrict__ b2,
    const float* __restrict__ g, const float* __restrict__ beta,
    const float* __restrict__ stats,
    float* __restrict__ xout, float* __restrict__ key, int* __restrict__ idx, int Lc)
{
    int i = blockIdx.x, tid = threadIdx.x;
    int c = i / Lc;
    __shared__ float hid[64];
    __shared__ float red[256];
    const float* st = stats + c * 12;
    float c0 = coord[(size_t)i*3+0], c1 = coord[(size_t)i*3+1], c2 = coord[(size_t)i*3+2];
    if (tid < 64) {
        float n0 = (c0 - st[0]) / st[3];
        float n1 = (c1 - st[1]) / st[4];
        float n2 = (c2 - st[2]) / st[5];
        float hv = b1[tid] + n0 * w1[tid] + n1 * w1[64 + tid] + n2 * w1[128 + tid];
        hid[tid] = fmaxf(hv, 0.f);
    }
    if (tid == 0) {
        float k0 = (c0 - st[6]) * st[9];
        float k1 = (c1 - st[7]) * st[10];
        float k2 = (c2 - st[8]) * st[11];
        key[i] = k0 + 2.17f * k1 + 3.31f * k2;
        idx[i] = i;
    }
    __syncthreads();
    float pe = b2[tid];
    #pragma unroll 8
    for (int h = 0; h < 64; h++) pe += hid[h] * w2[h * 256 + tid];
    float v = feats[(size_t)i * 256 + tid] + pe;
    red[tid] = v; __syncthreads();
    for (int s = 128; s > 0; s >>= 1) { if (tid < s) red[tid] += red[tid + s]; __syncthreads(); }
    float mean = red[0] * (1.f / 256.f); __syncthreads();
    float dv = v - mean;
    red[tid] = dv * dv; __syncthreads();
    for (int s = 128; s > 0; s >>= 1) { if (tid < s) red[tid] += red[tid + s]; __syncthreads(); }
    float var = red[0] * (1.f / 256.f);
    xout[(size_t)i * 256 + tid] = dv * rsqrtf(var + 1e-5f) * g[tid] + beta[tid];
}

// ---------------- per-cloud bitonic sort of (key, idx) ----------------
__global__ void __launch_bounds__(1024) sort_kernel(float* __restrict__ key, int* __restrict__ idx, int Lc) {
    int c = blockIdx.x, tid = threadIdx.x;
    size_t base = (size_t)c * Lc;
    for (int k = 2; k <= Lc; k <<= 1) {
        for (int j = k >> 1; j > 0; j >>= 1) {
            for (int i = tid; i < Lc; i += blockDim.x) {
                int ixj = i ^ j;
                if (ixj > i) {
                    bool up = ((i & k) == 0);
                    float a = key[base + i], b = key[base + ixj];
                    int ia = idx[base + i], ib = idx[base + ixj];
                    bool sw = up ? (a > b || (a == b && ia > ib))
                                 : (a < b || (a == b && ia < ib));
                    if (sw) {
                        key[base + i] = b; key[base + ixj] = a;
                        idx[base + i] = ib; idx[base + ixj] = ia;
                    }
                }
            }
            __syncthreads();
        }
    }
}

// ---------------- gather / scatter rows ----------------
__global__ void gather_kernel(const float* __restrict__ src, float* __restrict__ dst, const int* __restrict__ idx) {
    int p = blockIdx.x, tid = threadIdx.x;
    dst[(size_t)p * 256 + tid] = src[(size_t)idx[p] * 256 + tid];
}
__global__ void scatter_kernel(const float* __restrict__ src, float* __restrict__ dst, const int* __restrict__ idx) {
    int p = blockIdx.x, tid = threadIdx.x;
    dst[(size_t)idx[p] * 256 + tid] = src[(size_t)p * 256 + tid];
}

// ---------------- LayerNorm (256-wide rows) ----------------
__global__ void __launch_bounds__(256) ln_kernel(const float* __restrict__ x, const float* __restrict__ g,
                                                 const float* __restrict__ b, float* __restrict__ y) {
    int row = blockIdx.x, tid = threadIdx.x;
    __shared__ float red[256];
    float v = x[(size_t)row * 256 + tid];
    red[tid] = v; __syncthreads();
    for (int s = 128; s > 0; s >>= 1) { if (tid < s) red[tid] += red[tid + s]; __syncthreads(); }
    float mean = red[0] * (1.f / 256.f); __syncthreads();
    float dv = v - mean;
    red[tid] = dv * dv; __syncthreads();
    for (int s = 128; s > 0; s >>= 1) { if (tid < s) red[tid] += red[tid + s]; __syncthreads(); }
    float var = red[0] * (1.f / 256.f);
    y[(size_t)row * 256 + tid] = dv * rsqrtf(var + 1e-5f) * g[tid] + b[tid];
}

// ---------------- generic tiled GEMM with fused epilogues ----------------
// C[M,Nc] = epi(A[M,K] @ W[K,Nc] + bias)
// epi: 0 none, 1 relu, 2 gelu(exact), 3 sigmoid, 4 +resid, 5 resid + gate*val
#define BM 64
#define BN 64
#define BK 32
__global__ void __launch_bounds__(256) gemm_ep(
    const float* __restrict__ A, const float* __restrict__ W,
    const float* __restrict__ bias, const float* __restrict__ resid,
    const float* __restrict__ gate, float* __restrict__ C,
    int M, int Ncols, int K, int cloudLen, int epi)
{
    __shared__ float As[BK][BM + 4];
    __shared__ float Bs[BK][BN];
    int tid = threadIdx.x;
    int m0 = blockIdx.y * BM, n0 = blockIdx.x * BN;
    int tx = tid & 15, ty = tid >> 4;
    float acc[4][4] = {};
    for (int k0 = 0; k0 < K; k0 += BK) {
        #pragma unroll
        for (int it = 0; it < 2; it++) {
            int li = tid + it * 256;
            int row = li >> 3, c4 = li & 7;
            float4 v = *(const float4*)(A + (size_t)(m0 + row) * K + k0 + c4 * 4);
            As[c4*4+0][row] = v.x; As[c4*4+1][row] = v.y;
            As[c4*4+2][row] = v.z; As[c4*4+3][row] = v.w;
        }
        #pragma unroll
        for (int it = 0; it < 2; it++) {
            int li = tid + it * 256;
            int row = li >> 4, c4 = li & 15;
            float4 v = *(const float4*)(W + (size_t)(k0 + row) * Ncols + n0 + c4 * 4);
            *(float4*)&Bs[row][c4 * 4] = v;
        }
        __syncthreads();
        #pragma unroll
        for (int k = 0; k < BK; k++) {
            float a0 = As[k][ty*4+0], a1 = As[k][ty*4+1], a2 = As[k][ty*4+2], a3 = As[k][ty*4+3];
            float4 b = *(float4*)&Bs[k][tx * 4];
            acc[0][0] += a0*b.x; acc[0][1] += a0*b.y; acc[0][2] += a0*b.z; acc[0][3] += a0*b.w;
            acc[1][0] += a1*b.x; acc[1][1] += a1*b.y; acc[1][2] += a1*b.z; acc[1][3] += a1*b.w;
            acc[2][0] += a2*b.x; acc[2][1] += a2*b.y; acc[2][2] += a2*b.z; acc[2][3] += a2*b.w;
            acc[3][0] += a3*b.x; acc[3][1] += a3*b.y; acc[3][2] += a3*b.z; acc[3][3] += a3*b.w;
        }
        __syncthreads();
    }
    #pragma unroll
    for (int i = 0; i < 4; i++) {
        int m = m0 + ty * 4 + i;
        const float* bp = (cloudLen > 0) ? (bias + (size_t)(m / cloudLen) * Ncols) : bias;
        #pragma unroll
        for (int j = 0; j < 4; j++) {
            int n = n0 + tx * 4 + j;
            float v = acc[i][j] + bp[n];
            size_t o = (size_t)m * Ncols + n;
            switch (epi) {
                case 1: v = fmaxf(v, 0.f); break;
                case 2: v = 0.5f * v * (1.f + erff(v * 0.70710678118f)); break;
                case 3: v = 1.f / (1.f + __expf(-v)); break;
                case 4: v += resid[o]; break;
                case 5: v = resid[o] + gate[o] * v; break;
                default: break;
            }
            C[o] = v;
        }
    }
}

// ---------------- per-(patch,head) attention, online softmax ----------------
__global__ void __launch_bounds__(256) attn_kernel(const float* __restrict__ qkv, float* __restrict__ o) {
    extern __shared__ float sm[];
    float* ks = sm;            // [256][32]
    float* vs = sm + 256 * 32; // [256][32]
    int p = blockIdx.x, h = blockIdx.y, tid = threadIdx.x;
    size_t base = (size_t)p * 256;
    const float* qr = qkv + (base + tid) * 768 + h * 32;
    float q[32];
    #pragma unroll
    for (int d4 = 0; d4 < 8; d4++) {
        float4 v = *(const float4*)(qr + d4 * 4);
        q[d4*4+0] = v.x; q[d4*4+1] = v.y; q[d4*4+2] = v.z; q[d4*4+3] = v.w;
        float4 kv = *(const float4*)(qkv + (base + tid) * 768 + 256 + h * 32 + d4 * 4);
        *(float4*)&ks[tid * 32 + d4 * 4] = kv;
        float4 vv = *(const float4*)(qkv + (base + tid) * 768 + 512 + h * 32 + d4 * 4);
        *(float4*)&vs[tid * 32 + d4 * 4] = vv;
    }
    __syncthreads();
    float m = -1e30f, l = 0.f;
    float acc[32];
    #pragma unroll
    for (int d = 0; d < 32; d++) acc[d] = 0.f;
    for (int j = 0; j < 256; j++) {
        const float* kr = &ks[j * 32];
        float s = 0.f;
        #pragma unroll
        for (int d = 0; d < 32; d++) s += q[d] * kr[d];
        s *= 0.17677669529663687f; // 1/sqrt(32)
        const float* vr = &vs[j * 32];
        if (s <= m) {
            float pe = __expf(s - m);
            l += pe;
            #pragma unroll
            for (int d = 0; d < 32; d++) acc[d] += pe * vr[d];
        } else {
            float r = __expf(m - s);
            l = l * r + 1.f;
            #pragma unroll
            for (int d = 0; d < 32; d++) acc[d] = acc[d] * r + vr[d];
            m = s;
        }
    }
    float inv = 1.f / l;
    float* orow = o + (base + tid) * 256 + h * 32;
    #pragma unroll
    for (int d4 = 0; d4 < 8; d4++) {
        float4 v;
        v.x = acc[d4*4+0]*inv; v.y = acc[d4*4+1]*inv; v.z = acc[d4*4+2]*inv; v.w = acc[d4*4+3]*inv;
        *(float4*)(orow + d4 * 4) = v;
    }
}

// ---------------- per-cloud mean of serialized features ----------------
__global__ void gt_reduce_kernel(const float* __restrict__ xs, float* __restrict__ gt, int Lc) {
    int c = blockIdx.x, chunk = blockIdx.y, tid = threadIdx.x;
    int rows = (Lc + gridDim.y - 1) / gridDim.y;
    int r0 = chunk * rows;
    int r1 = min(r0 + rows, Lc);
    float acc = 0.f;
    for (int r = r0; r < r1; r++) acc += xs[((size_t)c * Lc + r) * 256 + tid];
    atomicAdd(&gt[c * 256 + tid], acc);
}

// ---------------- fold gt half of the concat-GEMMs into per-cloud biases ----------------
__global__ void cloudbias_kernel(const float* __restrict__ gtsum,
                                 const float* __restrict__ gg_w1, const float* __restrict__ gg_b1,
                                 const float* __restrict__ f_w1, const float* __restrict__ f_b1,
                                 float* __restrict__ ggb, float* __restrict__ fb, int Lc) {
    int c = blockIdx.x, j = threadIdx.x;
    float s1 = gg_b1[j], s2 = f_b1[j];
    float invL = 1.f / (float)Lc;
    for (int h = 0; h < 256; h++) {
        float gv = gtsum[c * 256 + h] * invL;
        s1 += gv * gg_w1[(size_t)(256 + h) * 256 + j];
        s2 += gv * f_w1[(size_t)(256 + h) * 256 + j];
    }
    ggb[c * 256 + j] = s1;
    fb[c * 256 + j] = s2;
}

// ---------------- launch ----------------
extern "C" void kernel_launch(void* const* d_in, const int* in_sizes, int n_in,
                              void* d_out, int out_size) {
    const float* feats = (const float*)d_in[0];
    const float* coord = (const float*)d_in[1];
    // d_in[2]: lengths (all equal)
    const float* pe_w1 = (const float*)d_in[3];
    const float* pe_b1 = (const float*)d_in[4];
    const float* pe_w2 = (const float*)d_in[5];
    const float* pe_b2 = (const float*)d_in[6];
    const float* pre_g = (const float*)d_in[7];
    const float* pre_b = (const float*)d_in[8];
    const float* n1_g  = (const float*)d_in[9];
    const float* n1_b  = (const float*)d_in[10];
    const float* wqkv  = (const float*)d_in[11];
    const float* bqkv  = (const float*)d_in[12];
    const float* wo    = (const float*)d_in[13];
    const float* bo    = (const float*)d_in[14];
    const float* n2_g  = (const float*)d_in[15];
    const float* n2_b  = (const float*)d_in[16];
    const float* m_w1  = (const float*)d_in[17];
    const float* m_b1  = (const float*)d_in[18];
    const float* m_w2  = (const float*)d_in[19];
    const float* m_b2  = (const float*)d_in[20];
    const float* gg_w1 = (const float*)d_in[21];
    const float* gg_b1 = (const float*)d_in[22];
    const float* gg_w2 = (const float*)d_in[23];
    const float* gg_b2 = (const float*)d_in[24];
    const float* f_w1  = (const float*)d_in[25];
    const float* f_b1  = (const float*)d_in[26];
    const float* f_w2  = (const float*)d_in[27];
    const float* f_b2  = (const float*)d_in[28];
    float* out = (float*)d_out;

    int N = in_sizes[0] / 256;
    int B = in_sizes[2];
    int Lc = N / B;
    int patches = N / 256;

    float *p_x, *p_xs, *p_qkv, *p_o, *p_key, *p_gt, *p_ggb, *p_fb, *p_stats;
    int* p_idx;
    cudaGetSymbolAddress((void**)&p_x, g_x);
    cudaGetSymbolAddress((void**)&p_xs, g_xs);
    cudaGetSymbolAddress((void**)&p_qkv, g_qkv);
    cudaGetSymbolAddress((void**)&p_o, g_o);
    cudaGetSymbolAddress((void**)&p_key, g_key);
    cudaGetSymbolAddress((void**)&p_idx, g_idx);
    cudaGetSymbolAddress((void**)&p_gt, g_gt);
    cudaGetSymbolAddress((void**)&p_ggb, g_ggb);
    cudaGetSymbolAddress((void**)&p_fb, g_fb);
    cudaGetSymbolAddress((void**)&p_stats, g_stats);

    cudaFuncSetAttribute(attn_kernel, cudaFuncAttributeMaxDynamicSharedMemorySize, 64 * 1024);

    // 1. per-cloud coord stats
    stats_kernel<<<B, 1024>>>(coord, p_stats, Lc);
    // 2. PE + pre-LN + key
    pe_ln_key_kernel<<<N, 256>>>(feats, coord, pe_w1, pe_b1, pe_w2, pe_b2,
                                 pre_g, pre_b, p_stats, p_x, p_key, p_idx, Lc);
    // 3. per-cloud bitonic sort
    sort_kernel<<<B, 1024>>>(p_key, p_idx, Lc);
    // 4. gather (serialize)
    gather_kernel<<<N, 256>>>(p_x, p_xs, p_idx);
    // 5. LN1
    ln_kernel<<<N, 256>>>(p_xs, n1_g, n1_b, p_x);
    // 6. qkv GEMM
    gemm_ep<<<dim3(768 / BN, N / BM), 256>>>(p_x, wqkv, bqkv, nullptr, nullptr, p_qkv,
                                             N, 768, 256, 0, 0);
    // 7. attention
    attn_kernel<<<dim3(patches, 8), 256, 64 * 1024>>>(p_qkv, p_o);
    // 8. wo GEMM + residual
    gemm_ep<<<dim3(256 / BN, N / BM), 256>>>(p_o, wo, bo, p_xs, nullptr, p_xs,
                                             N, 256, 256, 0, 4);
    // 9. LN2
    ln_kernel<<<N, 256>>>(p_xs, n2_g, n2_b, p_x);
    // 10. MLP1 + gelu
    gemm_ep<<<dim3(512 / BN, N / BM), 256>>>(p_x, m_w1, m_b1, nullptr, nullptr, p_qkv,
                                             N, 512, 256, 0, 2);
    // 11. MLP2 + residual
    gemm_ep<<<dim3(256 / BN, N / BM), 256>>>(p_qkv, m_w2, m_b2, p_xs, nullptr, p_xs,
                                             N, 256, 512, 0, 4);
    // 12. scatter (unserialize) -> xo in p_x
    scatter_kernel<<<N, 256>>>(p_xs, p_x, p_idx);
    // 13. per-cloud mean
    cudaMemsetAsync(p_gt, 0, (size_t)B * 256 * sizeof(float), 0);
    gt_reduce_kernel<<<dim3(B, 32), 256>>>(p_xs, p_gt, Lc);
    // 14. fold gt into per-cloud biases
    cloudbias_kernel<<<B, 256>>>(p_gt, gg_w1, gg_b1, f_w1, f_b1, p_ggb, p_fb, Lc);
    // 15. gate hidden: relu(f @ gg_w1_top + ggb[cloud])
    gemm_ep<<<dim3(256 / BN, N / BM), 256>>>(feats, gg_w1, p_ggb, nullptr, nullptr, p_o,
                                             N, 256, 256, Lc, 1);
    // 16. gate = sigmoid(hidden @ gg_w2 + gg_b2) -> reuse p_qkv
    gemm_ep<<<dim3(256 / BN, N / BM), 256>>>(p_o, gg_w2, gg_b2, nullptr, nullptr, p_qkv,
                                             N, 256, 256, 0, 3);
    // 17. fuse hidden: relu(xo @ f_w1_top + fb[cloud])
    gemm_ep<<<dim3(256 / BN, N / BM), 256>>>(p_x, f_w1, p_fb, nullptr, nullptr, p_o,
                                             N, 256, 256, Lc, 1);
    // 18. out = f + gate * (hidden @ f_w2 + f_b2)
    gemm_ep<<<dim3(256 / BN, N / BM), 256>>>(p_o, f_w2, f_b2, feats, p_qkv, out,
                                             N, 256, 256, 0, 5);
}

// round 3
// speedup vs baseline: 2.3404x; 2.3404x over previous
#include <cuda_runtime.h>
#include <cuda_bf16.h>
#include <math.h>
#include <stdint.h>

// ---------------- static scratch ----------------
#define MAXN 131072
#define DD 256
__device__ float g_x  [(size_t)MAXN * DD];
__device__ float g_xs [(size_t)MAXN * DD];
__device__ float g_qkv[(size_t)MAXN * 768];
__device__ __nv_bfloat16 g_ba[(size_t)MAXN * 512];
__device__ __nv_bfloat16 g_bb[(size_t)MAXN * 512];
__device__ __nv_bfloat16 g_fe[(size_t)MAXN * 256];
__device__ __nv_bfloat16 g_wt[786432];
__device__ float g_key[MAXN];
__device__ int   g_idx[MAXN];
__device__ float g_gt [8 * DD];
__device__ float g_ggb[8 * DD];
__device__ float g_fb [8 * DD];
__device__ float g_stats[8 * 12];

// ---------------- fast math (no MUFU) ----------------
__device__ __forceinline__ float fexpf_fast(float x) {
    x = fmaxf(x, -80.f);
    float y = x * 1.4426950408889634f;
    float n = rintf(y);
    float z = y - n;
    float p = 0.009618129f;
    p = p * z + 0.055504109f;
    p = p * z + 0.240226507f;
    p = p * z + 0.693147181f;
    p = p * z + 1.0f;
    int e = (int)n;
    float s = __int_as_float((e + 127) << 23);
    return p * s;
}
__device__ __forceinline__ float frcp_fast(float d) {
    float y = __int_as_float(0x7ef311c3 - __float_as_int(d));
    y = y * (2.f - d * y);
    y = y * (2.f - d * y);
    y = y * (2.f - d * y);
    return y;
}

// ---------------- per-cloud coord stats ----------------
__global__ void stats_kernel(const float* __restrict__ coord, float* __restrict__ stats, int Lc) {
    int c = blockIdx.x, tid = threadIdx.x;
    float sum[3] = {0,0,0}, mn[3] = {1e30f,1e30f,1e30f}, mx[3] = {-1e30f,-1e30f,-1e30f};
    for (int i = tid; i < Lc; i += blockDim.x) {
        const float* cp = coord + (size_t)(c * Lc + i) * 3;
        #pragma unroll
        for (int d = 0; d < 3; d++) {
            float v = cp[d];
            sum[d] += v; mn[d] = fminf(mn[d], v); mx[d] = fmaxf(mx[d], v);
        }
    }
    __shared__ float red[1024];
    for (int d = 0; d < 3; d++) {
        red[tid] = sum[d]; __syncthreads();
        for (int s = 512; s > 0; s >>= 1) { if (tid < s) red[tid] += red[tid + s]; __syncthreads(); }
        float tot = red[0]; __syncthreads();
        red[tid] = mn[d]; __syncthreads();
        for (int s = 512; s > 0; s >>= 1) { if (tid < s) red[tid] = fminf(red[tid], red[tid + s]); __syncthreads(); }
        float tmn = red[0]; __syncthreads();
        red[tid] = mx[d]; __syncthreads();
        for (int s = 512; s > 0; s >>= 1) { if (tid < s) red[tid] = fmaxf(red[tid], red[tid + s]); __syncthreads(); }
        float tmx = red[0]; __syncthreads();
        if (tid == 0) {
            float mean = tot / (float)Lc;
            stats[c*12 + d]     = mean;
            stats[c*12 + 3 + d] = fmaxf(fmaxf(tmx - mean, mean - tmn), 1e-6f);
            stats[c*12 + 6 + d] = tmn;
            stats[c*12 + 9 + d] = 1.f / fmaxf(tmx - tmn, 1e-6f);
        }
        __syncthreads();
    }
}

// ---------------- PE + pre-LN + serialization key ----------------
__global__ void __launch_bounds__(256) pe_ln_key_kernel(
    const float* __restrict__ feats, const float* __restrict__ coord,
    const float* __restrict__ w1, const float* __restrict__ b1,
    const float* __restrict__ w2, const float* __restrict__ b2,
    const float* __restrict__ g, const float* __restrict__ beta,
    const float* __restrict__ stats,
    float* __restrict__ xout, float* __restrict__ key, int* __restrict__ idx, int Lc)
{
    int i = blockIdx.x, tid = threadIdx.x;
    int c = i / Lc;
    __shared__ float hid[64];
    __shared__ float red[256];
    const float* st = stats + c * 12;
    float c0 = coord[(size_t)i*3+0], c1 = coord[(size_t)i*3+1], c2 = coord[(size_t)i*3+2];
    if (tid < 64) {
        float n0 = (c0 - st[0]) / st[3];
        float n1 = (c1 - st[1]) / st[4];
        float n2 = (c2 - st[2]) / st[5];
        float hv = b1[tid] + n0 * w1[tid] + n1 * w1[64 + tid] + n2 * w1[128 + tid];
        hid[tid] = fmaxf(hv, 0.f);
    }
    if (tid == 0) {
        float k0 = (c0 - st[6]) * st[9];
        float k1 = (c1 - st[7]) * st[10];
        float k2 = (c2 - st[8]) * st[11];
        key[i] = k0 + 2.17f * k1 + 3.31f * k2;
        idx[i] = i;
    }
    __syncthreads();
    float pe = b2[tid];
    #pragma unroll 8
    for (int h = 0; h < 64; h++) pe += hid[h] * w2[h * 256 + tid];
    float v = feats[(size_t)i * 256 + tid] + pe;
    red[tid] = v; __syncthreads();
    for (int s = 128; s > 0; s >>= 1) { if (tid < s) red[tid] += red[tid + s]; __syncthreads(); }
    float mean = red[0] * (1.f / 256.f); __syncthreads();
    float dv = v - mean;
    red[tid] = dv * dv; __syncthreads();
    for (int s = 128; s > 0; s >>= 1) { if (tid < s) red[tid] += red[tid + s]; __syncthreads(); }
    float var = red[0] * (1.f / 256.f);
    xout[(size_t)i * 256 + tid] = dv * rsqrtf(var + 1e-5f) * g[tid] + beta[tid];
}

// ---------------- hierarchical bitonic sort ----------------
#define CHUNK 8192
__global__ void __launch_bounds__(1024) sort_local(float* __restrict__ key, int* __restrict__ idx, int Lc) {
    extern __shared__ char smraw[];
    float* sk = (float*)smraw;
    int*   si = (int*)(smraw + CHUNK * 4);
    size_t gbase = (size_t)blockIdx.x * CHUNK;
    int lbase = (int)(gbase % (size_t)Lc);
    for (int t = threadIdx.x; t < CHUNK; t += 1024) { sk[t] = key[gbase + t]; si[t] = idx[gbase + t]; }
    __syncthreads();
    for (int k = 2; k <= CHUNK; k <<= 1) {
        for (int j = k >> 1; j > 0; j >>= 1) {
            for (int t = threadIdx.x; t < CHUNK / 2; t += 1024) {
                int i = 2 * t - (t & (j - 1));
                int p = i + j;
                bool up = (((lbase + i) & k) == 0);
                float a = sk[i], b = sk[p];
                int ia = si[i], ib = si[p];
                bool sw = up ? (a > b || (a == b && ia > ib)) : (a < b || (a == b && ia < ib));
                if (sw) { sk[i] = b; sk[p] = a; si[i] = ib; si[p] = ia; }
            }
            __syncthreads();
        }
    }
    for (int t = threadIdx.x; t < CHUNK; t += 1024) { key[gbase + t] = sk[t]; idx[gbase + t] = si[t]; }
}

__global__ void __launch_bounds__(1024) merge_local(float* __restrict__ key, int* __restrict__ idx, int k, int Lc) {
    extern __shared__ char smraw[];
    float* sk = (float*)smraw;
    int*   si = (int*)(smraw + CHUNK * 4);
    size_t gbase = (size_t)blockIdx.x * CHUNK;
    int lbase = (int)(gbase % (size_t)Lc);
    for (int t = threadIdx.x; t < CHUNK; t += 1024) { sk[t] = key[gbase + t]; si[t] = idx[gbase + t]; }
    __syncthreads();
    for (int j = CHUNK / 2; j > 0; j >>= 1) {
        for (int t = threadIdx.x; t < CHUNK / 2; t += 1024) {
            int i = 2 * t - (t & (j - 1));
            int p = i + j;
            bool up = (((lbase + i) & k) == 0);
            float a = sk[i], b = sk[p];
            int ia = si[i], ib = si[p];
            bool sw = up ? (a > b || (a == b && ia > ib)) : (a < b || (a == b && ia < ib));
            if (sw) { sk[i] = b; sk[p] = a; si[i] = ib; si[p] = ia; }
        }
        __syncthreads();
    }
    for (int t = threadIdx.x; t < CHUNK; t += 1024) { key[gbase + t] = sk[t]; idx[gbase + t] = si[t]; }
}

__global__ void __launch_bounds__(256) sort_global(float* __restrict__ key, int* __restrict__ idx, int k, int j, int Lc) {
    int c = blockIdx.y;
    size_t base = (size_t)c * Lc;
    int t = blockIdx.x * 256 + threadIdx.x;
    int i = 2 * t - (t & (j - 1));
    int p = i + j;
    bool up = ((i & k) == 0);
    float a = key[base + i], b = key[base + p];
    int ia = idx[base + i], ib = idx[base + p];
    bool sw = up ? (a > b || (a == b && ia > ib)) : (a < b || (a == b && ia < ib));
    if (sw) {
        key[base + i] = b; key[base + p] = a;
        idx[base + i] = ib; idx[base + p] = ia;
    }
}

// ---------------- gather+LN (fp32 resid + bf16 LN out) ----------------
__global__ void __launch_bounds__(256) gather_ln(const float* __restrict__ src, const int* __restrict__ idx,
                                                 const float* __restrict__ g, const float* __restrict__ b,
                                                 float* __restrict__ xs, __nv_bfloat16* __restrict__ hbf) {
    int p = blockIdx.x, tid = threadIdx.x;
    __shared__ float red[256];
    float v = src[(size_t)idx[p] * 256 + tid];
    xs[(size_t)p * 256 + tid] = v;
    red[tid] = v; __syncthreads();
    for (int s = 128; s > 0; s >>= 1) { if (tid < s) red[tid] += red[tid + s]; __syncthreads(); }
    float mean = red[0] * (1.f / 256.f); __syncthreads();
    float dv = v - mean;
    red[tid] = dv * dv; __syncthreads();
    for (int s = 128; s > 0; s >>= 1) { if (tid < s) red[tid] += red[tid + s]; __syncthreads(); }
    float var = red[0] * (1.f / 256.f);
    hbf[(size_t)p * 256 + tid] = __float2bfloat16(dv * rsqrtf(var + 1e-5f) * g[tid] + b[tid]);
}

// ---------------- LN -> bf16 ----------------
__global__ void __launch_bounds__(256) ln_bf(const float* __restrict__ x, const float* __restrict__ g,
                                             const float* __restrict__ b, __nv_bfloat16* __restrict__ y) {
    int row = blockIdx.x, tid = threadIdx.x;
    __shared__ float red[256];
    float v = x[(size_t)row * 256 + tid];
    red[tid] = v; __syncthreads();
    for (int s = 128; s > 0; s >>= 1) { if (tid < s) red[tid] += red[tid + s]; __syncthreads(); }
    float mean = red[0] * (1.f / 256.f); __syncthreads();
    float dv = v - mean;
    red[tid] = dv * dv; __syncthreads();
    for (int s = 128; s > 0; s >>= 1) { if (tid < s) red[tid] += red[tid + s]; __syncthreads(); }
    float var = red[0] * (1.f / 256.f);
    y[(size_t)row * 256 + tid] = __float2bfloat16(dv * rsqrtf(var + 1e-5f) * g[tid] + b[tid]);
}

// ---------------- scatter fp32 -> bf16 ----------------
__global__ void scatter_bf(const float* __restrict__ src, __nv_bfloat16* __restrict__ dst, const int* __restrict__ idx) {
    int p = blockIdx.x, tid = threadIdx.x;
    dst[(size_t)idx[p] * 256 + tid] = __float2bfloat16(src[(size_t)p * 256 + tid]);
}

// ---------------- fp32 -> bf16 elementwise (feats) ----------------
__global__ void f2bf(const float* __restrict__ x, __nv_bfloat16* __restrict__ y, size_t n4) {
    size_t i = (size_t)blockIdx.x * blockDim.x + threadIdx.x;
    if (i >= n4) return;
    float4 v = ((const float4*)x)[i];
    __nv_bfloat162 a; a.x = __float2bfloat16(v.x); a.y = __float2bfloat16(v.y);
    __nv_bfloat162 b; b.x = __float2bfloat16(v.z); b.y = __float2bfloat16(v.w);
    ((__nv_bfloat162*)y)[i * 2 + 0] = a;
    ((__nv_bfloat162*)y)[i * 2 + 1] = b;
}

// ---------------- weight transpose + convert: W[K][N] fp32 -> Wt[N][K] bf16 ----------------
__global__ void wconv(const float* __restrict__ W, __nv_bfloat16* __restrict__ Wt, int K, int Ncols) {
    __shared__ float t[32][33];
    int bx = blockIdx.x * 32, by = blockIdx.y * 32;
    for (int r = threadIdx.y; r < 32; r += 8)
        t[r][threadIdx.x] = W[(size_t)(by + r) * Ncols + bx + threadIdx.x];
    __syncthreads();
    for (int r = threadIdx.y; r < 32; r += 8)
        Wt[(size_t)(bx + r) * K + by + threadIdx.x] = __float2bfloat16(t[threadIdx.x][r]);
}

// ---------------- tensor-core GEMM: C = epi(A[M,K] @ Wt[N,K]^T + bias) ----------------
// epi: 0 none, 1 relu, 2 gelu, 3 sigmoid, 4 +resid, 5 resid + gate*val
__device__ __forceinline__ uint32_t smem_u32(const void* p) {
    return (uint32_t)__cvta_generic_to_shared(p);
}

#define GBM 128
#define GBN 128
#define GKT 32
#define STG_BYTES 20480  // A 10240 + B 10240 per stage

__global__ void __launch_bounds__(256) gemm_bf16(
    const __nv_bfloat16* __restrict__ A,
    const __nv_bfloat16* __restrict__ Bt,
    const float* __restrict__ bias,
    const float* __restrict__ resid,
    const float* __restrict__ gate,
    void* __restrict__ Cout,
    int M, int Ncols, int K, int cloudLen, int epi, int outBf16)
{
    extern __shared__ char smraw[];
    const int tid = threadIdx.x;
    const int lane = tid & 31;
    const int warp = tid >> 5;
    const int wm = warp >> 1, wn = warp & 1;
    const int m0 = blockIdx.y * GBM, n0 = blockIdx.x * GBN;

    float acc[2][8][4];
    #pragma unroll
    for (int i = 0; i < 2; i++)
        #pragma unroll
        for (int j = 0; j < 8; j++)
            #pragma unroll
            for (int q = 0; q < 4; q++) acc[i][j][q] = 0.f;

    const int ldrow0 = tid >> 2, ldc0 = tid & 3;
    const int ldrow1 = (tid + 256) >> 2, ldc1 = tid & 3;

    auto issue = [&](int s, int kt) {
        char* sA = smraw + s * STG_BYTES;
        char* sB = sA + 10240;
        {
            const __nv_bfloat16* gA = A + (size_t)(m0 + ldrow0) * K + kt * GKT + ldc0 * 8;
            uint32_t d = smem_u32(sA + ldrow0 * 80 + ldc0 * 16);
            asm volatile("cp.async.cg.shared.global [%0], [%1], 16;\n" :: "r"(d), "l"(gA));
            const __nv_bfloat16* gB = Bt + (size_t)(n0 + ldrow0) * K + kt * GKT + ldc0 * 8;
            uint32_t d2 = smem_u32(sB + ldrow0 * 80 + ldc0 * 16);
            asm volatile("cp.async.cg.shared.global [%0], [%1], 16;\n" :: "r"(d2), "l"(gB));
        }
        {
            const __nv_bfloat16* gA = A + (size_t)(m0 + ldrow1) * K + kt * GKT + ldc1 * 8;
            uint32_t d = smem_u32(sA + ldrow1 * 80 + ldc1 * 16);
            asm volatile("cp.async.cg.shared.global [%0], [%1], 16;\n" :: "r"(d), "l"(gA));
            const __nv_bfloat16* gB = Bt + (size_t)(n0 + ldrow1) * K + kt * GKT + ldc1 * 8;
            uint32_t d2 = smem_u32(sB + ldrow1 * 80 + ldc1 * 16);
            asm volatile("cp.async.cg.shared.global [%0], [%1], 16;\n" :: "r"(d2), "l"(gB));
        }
        asm volatile("cp.async.commit_group;\n");
    };

    const int nk = K / GKT;
    issue(0, 0);
    for (int kt = 0; kt < nk; kt++) {
        int s = kt & 1;
        if (kt + 1 < nk) {
            issue((kt + 1) & 1, kt + 1);
            asm volatile("cp.async.wait_group 1;\n");
        } else {
            asm volatile("cp.async.wait_group 0;\n");
        }
        __syncthreads();

        char* sA = smraw + s * STG_BYTES;
        char* sB = sA + 10240;
        #pragma unroll
        for (int kk = 0; kk < 2; kk++) {
            uint32_t af[2][4];
            #pragma unroll
            for (int i = 0; i < 2; i++) {
                int r = wm * 32 + i * 16 + (lane & 15);
                int c = kk * 2 + (lane >> 4);
                uint32_t addr = smem_u32(sA + r * 80 + c * 16);
                asm volatile("ldmatrix.sync.aligned.m8n8.x4.shared.b16 {%0,%1,%2,%3}, [%4];"
                             : "=r"(af[i][0]), "=r"(af[i][1]), "=r"(af[i][2]), "=r"(af[i][3])
                             : "r"(addr));
            }
            uint32_t bf[8][2];
            #pragma unroll
            for (int jp = 0; jp < 4; jp++) {
                int r = wn * 64 + jp * 16 + (lane & 15);
                int c = kk * 2 + (lane >> 4);
                uint32_t addr = smem_u32(sB + r * 80 + c * 16);
                uint32_t r0, r1, r2, r3;
                asm volatile("ldmatrix.sync.aligned.m8n8.x4.shared.b16 {%0,%1,%2,%3}, [%4];"
                             : "=r"(r0), "=r"(r1), "=r"(r2), "=r"(r3) : "r"(addr));
                bf[2*jp][0] = r0; bf[2*jp+1][0] = r1;
                bf[2*jp][1] = r2; bf[2*jp+1][1] = r3;
            }
            #pragma unroll
            for (int i = 0; i < 2; i++)
                #pragma unroll
                for (int j = 0; j < 8; j++) {
                    asm volatile("mma.sync.aligned.m16n8k16.row.col.f32.bf16.bf16.f32 "
                                 "{%0,%1,%2,%3}, {%4,%5,%6,%7}, {%8,%9}, {%0,%1,%2,%3};"
                                 : "+f"(acc[i][j][0]), "+f"(acc[i][j][1]),
                                   "+f"(acc[i][j][2]), "+f"(acc[i][j][3])
                                 : "r"(af[i][0]), "r"(af[i][1]), "r"(af[i][2]), "r"(af[i][3]),
                                   "r"(bf[j][0]), "r"(bf[j][1]));
                }
        }
        __syncthreads();
    }

    const int rbase = m0 + wm * 32 + (lane >> 2);
    const int cbase = n0 + wn * 64 + 2 * (lane & 3);
    #pragma unroll
    for (int i = 0; i < 2; i++) {
        #pragma unroll
        for (int half = 0; half < 2; half++) {
            int m = rbase + i * 16 + half * 8;
            const float* bp = (cloudLen > 0) ? (bias + (size_t)(m / cloudLen) * Ncols) : bias;
            #pragma unroll
            for (int j = 0; j < 8; j++) {
                int n = cbase + j * 8;
                float v0 = acc[i][j][half * 2 + 0] + bp[n];
                float v1 = acc[i][j][half * 2 + 1] + bp[n + 1];
                size_t o = (size_t)m * Ncols + n;
                switch (epi) {
                    case 1: v0 = fmaxf(v0, 0.f); v1 = fmaxf(v1, 0.f); break;
                    case 2:
                        v0 = 0.5f * v0 * (1.f + erff(v0 * 0.70710678118f));
                        v1 = 0.5f * v1 * (1.f + erff(v1 * 0.70710678118f));
                        break;
                    case 3:
                        v0 = frcp_fast(1.f + fexpf_fast(-v0));
                        v1 = frcp_fast(1.f + fexpf_fast(-v1));
                        break;
                    case 4: { float2 r = *(const float2*)(resid + o); v0 += r.x; v1 += r.y; } break;
                    case 5: {
                        float2 r = *(const float2*)(resid + o);
                        float2 gg = *(const float2*)(gate + o);
                        v0 = r.x + gg.x * v0; v1 = r.y + gg.y * v1;
                    } break;
                    default: break;
                }
                if (outBf16) {
                    __nv_bfloat162 h;
                    h.x = __float2bfloat16(v0); h.y = __float2bfloat16(v1);
                    *(__nv_bfloat162*)((__nv_bfloat16*)Cout + o) = h;
                } else {
                    *(float2*)((float*)Cout + o) = make_float2(v0, v1);
                }
            }
        }
    }
}

// ---------------- attention (online softmax, FMA-only exp, bf16 out) ----------------
__global__ void __launch_bounds__(256) attn_kernel(const float* __restrict__ qkv, __nv_bfloat16* __restrict__ o) {
    extern __shared__ float sm[];
    float* ks = sm;            // [256][32]
    float* vs = sm + 256 * 32; // [256][32]
    int p = blockIdx.x, h = blockIdx.y, tid = threadIdx.x;
    size_t base = (size_t)p * 256;
    const float* qr = qkv + (base + tid) * 768 + h * 32;
    float q[32];
    #pragma unroll
    for (int d4 = 0; d4 < 8; d4++) {
        float4 v = *(const float4*)(qr + d4 * 4);
        q[d4*4+0] = v.x; q[d4*4+1] = v.y; q[d4*4+2] = v.z; q[d4*4+3] = v.w;
        float4 kv = *(const float4*)(qkv + (base + tid) * 768 + 256 + h * 32 + d4 * 4);
        *(float4*)&ks[tid * 32 + d4 * 4] = kv;
        float4 vv = *(const float4*)(qkv + (base + tid) * 768 + 512 + h * 32 + d4 * 4);
        *(float4*)&vs[tid * 32 + d4 * 4] = vv;
    }
    __syncthreads();
    float m = -1e30f, l = 0.f;
    float acc[32];
    #pragma unroll
    for (int d = 0; d < 32; d++) acc[d] = 0.f;
    for (int j = 0; j < 256; j++) {
        const float* kr = &ks[j * 32];
        float s = 0.f;
        #pragma unroll
        for (int d = 0; d < 32; d++) s += q[d] * kr[d];
        s *= 0.17677669529663687f;
        const float* vr = &vs[j * 32];
        if (s <= m) {
            float pe = fexpf_fast(s - m);
            l += pe;
            #pragma unroll
            for (int d = 0; d < 32; d++) acc[d] += pe * vr[d];
        } else {
            float r = fexpf_fast(m - s);
            l = l * r + 1.f;
            #pragma unroll
            for (int d = 0; d < 32; d++) acc[d] = acc[d] * r + vr[d];
            m = s;
        }
    }
    float inv = 1.f / l;
    __nv_bfloat16* orow = o + (base + tid) * 256 + h * 32;
    #pragma unroll
    for (int d2 = 0; d2 < 16; d2++) {
        __nv_bfloat162 hv;
        hv.x = __float2bfloat16(acc[d2*2+0] * inv);
        hv.y = __float2bfloat16(acc[d2*2+1] * inv);
        *(__nv_bfloat162*)(orow + d2 * 2) = hv;
    }
}

// ---------------- per-cloud mean ----------------
__global__ void gt_reduce_kernel(const float* __restrict__ xs, float* __restrict__ gt, int Lc) {
    int c = blockIdx.x, chunk = blockIdx.y, tid = threadIdx.x;
    int rows = (Lc + gridDim.y - 1) / gridDim.y;
    int r0 = chunk * rows;
    int r1 = min(r0 + rows, Lc);
    float acc = 0.f;
    for (int r = r0; r < r1; r++) acc += xs[((size_t)c * Lc + r) * 256 + tid];
    atomicAdd(&gt[c * 256 + tid], acc);
}

// ---------------- fold gt into per-cloud biases ----------------
__global__ void cloudbias_kernel(const float* __restrict__ gtsum,
                                 const float* __restrict__ gg_w1, const float* __restrict__ gg_b1,
                                 const float* __restrict__ f_w1, const float* __restrict__ f_b1,
                                 float* __restrict__ ggb, float* __restrict__ fb, int Lc) {
    int c = blockIdx.x, j = threadIdx.x;
    float s1 = gg_b1[j], s2 = f_b1[j];
    float invL = 1.f / (float)Lc;
    for (int h = 0; h < 256; h++) {
        float gv = gtsum[c * 256 + h] * invL;
        s1 += gv * gg_w1[(size_t)(256 + h) * 256 + j];
        s2 += gv * f_w1[(size_t)(256 + h) * 256 + j];
    }
    ggb[c * 256 + j] = s1;
    fb[c * 256 + j] = s2;
}

// ---------------- launch ----------------
extern "C" void kernel_launch(void* const* d_in, const int* in_sizes, int n_in,
                              void* d_out, int out_size) {
    const float* feats = (const float*)d_in[0];
    const float* coord = (const float*)d_in[1];
    const float* pe_w1 = (const float*)d_in[3];
    const float* pe_b1 = (const float*)d_in[4];
    const float* pe_w2 = (const float*)d_in[5];
    const float* pe_b2 = (const float*)d_in[6];
    const float* pre_g = (const float*)d_in[7];
    const float* pre_b = (const float*)d_in[8];
    const float* n1_g  = (const float*)d_in[9];
    const float* n1_b  = (const float*)d_in[10];
    const float* wqkv  = (const float*)d_in[11];
    const float* bqkv  = (const float*)d_in[12];
    const float* wo    = (const float*)d_in[13];
    const float* bo    = (const float*)d_in[14];
    const float* n2_g  = (const float*)d_in[15];
    const float* n2_b  = (const float*)d_in[16];
    const float* m_w1  = (const float*)d_in[17];
    const float* m_b1  = (const float*)d_in[18];
    const float* m_w2  = (const float*)d_in[19];
    const float* m_b2  = (const float*)d_in[20];
    const float* gg_w1 = (const float*)d_in[21];
    const float* gg_b1 = (const float*)d_in[22];
    const float* gg_w2 = (const float*)d_in[23];
    const float* gg_b2 = (const float*)d_in[24];
    const float* f_w1  = (const float*)d_in[25];
    const float* f_b1  = (const float*)d_in[26];
    const float* f_w2  = (const float*)d_in[27];
    const float* f_b2  = (const float*)d_in[28];
    float* out = (float*)d_out;

    int N = in_sizes[0] / 256;
    int B = in_sizes[2];
    int Lc = N / B;
    int patches = N / 256;

    float *p_x, *p_xs, *p_qkv, *p_key, *p_gt, *p_ggb, *p_fb, *p_stats;
    __nv_bfloat16 *p_ba, *p_bb, *p_fe, *p_wt;
    int* p_idx;
    cudaGetSymbolAddress((void**)&p_x, g_x);
    cudaGetSymbolAddress((void**)&p_xs, g_xs);
    cudaGetSymbolAddress((void**)&p_qkv, g_qkv);
    cudaGetSymbolAddress((void**)&p_ba, g_ba);
    cudaGetSymbolAddress((void**)&p_bb, g_bb);
    cudaGetSymbolAddress((void**)&p_fe, g_fe);
    cudaGetSymbolAddress((void**)&p_wt, g_wt);
    cudaGetSymbolAddress((void**)&p_key, g_key);
    cudaGetSymbolAddress((void**)&p_idx, g_idx);
    cudaGetSymbolAddress((void**)&p_gt, g_gt);
    cudaGetSymbolAddress((void**)&p_ggb, g_ggb);
    cudaGetSymbolAddress((void**)&p_fb, g_fb);
    cudaGetSymbolAddress((void**)&p_stats, g_stats);

    __nv_bfloat16* wqkv_t = p_wt + 0;
    __nv_bfloat16* wo_t   = p_wt + 196608;
    __nv_bfloat16* mw1_t  = p_wt + 262144;
    __nv_bfloat16* mw2_t  = p_wt + 393216;
    __nv_bfloat16* ggw1_t = p_wt + 524288;
    __nv_bfloat16* ggw2_t = p_wt + 589824;
    __nv_bfloat16* fw1_t  = p_wt + 655360;
    __nv_bfloat16* fw2_t  = p_wt + 720896;

    cudaFuncSetAttribute(attn_kernel, cudaFuncAttributeMaxDynamicSharedMemorySize, 64 * 1024);
    cudaFuncSetAttribute(sort_local, cudaFuncAttributeMaxDynamicSharedMemorySize, 64 * 1024);
    cudaFuncSetAttribute(merge_local, cudaFuncAttributeMaxDynamicSharedMemorySize, 64 * 1024);

    dim3 wblk(32, 8);
    wconv<<<dim3(768/32, 256/32), wblk>>>(wqkv,  wqkv_t, 256, 768);
    wconv<<<dim3(256/32, 256/32), wblk>>>(wo,    wo_t,   256, 256);
    wconv<<<dim3(512/32, 256/32), wblk>>>(m_w1,  mw1_t,  256, 512);
    wconv<<<dim3(256/32, 512/32), wblk>>>(m_w2,  mw2_t,  512, 256);
    wconv<<<dim3(256/32, 256/32), wblk>>>(gg_w1, ggw1_t, 256, 256);
    wconv<<<dim3(256/32, 256/32), wblk>>>(gg_w2, ggw2_t, 256, 256);
    wconv<<<dim3(256/32, 256/32), wblk>>>(f_w1,  fw1_t,  256, 256);
    wconv<<<dim3(256/32, 256/32), wblk>>>(f_w2,  fw2_t,  256, 256);
    f2bf<<<(unsigned)(((size_t)N * 64 + 255) / 256), 256>>>(feats, p_fe, (size_t)N * 64);

    stats_kernel<<<B, 1024>>>(coord, p_stats, Lc);
    pe_ln_key_kernel<<<N, 256>>>(feats, coord, pe_w1, pe_b1, pe_w2, pe_b2,
                                 pre_g, pre_b, p_stats, p_x, p_key, p_idx, Lc);
    sort_local<<<N / CHUNK, 1024, 64 * 1024>>>(p_key, p_idx, Lc);
    for (int k = CHUNK * 2; k <= Lc; k <<= 1) {
        for (int j = k >> 1; j >= CHUNK; j >>= 1)
            sort_global<<<dim3(Lc / 512, B), 256>>>(p_key, p_idx, k, j, Lc);
        merge_local<<<N / CHUNK, 1024, 64 * 1024>>>(p_key, p_idx, k, Lc);
    }
    gather_ln<<<N, 256>>>(p_x, p_idx, n1_g, n1_b, p_xs, p_ba);
    gemm_bf16<<<dim3(768/GBN, N/GBM), 256, 2*STG_BYTES>>>(p_ba, wqkv_t, bqkv, nullptr, nullptr,
                                                          p_qkv, N, 768, 256, 0, 0, 0);
    attn_kernel<<<dim3(patches, 8), 256, 64 * 1024>>>(p_qkv, p_ba);
    gemm_bf16<<<dim3(256/GBN, N/GBM), 256, 2*STG_BYTES>>>(p_ba, wo_t, bo, p_xs, nullptr,
                                                          p_xs, N, 256, 256, 0, 4, 0);
    ln_bf<<<N, 256>>>(p_xs, n2_g, n2_b, p_ba);
    gemm_bf16<<<dim3(512/GBN, N/GBM), 256, 2*STG_BYTES>>>(p_ba, mw1_t, m_b1, nullptr, nullptr,
                                                          p_bb, N, 512, 256, 0, 2, 1);
    gemm_bf16<<<dim3(256/GBN, N/GBM), 256, 2*STG_BYTES>>>(p_bb, mw2_t, m_b2, p_xs, nullptr,
                                                          p_xs, N, 256, 512, 0, 4, 0);
    scatter_bf<<<N, 256>>>(p_xs, p_ba, p_idx);
    cudaMemsetAsync(p_gt, 0, (size_t)B * 256 * sizeof(float), 0);
    gt_reduce_kernel<<<dim3(B, 32), 256>>>(p_xs, p_gt, Lc);
    cloudbias_kernel<<<B, 256>>>(p_gt, gg_w1, gg_b1, f_w1, f_b1, p_ggb, p_fb, Lc);
    gemm_bf16<<<dim3(256/GBN, N/GBM), 256, 2*STG_BYTES>>>(p_fe, ggw1_t, p_ggb, nullptr, nullptr,
                                                          p_bb, N, 256, 256, Lc, 1, 1);
    gemm_bf16<<<dim3(256/GBN, N/GBM), 256, 2*STG_BYTES>>>(p_bb, ggw2_t, gg_b2, nullptr, nullptr,
                                                          p_qkv, N, 256, 256, 0, 3, 0);
    gemm_bf16<<<dim3(256/GBN, N/GBM), 256, 2*STG_BYTES>>>(p_ba, fw1_t, p_fb, nullptr, nullptr,
                                                          p_bb, N, 256, 256, Lc, 1, 1);
    gemm_bf16<<<dim3(256/GBN, N/GBM), 256, 2*STG_BYTES>>>(p_bb, fw2_t, f_b2, feats, p_qkv,
                                                          out, N, 256, 256, 0, 5, 0);
}

// round 4
// speedup vs baseline: 3.5891x; 1.5336x over previous
#include <cuda_runtime.h>
#include <cuda_bf16.h>
#include <math.h>
#include <stdint.h>

// ---------------- static scratch ----------------
#define MAXN 131072
#define DD 256
__device__ float g_x  [(size_t)MAXN * DD];           // preLN out -> gate (fp32)
__device__ float g_xs [(size_t)MAXN * DD];           // residual stream fp32
__device__ __nv_bfloat16 g_ba[(size_t)MAXN * 768];   // qkv bf16 -> ln2 out -> xo
__device__ __nv_bfloat16 g_bb[(size_t)MAXN * 512];   // attn out -> mlp hidden -> gate/fuse hidden
__device__ __nv_bfloat16 g_fe[(size_t)MAXN * 256];   // feats bf16
__device__ __nv_bfloat16 g_wt[786432];
__device__ float g_key[MAXN];
__device__ int   g_idx[MAXN];
__device__ float g_gt [8 * DD];
__device__ float g_ggb[8 * DD];
__device__ float g_fb [8 * DD];
__device__ float g_stats[8 * 12];

// ---------------- fast math (no MUFU) ----------------
__device__ __forceinline__ float fexp2_fast(float z) {
    z = fmaxf(z, -80.f);
    float n = rintf(z);
    float f = z - n;
    float p = 0.009618129f;
    p = p * f + 0.055504109f;
    p = p * f + 0.240226507f;
    p = p * f + 0.693147181f;
    p = p * f + 1.0f;
    return p * __int_as_float(((int)n + 127) << 23);
}
__device__ __forceinline__ float fexpf_fast(float x) {
    return fexp2_fast(x * 1.4426950408889634f);
}
__device__ __forceinline__ float frcp_fast(float d) {
    float y = __int_as_float(0x7ef311c3 - __float_as_int(d));
    y = y * (2.f - d * y);
    y = y * (2.f - d * y);
    y = y * (2.f - d * y);
    return y;
}
__device__ __forceinline__ uint32_t smem_u32(const void* p) {
    return (uint32_t)__cvta_generic_to_shared(p);
}
// 256-thread block sum; red8 must have 8 floats; caller must not reuse red8 until after next sync
__device__ __forceinline__ float blocksum256(float v, float* red8) {
    #pragma unroll
    for (int off = 16; off; off >>= 1) v += __shfl_xor_sync(0xffffffffu, v, off);
    if ((threadIdx.x & 31) == 0) red8[threadIdx.x >> 5] = v;
    __syncthreads();
    float s = 0.f;
    #pragma unroll
    for (int i = 0; i < 8; i++) s += red8[i];
    return s;
}

// ---------------- per-cloud coord stats ----------------
__global__ void stats_kernel(const float* __restrict__ coord, float* __restrict__ stats, int Lc) {
    int c = blockIdx.x, tid = threadIdx.x;
    float sum[3] = {0,0,0}, mn[3] = {1e30f,1e30f,1e30f}, mx[3] = {-1e30f,-1e30f,-1e30f};
    for (int i = tid; i < Lc; i += blockDim.x) {
        const float* cp = coord + (size_t)(c * Lc + i) * 3;
        #pragma unroll
        for (int d = 0; d < 3; d++) {
            float v = cp[d];
            sum[d] += v; mn[d] = fminf(mn[d], v); mx[d] = fmaxf(mx[d], v);
        }
    }
    __shared__ float red[1024];
    for (int d = 0; d < 3; d++) {
        red[tid] = sum[d]; __syncthreads();
        for (int s = 512; s > 0; s >>= 1) { if (tid < s) red[tid] += red[tid + s]; __syncthreads(); }
        float tot = red[0]; __syncthreads();
        red[tid] = mn[d]; __syncthreads();
        for (int s = 512; s > 0; s >>= 1) { if (tid < s) red[tid] = fminf(red[tid], red[tid + s]); __syncthreads(); }
        float tmn = red[0]; __syncthreads();
        red[tid] = mx[d]; __syncthreads();
        for (int s = 512; s > 0; s >>= 1) { if (tid < s) red[tid] = fmaxf(red[tid], red[tid + s]); __syncthreads(); }
        float tmx = red[0]; __syncthreads();
        if (tid == 0) {
            float mean = tot / (float)Lc;
            stats[c*12 + d]     = mean;
            stats[c*12 + 3 + d] = fmaxf(fmaxf(tmx - mean, mean - tmn), 1e-6f);
            stats[c*12 + 6 + d] = tmn;
            stats[c*12 + 9 + d] = 1.f / fmaxf(tmx - tmn, 1e-6f);
        }
        __syncthreads();
    }
}

// ---------------- PE + pre-LN + serialization key ----------------
__global__ void __launch_bounds__(256) pe_ln_key_kernel(
    const float* __restrict__ feats, const float* __restrict__ coord,
    const float* __restrict__ w1, const float* __restrict__ b1,
    const float* __restrict__ w2, const float* __restrict__ b2,
    const float* __restrict__ g, const float* __restrict__ beta,
    const float* __restrict__ stats,
    float* __restrict__ xout, float* __restrict__ key, int* __restrict__ idx, int Lc)
{
    int i = blockIdx.x, tid = threadIdx.x;
    int c = i / Lc;
    __shared__ float hid[64];
    __shared__ float red8[8];
    const float* st = stats + c * 12;
    float c0 = coord[(size_t)i*3+0], c1 = coord[(size_t)i*3+1], c2 = coord[(size_t)i*3+2];
    if (tid < 64) {
        float n0 = (c0 - st[0]) / st[3];
        float n1 = (c1 - st[1]) / st[4];
        float n2 = (c2 - st[2]) / st[5];
        float hv = b1[tid] + n0 * w1[tid] + n1 * w1[64 + tid] + n2 * w1[128 + tid];
        hid[tid] = fmaxf(hv, 0.f);
    }
    if (tid == 0) {
        float k0 = (c0 - st[6]) * st[9];
        float k1 = (c1 - st[7]) * st[10];
        float k2 = (c2 - st[8]) * st[11];
        key[i] = k0 + 2.17f * k1 + 3.31f * k2;
        idx[i] = i;
    }
    __syncthreads();
    float pe = b2[tid];
    #pragma unroll 8
    for (int h = 0; h < 64; h++) pe += hid[h] * w2[h * 256 + tid];
    float v = feats[(size_t)i * 256 + tid] + pe;
    float mean = blocksum256(v, red8) * (1.f / 256.f);
    __syncthreads();
    float dv = v - mean;
    float var = blocksum256(dv * dv, red8) * (1.f / 256.f);
    xout[(size_t)i * 256 + tid] = dv * rsqrtf(var + 1e-5f) * g[tid] + beta[tid];
}

// ---------------- hierarchical bitonic sort ----------------
#define CHUNK 8192
__global__ void __launch_bounds__(1024) sort_local(float* __restrict__ key, int* __restrict__ idx, int Lc) {
    extern __shared__ char smraw[];
    float* sk = (float*)smraw;
    int*   si = (int*)(smraw + CHUNK * 4);
    size_t gbase = (size_t)blockIdx.x * CHUNK;
    int lbase = (int)(gbase % (size_t)Lc);
    for (int t = threadIdx.x; t < CHUNK; t += 1024) { sk[t] = key[gbase + t]; si[t] = idx[gbase + t]; }
    __syncthreads();
    for (int k = 2; k <= CHUNK; k <<= 1) {
        for (int j = k >> 1; j > 0; j >>= 1) {
            for (int t = threadIdx.x; t < CHUNK / 2; t += 1024) {
                int i = 2 * t - (t & (j - 1));
                int p = i + j;
                bool up = (((lbase + i) & k) == 0);
                float a = sk[i], b = sk[p];
                int ia = si[i], ib = si[p];
                bool sw = up ? (a > b || (a == b && ia > ib)) : (a < b || (a == b && ia < ib));
                if (sw) { sk[i] = b; sk[p] = a; si[i] = ib; si[p] = ia; }
            }
            __syncthreads();
        }
    }
    for (int t = threadIdx.x; t < CHUNK; t += 1024) { key[gbase + t] = sk[t]; idx[gbase + t] = si[t]; }
}

__global__ void __launch_bounds__(1024) merge_local(float* __restrict__ key, int* __restrict__ idx, int k, int Lc) {
    extern __shared__ char smraw[];
    float* sk = (float*)smraw;
    int*   si = (int*)(smraw + CHUNK * 4);
    size_t gbase = (size_t)blockIdx.x * CHUNK;
    int lbase = (int)(gbase % (size_t)Lc);
    for (int t = threadIdx.x; t < CHUNK; t += 1024) { sk[t] = key[gbase + t]; si[t] = idx[gbase + t]; }
    __syncthreads();
    for (int j = CHUNK / 2; j > 0; j >>= 1) {
        for (int t = threadIdx.x; t < CHUNK / 2; t += 1024) {
            int i = 2 * t - (t & (j - 1));
            int p = i + j;
            bool up = (((lbase + i) & k) == 0);
            float a = sk[i], b = sk[p];
            int ia = si[i], ib = si[p];
            bool sw = up ? (a > b || (a == b && ia > ib)) : (a < b || (a == b && ia < ib));
            if (sw) { sk[i] = b; sk[p] = a; si[i] = ib; si[p] = ia; }
        }
        __syncthreads();
    }
    for (int t = threadIdx.x; t < CHUNK; t += 1024) { key[gbase + t] = sk[t]; idx[gbase + t] = si[t]; }
}

__global__ void __launch_bounds__(256) sort_global(float* __restrict__ key, int* __restrict__ idx, int k, int j, int Lc) {
    int c = blockIdx.y;
    size_t base = (size_t)c * Lc;
    int t = blockIdx.x * 256 + threadIdx.x;
    int i = 2 * t - (t & (j - 1));
    int p = i + j;
    bool up = ((i & k) == 0);
    float a = key[base + i], b = key[base + p];
    int ia = idx[base + i], ib = idx[base + p];
    bool sw = up ? (a > b || (a == b && ia > ib)) : (a < b || (a == b && ia < ib));
    if (sw) {
        key[base + i] = b; key[base + p] = a;
        idx[base + i] = ib; idx[base + p] = ia;
    }
}

// ---------------- gather+LN ----------------
__global__ void __launch_bounds__(256) gather_ln(const float* __restrict__ src, const int* __restrict__ idx,
                                                 const float* __restrict__ g, const float* __restrict__ b,
                                                 float* __restrict__ xs, __nv_bfloat16* __restrict__ hbf) {
    int p = blockIdx.x, tid = threadIdx.x;
    __shared__ float red8[8];
    float v = src[(size_t)idx[p] * 256 + tid];
    xs[(size_t)p * 256 + tid] = v;
    float mean = blocksum256(v, red8) * (1.f / 256.f);
    __syncthreads();
    float dv = v - mean;
    float var = blocksum256(dv * dv, red8) * (1.f / 256.f);
    hbf[(size_t)p * 256 + tid] = __float2bfloat16(dv * rsqrtf(var + 1e-5f) * g[tid] + b[tid]);
}

// ---------------- LN -> bf16 ----------------
__global__ void __launch_bounds__(256) ln_bf(const float* __restrict__ x, const float* __restrict__ g,
                                             const float* __restrict__ b, __nv_bfloat16* __restrict__ y) {
    int row = blockIdx.x, tid = threadIdx.x;
    __shared__ float red8[8];
    float v = x[(size_t)row * 256 + tid];
    float mean = blocksum256(v, red8) * (1.f / 256.f);
    __syncthreads();
    float dv = v - mean;
    float var = blocksum256(dv * dv, red8) * (1.f / 256.f);
    y[(size_t)row * 256 + tid] = __float2bfloat16(dv * rsqrtf(var + 1e-5f) * g[tid] + b[tid]);
}

// ---------------- scatter fp32 -> bf16 ----------------
__global__ void scatter_bf(const float* __restrict__ src, __nv_bfloat16* __restrict__ dst, const int* __restrict__ idx) {
    int p = blockIdx.x, tid = threadIdx.x;
    dst[(size_t)idx[p] * 256 + tid] = __float2bfloat16(src[(size_t)p * 256 + tid]);
}

// ---------------- fp32 -> bf16 elementwise ----------------
__global__ void f2bf(const float* __restrict__ x, __nv_bfloat16* __restrict__ y, size_t n4) {
    size_t i = (size_t)blockIdx.x * blockDim.x + threadIdx.x;
    if (i >= n4) return;
    float4 v = ((const float4*)x)[i];
    __nv_bfloat162 a; a.x = __float2bfloat16(v.x); a.y = __float2bfloat16(v.y);
    __nv_bfloat162 b; b.x = __float2bfloat16(v.z); b.y = __float2bfloat16(v.w);
    ((__nv_bfloat162*)y)[i * 2 + 0] = a;
    ((__nv_bfloat162*)y)[i * 2 + 1] = b;
}

// ---------------- weight transpose + convert ----------------
__global__ void wconv(const float* __restrict__ W, __nv_bfloat16* __restrict__ Wt, int K, int Ncols) {
    __shared__ float t[32][33];
    int bx = blockIdx.x * 32, by = blockIdx.y * 32;
    for (int r = threadIdx.y; r < 32; r += 8)
        t[r][threadIdx.x] = W[(size_t)(by + r) * Ncols + bx + threadIdx.x];
    __syncthreads();
    for (int r = threadIdx.y; r < 32; r += 8)
        Wt[(size_t)(bx + r) * K + by + threadIdx.x] = __float2bfloat16(t[threadIdx.x][r]);
}

// ---------------- tensor-core GEMM ----------------
#define GBM 128
#define GBN 128
#define GKT 32
#define STG_BYTES 20480

__global__ void __launch_bounds__(256) gemm_bf16(
    const __nv_bfloat16* __restrict__ A,
    const __nv_bfloat16* __restrict__ Bt,
    const float* __restrict__ bias,
    const float* __restrict__ resid,
    const float* __restrict__ gate,
    void* __restrict__ Cout,
    int M, int Ncols, int K, int cloudLen, int epi, int outBf16)
{
    extern __shared__ char smraw[];
    const int tid = threadIdx.x;
    const int lane = tid & 31;
    const int warp = tid >> 5;
    const int wm = warp >> 1, wn = warp & 1;
    const int m0 = blockIdx.y * GBM, n0 = blockIdx.x * GBN;

    float acc[2][8][4];
    #pragma unroll
    for (int i = 0; i < 2; i++)
        #pragma unroll
        for (int j = 0; j < 8; j++)
            #pragma unroll
            for (int q = 0; q < 4; q++) acc[i][j][q] = 0.f;

    const int ldrow0 = tid >> 2, ldc0 = tid & 3;
    const int ldrow1 = (tid + 256) >> 2, ldc1 = tid & 3;

    auto issue = [&](int s, int kt) {
        char* sA = smraw + s * STG_BYTES;
        char* sB = sA + 10240;
        {
            const __nv_bfloat16* gA = A + (size_t)(m0 + ldrow0) * K + kt * GKT + ldc0 * 8;
            uint32_t d = smem_u32(sA + ldrow0 * 80 + ldc0 * 16);
            asm volatile("cp.async.cg.shared.global [%0], [%1], 16;\n" :: "r"(d), "l"(gA));
            const __nv_bfloat16* gB = Bt + (size_t)(n0 + ldrow0) * K + kt * GKT + ldc0 * 8;
            uint32_t d2 = smem_u32(sB + ldrow0 * 80 + ldc0 * 16);
            asm volatile("cp.async.cg.shared.global [%0], [%1], 16;\n" :: "r"(d2), "l"(gB));
        }
        {
            const __nv_bfloat16* gA = A + (size_t)(m0 + ldrow1) * K + kt * GKT + ldc1 * 8;
            uint32_t d = smem_u32(sA + ldrow1 * 80 + ldc1 * 16);
            asm volatile("cp.async.cg.shared.global [%0], [%1], 16;\n" :: "r"(d), "l"(gA));
            const __nv_bfloat16* gB = Bt + (size_t)(n0 + ldrow1) * K + kt * GKT + ldc1 * 8;
            uint32_t d2 = smem_u32(sB + ldrow1 * 80 + ldc1 * 16);
            asm volatile("cp.async.cg.shared.global [%0], [%1], 16;\n" :: "r"(d2), "l"(gB));
        }
        asm volatile("cp.async.commit_group;\n");
    };

    const int nk = K / GKT;
    issue(0, 0);
    for (int kt = 0; kt < nk; kt++) {
        int s = kt & 1;
        if (kt + 1 < nk) {
            issue((kt + 1) & 1, kt + 1);
            asm volatile("cp.async.wait_group 1;\n");
        } else {
            asm volatile("cp.async.wait_group 0;\n");
        }
        __syncthreads();

        char* sA = smraw + s * STG_BYTES;
        char* sB = sA + 10240;
        #pragma unroll
        for (int kk = 0; kk < 2; kk++) {
            uint32_t af[2][4];
            #pragma unroll
            for (int i = 0; i < 2; i++) {
                int r = wm * 32 + i * 16 + (lane & 15);
                int c = kk * 2 + (lane >> 4);
                uint32_t addr = smem_u32(sA + r * 80 + c * 16);
                asm volatile("ldmatrix.sync.aligned.m8n8.x4.shared.b16 {%0,%1,%2,%3}, [%4];"
                             : "=r"(af[i][0]), "=r"(af[i][1]), "=r"(af[i][2]), "=r"(af[i][3])
                             : "r"(addr));
            }
            uint32_t bf[8][2];
            #pragma unroll
            for (int jp = 0; jp < 4; jp++) {
                int r = wn * 64 + jp * 16 + (lane & 15);
                int c = kk * 2 + (lane >> 4);
                uint32_t addr = smem_u32(sB + r * 80 + c * 16);
                uint32_t r0, r1, r2, r3;
                asm volatile("ldmatrix.sync.aligned.m8n8.x4.shared.b16 {%0,%1,%2,%3}, [%4];"
                             : "=r"(r0), "=r"(r1), "=r"(r2), "=r"(r3) : "r"(addr));
                bf[2*jp][0] = r0; bf[2*jp+1][0] = r1;
                bf[2*jp][1] = r2; bf[2*jp+1][1] = r3;
            }
            #pragma unroll
            for (int i = 0; i < 2; i++)
                #pragma unroll
                for (int j = 0; j < 8; j++) {
                    asm volatile("mma.sync.aligned.m16n8k16.row.col.f32.bf16.bf16.f32 "
                                 "{%0,%1,%2,%3}, {%4,%5,%6,%7}, {%8,%9}, {%0,%1,%2,%3};"
                                 : "+f"(acc[i][j][0]), "+f"(acc[i][j][1]),
                                   "+f"(acc[i][j][2]), "+f"(acc[i][j][3])
                                 : "r"(af[i][0]), "r"(af[i][1]), "r"(af[i][2]), "r"(af[i][3]),
                                   "r"(bf[j][0]), "r"(bf[j][1]));
                }
        }
        __syncthreads();
    }

    const int rbase = m0 + wm * 32 + (lane >> 2);
    const int cbase = n0 + wn * 64 + 2 * (lane & 3);
    #pragma unroll
    for (int i = 0; i < 2; i++) {
        #pragma unroll
        for (int half = 0; half < 2; half++) {
            int m = rbase + i * 16 + half * 8;
            const float* bp = (cloudLen > 0) ? (bias + (size_t)(m / cloudLen) * Ncols) : bias;
            #pragma unroll
            for (int j = 0; j < 8; j++) {
                int n = cbase + j * 8;
                float v0 = acc[i][j][half * 2 + 0] + bp[n];
                float v1 = acc[i][j][half * 2 + 1] + bp[n + 1];
                size_t o = (size_t)m * Ncols + n;
                switch (epi) {
                    case 1: v0 = fmaxf(v0, 0.f); v1 = fmaxf(v1, 0.f); break;
                    case 2:
                        v0 = 0.5f * v0 * (1.f + erff(v0 * 0.70710678118f));
                        v1 = 0.5f * v1 * (1.f + erff(v1 * 0.70710678118f));
                        break;
                    case 3:
                        v0 = frcp_fast(1.f + fexpf_fast(-v0));
                        v1 = frcp_fast(1.f + fexpf_fast(-v1));
                        break;
                    case 4: { float2 r = *(const float2*)(resid + o); v0 += r.x; v1 += r.y; } break;
                    case 5: {
                        float2 r = *(const float2*)(resid + o);
                        float2 gg = *(const float2*)(gate + o);
                        v0 = r.x + gg.x * v0; v1 = r.y + gg.y * v1;
                    } break;
                    default: break;
                }
                if (outBf16) {
                    __nv_bfloat162 h;
                    h.x = __float2bfloat16(v0); h.y = __float2bfloat16(v1);
                    *(__nv_bfloat162*)((__nv_bfloat16*)Cout + o) = h;
                } else {
                    *(float2*)((float*)Cout + o) = make_float2(v0, v1);
                }
            }
        }
    }
}

// ---------------- flash attention on tensor cores ----------------
// block = (patch, head); 8 warps, warp w handles query rows [32w, 32w+32)
// smem: Q [256][80B], K [256][80B], Vt [32][528B]
#define FA_SMEM (20480 * 2 + 32 * 528)
__global__ void __launch_bounds__(256) fattn(const __nv_bfloat16* __restrict__ qkv,
                                             __nv_bfloat16* __restrict__ o) {
    extern __shared__ char sm[];
    char* sq = sm;
    char* sk = sm + 20480;
    char* svt = sm + 40960;
    const int p = blockIdx.x, h = blockIdx.y;
    const int tid = threadIdx.x;
    const int lane = tid & 31;
    const int w = tid >> 5;
    const size_t base = (size_t)p * 256;
    const float SC = 0.17677669529663687f * 1.4426950408889634f; // 1/sqrt(32) * log2(e)

    // load Q, K rows; V transposed
    {
        const uint4* qr = (const uint4*)(qkv + (base + tid) * 768 + h * 32);
        const uint4* kr = (const uint4*)(qkv + (base + tid) * 768 + 256 + h * 32);
        const uint4* vr = (const uint4*)(qkv + (base + tid) * 768 + 512 + h * 32);
        uint4* dq = (uint4*)(sq + tid * 80);
        uint4* dk = (uint4*)(sk + tid * 80);
        uint4 v0 = vr[0], v1 = vr[1], v2 = vr[2], v3 = vr[3];
        dq[0] = qr[0]; dq[1] = qr[1]; dq[2] = qr[2]; dq[3] = qr[3];
        dk[0] = kr[0]; dk[1] = kr[1]; dk[2] = kr[2]; dk[3] = kr[3];
        uint32_t vu[8] = {v0.x, v0.y, v0.z, v0.w, v1.x, v1.y, v1.z, v1.w};
        uint32_t vu2[8] = {v2.x, v2.y, v2.z, v2.w, v3.x, v3.y, v3.z, v3.w};
        #pragma unroll
        for (int e = 0; e < 8; e++) {
            ((__nv_bfloat16*)(svt + (2 * e + 0) * 528))[tid] = ((__nv_bfloat162*)&vu[e])->x;
            ((__nv_bfloat16*)(svt + (2 * e + 1) * 528))[tid] = ((__nv_bfloat162*)&vu[e])->y;
        }
        #pragma unroll
        for (int e = 0; e < 8; e++) {
            ((__nv_bfloat16*)(svt + (16 + 2 * e + 0) * 528))[tid] = ((__nv_bfloat162*)&vu2[e])->x;
            ((__nv_bfloat16*)(svt + (16 + 2 * e + 1) * 528))[tid] = ((__nv_bfloat162*)&vu2[e])->y;
        }
    }
    __syncthreads();

    const int m0w = w * 32;
    // Q fragments: [m-tile][k-half][4]
    uint32_t qa[2][2][4];
    #pragma unroll
    for (int i = 0; i < 2; i++)
        #pragma unroll
        for (int kk = 0; kk < 2; kk++) {
            int r = m0w + i * 16 + (lane & 15);
            uint32_t addr = smem_u32(sq + r * 80 + kk * 32 + (lane >> 4) * 16);
            asm volatile("ldmatrix.sync.aligned.m8n8.x4.shared.b16 {%0,%1,%2,%3}, [%4];"
                         : "=r"(qa[i][kk][0]), "=r"(qa[i][kk][1]),
                           "=r"(qa[i][kk][2]), "=r"(qa[i][kk][3])
                         : "r"(addr));
        }

    float oacc[2][4][4];
    #pragma unroll
    for (int i = 0; i < 2; i++)
        #pragma unroll
        for (int d = 0; d < 4; d++)
            #pragma unroll
            for (int q = 0; q < 4; q++) oacc[i][d][q] = 0.f;
    float mrow[2][2] = {{-1e30f, -1e30f}, {-1e30f, -1e30f}};
    float lrow[2][2] = {{0.f, 0.f}, {0.f, 0.f}};

    for (int jc = 0; jc < 8; jc++) {
        // K fragments: kb[kk][nt][2]
        uint32_t kb[2][4][2];
        #pragma unroll
        for (int jp = 0; jp < 2; jp++)
            #pragma unroll
            for (int kk = 0; kk < 2; kk++) {
                int r = jc * 32 + jp * 16 + (lane & 15);
                uint32_t addr = smem_u32(sk + r * 80 + kk * 32 + (lane >> 4) * 16);
                uint32_t r0, r1, r2, r3;
                asm volatile("ldmatrix.sync.aligned.m8n8.x4.shared.b16 {%0,%1,%2,%3}, [%4];"
                             : "=r"(r0), "=r"(r1), "=r"(r2), "=r"(r3) : "r"(addr));
                kb[kk][2*jp][0] = r0;   kb[kk][2*jp][1] = r2;
                kb[kk][2*jp+1][0] = r1; kb[kk][2*jp+1][1] = r3;
            }

        float sacc[2][4][4];
        #pragma unroll
        for (int i = 0; i < 2; i++)
            #pragma unroll
            for (int nt = 0; nt < 4; nt++)
                #pragma unroll
                for (int q = 0; q < 4; q++) sacc[i][nt][q] = 0.f;
        #pragma unroll
        for (int kk = 0; kk < 2; kk++)
            #pragma unroll
            for (int i = 0; i < 2; i++)
                #pragma unroll
                for (int nt = 0; nt < 4; nt++) {
                    asm volatile("mma.sync.aligned.m16n8k16.row.col.f32.bf16.bf16.f32 "
                                 "{%0,%1,%2,%3}, {%4,%5,%6,%7}, {%8,%9}, {%0,%1,%2,%3};"
                                 : "+f"(sacc[i][nt][0]), "+f"(sacc[i][nt][1]),
                                   "+f"(sacc[i][nt][2]), "+f"(sacc[i][nt][3])
                                 : "r"(qa[i][kk][0]), "r"(qa[i][kk][1]),
                                   "r"(qa[i][kk][2]), "r"(qa[i][kk][3]),
                                   "r"(kb[kk][nt][0]), "r"(kb[kk][nt][1]));
                }

        // scale into exp2 domain
        #pragma unroll
        for (int i = 0; i < 2; i++)
            #pragma unroll
            for (int nt = 0; nt < 4; nt++)
                #pragma unroll
                for (int q = 0; q < 4; q++) sacc[i][nt][q] *= SC;

        // online softmax per row
        #pragma unroll
        for (int i = 0; i < 2; i++) {
            #pragma unroll
            for (int half = 0; half < 2; half++) {
                float mx = -1e30f;
                #pragma unroll
                for (int nt = 0; nt < 4; nt++) {
                    mx = fmaxf(mx, sacc[i][nt][half*2+0]);
                    mx = fmaxf(mx, sacc[i][nt][half*2+1]);
                }
                mx = fmaxf(mx, __shfl_xor_sync(0xffffffffu, mx, 1));
                mx = fmaxf(mx, __shfl_xor_sync(0xffffffffu, mx, 2));
                float newm = fmaxf(mrow[i][half], mx);
                float alpha = fexp2_fast(mrow[i][half] - newm);
                mrow[i][half] = newm;
                float rs = 0.f;
                #pragma unroll
                for (int nt = 0; nt < 4; nt++) {
                    float p0 = fexp2_fast(sacc[i][nt][half*2+0] - newm);
                    float p1 = fexp2_fast(sacc[i][nt][half*2+1] - newm);
                    sacc[i][nt][half*2+0] = p0;
                    sacc[i][nt][half*2+1] = p1;
                    rs += p0 + p1;
                }
                rs += __shfl_xor_sync(0xffffffffu, rs, 1);
                rs += __shfl_xor_sync(0xffffffffu, rs, 2);
                lrow[i][half] = lrow[i][half] * alpha + rs;
                #pragma unroll
                for (int dt = 0; dt < 4; dt++) {
                    oacc[i][dt][half*2+0] *= alpha;
                    oacc[i][dt][half*2+1] *= alpha;
                }
            }
        }

        // pack P into A fragments: pa[i][k-half][4]
        uint32_t pa[2][2][4];
        #pragma unroll
        for (int i = 0; i < 2; i++)
            #pragma unroll
            for (int kk = 0; kk < 2; kk++) {
                int ntl = kk * 2, nth = kk * 2 + 1;
                __nv_bfloat162 b0 = __float22bfloat162_rn(make_float2(sacc[i][ntl][0], sacc[i][ntl][1]));
                __nv_bfloat162 b1 = __float22bfloat162_rn(make_float2(sacc[i][ntl][2], sacc[i][ntl][3]));
                __nv_bfloat162 b2 = __float22bfloat162_rn(make_float2(sacc[i][nth][0], sacc[i][nth][1]));
                __nv_bfloat162 b3 = __float22bfloat162_rn(make_float2(sacc[i][nth][2], sacc[i][nth][3]));
                pa[i][kk][0] = *(uint32_t*)&b0;
                pa[i][kk][1] = *(uint32_t*)&b1;
                pa[i][kk][2] = *(uint32_t*)&b2;
                pa[i][kk][3] = *(uint32_t*)&b3;
            }

        // V fragments: vb[kk][dt][2]
        uint32_t vb[2][4][2];
        #pragma unroll
        for (int jp = 0; jp < 2; jp++)
            #pragma unroll
            for (int kk = 0; kk < 2; kk++) {
                int r = jp * 16 + (lane & 15);
                uint32_t addr = smem_u32(svt + r * 528 + jc * 64 + kk * 32 + (lane >> 4) * 16);
                uint32_t r0, r1, r2, r3;
                asm volatile("ldmatrix.sync.aligned.m8n8.x4.shared.b16 {%0,%1,%2,%3}, [%4];"
                             : "=r"(r0), "=r"(r1), "=r"(r2), "=r"(r3) : "r"(addr));
                vb[kk][2*jp][0] = r0;   vb[kk][2*jp][1] = r2;
                vb[kk][2*jp+1][0] = r1; vb[kk][2*jp+1][1] = r3;
            }

        #pragma unroll
        for (int kk = 0; kk < 2; kk++)
            #pragma unroll
            for (int i = 0; i < 2; i++)
                #pragma unroll
                for (int dt = 0; dt < 4; dt++) {
                    asm volatile("mma.sync.aligned.m16n8k16.row.col.f32.bf16.bf16.f32 "
                                 "{%0,%1,%2,%3}, {%4,%5,%6,%7}, {%8,%9}, {%0,%1,%2,%3};"
                                 : "+f"(oacc[i][dt][0]), "+f"(oacc[i][dt][1]),
                                   "+f"(oacc[i][dt][2]), "+f"(oacc[i][dt][3])
                                 : "r"(pa[i][kk][0]), "r"(pa[i][kk][1]),
                                   "r"(pa[i][kk][2]), "r"(pa[i][kk][3]),
                                   "r"(vb[kk][dt][0]), "r"(vb[kk][dt][1]));
                }
    }

    // write out: o[(base+row)*256 + h*32 + col]
    #pragma unroll
    for (int i = 0; i < 2; i++)
        #pragma unroll
        for (int half = 0; half < 2; half++) {
            float inv = 1.f / lrow[i][half];
            int row = m0w + i * 16 + half * 8 + (lane >> 2);
            #pragma unroll
            for (int dt = 0; dt < 4; dt++) {
                int col = h * 32 + dt * 8 + 2 * (lane & 3);
                __nv_bfloat162 hv;
                hv.x = __float2bfloat16(oacc[i][dt][half*2+0] * inv);
                hv.y = __float2bfloat16(oacc[i][dt][half*2+1] * inv);
                *(__nv_bfloat162*)(o + (base + row) * 256 + col) = hv;
            }
        }
}

// ---------------- per-cloud mean ----------------
__global__ void gt_reduce_kernel(const float* __restrict__ xs, float* __restrict__ gt, int Lc) {
    int c = blockIdx.x, chunk = blockIdx.y, tid = threadIdx.x;
    int rows = (Lc + gridDim.y - 1) / gridDim.y;
    int r0 = chunk * rows;
    int r1 = min(r0 + rows, Lc);
    float acc = 0.f;
    for (int r = r0; r < r1; r++) acc += xs[((size_t)c * Lc + r) * 256 + tid];
    atomicAdd(&gt[c * 256 + tid], acc);
}

// ---------------- fold gt into per-cloud biases ----------------
__global__ void cloudbias_kernel(const float* __restrict__ gtsum,
                                 const float* __restrict__ gg_w1, const float* __restrict__ gg_b1,
                                 const float* __restrict__ f_w1, const float* __restrict__ f_b1,
                                 float* __restrict__ ggb, float* __restrict__ fb, int Lc) {
    int c = blockIdx.x, j = threadIdx.x;
    float s1 = gg_b1[j], s2 = f_b1[j];
    float invL = 1.f / (float)Lc;
    for (int h = 0; h < 256; h++) {
        float gv = gtsum[c * 256 + h] * invL;
        s1 += gv * gg_w1[(size_t)(256 + h) * 256 + j];
        s2 += gv * f_w1[(size_t)(256 + h) * 256 + j];
    }
    ggb[c * 256 + j] = s1;
    fb[c * 256 + j] = s2;
}

// ---------------- launch ----------------
extern "C" void kernel_launch(void* const* d_in, const int* in_sizes, int n_in,
                              void* d_out, int out_size) {
    const float* feats = (const float*)d_in[0];
    const float* coord = (const float*)d_in[1];
    const float* pe_w1 = (const float*)d_in[3];
    const float* pe_b1 = (const float*)d_in[4];
    const float* pe_w2 = (const float*)d_in[5];
    const float* pe_b2 = (const float*)d_in[6];
    const float* pre_g = (const float*)d_in[7];
    const float* pre_b = (const float*)d_in[8];
    const float* n1_g  = (const float*)d_in[9];
    const float* n1_b  = (const float*)d_in[10];
    const float* wqkv  = (const float*)d_in[11];
    const float* bqkv  = (const float*)d_in[12];
    const float* wo    = (const float*)d_in[13];
    const float* bo    = (const float*)d_in[14];
    const float* n2_g  = (const float*)d_in[15];
    const float* n2_b  = (const float*)d_in[16];
    const float* m_w1  = (const float*)d_in[17];
    const float* m_b1  = (const float*)d_in[18];
    const float* m_w2  = (const float*)d_in[19];
    const float* m_b2  = (const float*)d_in[20];
    const float* gg_w1 = (const float*)d_in[21];
    const float* gg_b1 = (const float*)d_in[22];
    const float* gg_w2 = (const float*)d_in[23];
    const float* gg_b2 = (const float*)d_in[24];
    const float* f_w1  = (const float*)d_in[25];
    const float* f_b1  = (const float*)d_in[26];
    const float* f_w2  = (const float*)d_in[27];
    const float* f_b2  = (const float*)d_in[28];
    float* out = (float*)d_out;

    int N = in_sizes[0] / 256;
    int B = in_sizes[2];
    int Lc = N / B;
    int patches = N / 256;

    float *p_x, *p_xs, *p_key, *p_gt, *p_ggb, *p_fb, *p_stats;
    __nv_bfloat16 *p_ba, *p_bb, *p_fe, *p_wt;
    int* p_idx;
    cudaGetSymbolAddress((void**)&p_x, g_x);
    cudaGetSymbolAddress((void**)&p_xs, g_xs);
    cudaGetSymbolAddress((void**)&p_ba, g_ba);
    cudaGetSymbolAddress((void**)&p_bb, g_bb);
    cudaGetSymbolAddress((void**)&p_fe, g_fe);
    cudaGetSymbolAddress((void**)&p_wt, g_wt);
    cudaGetSymbolAddress((void**)&p_key, g_key);
    cudaGetSymbolAddress((void**)&p_idx, g_idx);
    cudaGetSymbolAddress((void**)&p_gt, g_gt);
    cudaGetSymbolAddress((void**)&p_ggb, g_ggb);
    cudaGetSymbolAddress((void**)&p_fb, g_fb);
    cudaGetSymbolAddress((void**)&p_stats, g_stats);

    __nv_bfloat16* wqkv_t = p_wt + 0;
    __nv_bfloat16* wo_t   = p_wt + 196608;
    __nv_bfloat16* mw1_t  = p_wt + 262144;
    __nv_bfloat16* mw2_t  = p_wt + 393216;
    __nv_bfloat16* ggw1_t = p_wt + 524288;
    __nv_bfloat16* ggw2_t = p_wt + 589824;
    __nv_bfloat16* fw1_t  = p_wt + 655360;
    __nv_bfloat16* fw2_t  = p_wt + 720896;

    cudaFuncSetAttribute(fattn, cudaFuncAttributeMaxDynamicSharedMemorySize, FA_SMEM);
    cudaFuncSetAttribute(sort_local, cudaFuncAttributeMaxDynamicSharedMemorySize, 64 * 1024);
    cudaFuncSetAttribute(merge_local, cudaFuncAttributeMaxDynamicSharedMemorySize, 64 * 1024);

    dim3 wblk(32, 8);
    wconv<<<dim3(768/32, 256/32), wblk>>>(wqkv,  wqkv_t, 256, 768);
    wconv<<<dim3(256/32, 256/32), wblk>>>(wo,    wo_t,   256, 256);
    wconv<<<dim3(512/32, 256/32), wblk>>>(m_w1,  mw1_t,  256, 512);
    wconv<<<dim3(256/32, 512/32), wblk>>>(m_w2,  mw2_t,  512, 256);
    wconv<<<dim3(256/32, 256/32), wblk>>>(gg_w1, ggw1_t, 256, 256);
    wconv<<<dim3(256/32, 256/32), wblk>>>(gg_w2, ggw2_t, 256, 256);
    wconv<<<dim3(256/32, 256/32), wblk>>>(f_w1,  fw1_t,  256, 256);
    wconv<<<dim3(256/32, 256/32), wblk>>>(f_w2,  fw2_t,  256, 256);
    f2bf<<<(unsigned)(((size_t)N * 64 + 255) / 256), 256>>>(feats, p_fe, (size_t)N * 64);

    stats_kernel<<<B, 1024>>>(coord, p_stats, Lc);
    pe_ln_key_kernel<<<N, 256>>>(feats, coord, pe_w1, pe_b1, pe_w2, pe_b2,
                                 pre_g, pre_b, p_stats, p_x, p_key, p_idx, Lc);
    sort_local<<<N / CHUNK, 1024, 64 * 1024>>>(p_key, p_idx, Lc);
    for (int k = CHUNK * 2; k <= Lc; k <<= 1) {
        for (int j = k >> 1; j >= CHUNK; j >>= 1)
            sort_global<<<dim3(Lc / 512, B), 256>>>(p_key, p_idx, k, j, Lc);
        merge_local<<<N / CHUNK, 1024, 64 * 1024>>>(p_key, p_idx, k, Lc);
    }
    gather_ln<<<N, 256>>>(p_x, p_idx, n1_g, n1_b, p_xs, p_bb);
    // qkv GEMM -> bf16 [N,768] in ba  (A = LN1 out stored temporarily in bb's first N*256)
    gemm_bf16<<<dim3(768/GBN, N/GBM), 256, 2*STG_BYTES>>>(p_bb, wqkv_t, bqkv, nullptr, nullptr,
                                                          p_ba, N, 768, 256, 0, 0, 1);
    // flash attention: ba(qkv bf16) -> bb (attn out bf16 [N,256])
    fattn<<<dim3(patches, 8), 256, FA_SMEM>>>(p_ba, p_bb);
    // wo GEMM + residual -> xs fp32
    gemm_bf16<<<dim3(256/GBN, N/GBM), 256, 2*STG_BYTES>>>(p_bb, wo_t, bo, p_xs, nullptr,
                                                          p_xs, N, 256, 256, 0, 4, 0);
    // LN2 -> ba bf16
    ln_bf<<<N, 256>>>(p_xs, n2_g, n2_b, p_ba);
    // MLP1 + gelu -> bb bf16 [N,512]
    gemm_bf16<<<dim3(512/GBN, N/GBM), 256, 2*STG_BYTES>>>(p_ba, mw1_t, m_b1, nullptr, nullptr,
                                                          p_bb, N, 512, 256, 0, 2, 1);
    // MLP2 + residual -> xs fp32
    gemm_bf16<<<dim3(256/GBN, N/GBM), 256, 2*STG_BYTES>>>(p_bb, mw2_t, m_b2, p_xs, nullptr,
                                                          p_xs, N, 256, 512, 0, 4, 0);
    // scatter -> xo bf16 in ba
    scatter_bf<<<N, 256>>>(p_xs, p_ba, p_idx);
    cudaMemsetAsync(p_gt, 0, (size_t)B * 256 * sizeof(float), 0);
    gt_reduce_kernel<<<dim3(B, 32), 256>>>(p_xs, p_gt, Lc);
    cloudbias_kernel<<<B, 256>>>(p_gt, gg_w1, gg_b1, f_w1, f_b1, p_ggb, p_fb, Lc);
    // gate hidden: relu(feats @ gg_w1_top + ggb[cloud]) -> bb bf16
    gemm_bf16<<<dim3(256/GBN, N/GBM), 256, 2*STG_BYTES>>>(p_fe, ggw1_t, p_ggb, nullptr, nullptr,
                                                          p_bb, N, 256, 256, Lc, 1, 1);
    // gate = sigmoid(...) -> g_x fp32
    gemm_bf16<<<dim3(256/GBN, N/GBM), 256, 2*STG_BYTES>>>(p_bb, ggw2_t, gg_b2, nullptr, nullptr,
                                                          p_x, N, 256, 256, 0, 3, 0);
    // fuse hidden: relu(xo @ f_w1_top + fb[cloud]) -> bb bf16
    gemm_bf16<<<dim3(256/GBN, N/GBM), 256, 2*STG_BYTES>>>(p_ba, fw1_t, p_fb, nullptr, nullptr,
                                                          p_bb, N, 256, 256, Lc, 1, 1);
    // out = feats + gate * (hidden @ f_w2 + f_b2)
    gemm_bf16<<<dim3(256/GBN, N/GBM), 256, 2*STG_BYTES>>>(p_bb, fw2_t, f_b2, feats, p_x,
                                                          out, N, 256, 256, 0, 5, 0);
}

// round 5
// speedup vs baseline: 3.7209x; 1.0367x over previous
#include <cuda_runtime.h>
#include <cuda_bf16.h>
#include <math.h>
#include <stdint.h>

// ---------------- static scratch ----------------
#define MAXN 131072
#define DD 256
__device__ float g_x  [(size_t)MAXN * DD];           // LN-pre out fp32 (unpermuted) -> gate fp32
__device__ float g_xs [(size_t)MAXN * DD];           // serialized residual stream fp32
__device__ __nv_bfloat16 g_ba[(size_t)MAXN * 768];   // qkv bf16 -> ln2 out -> xo
__device__ __nv_bfloat16 g_bb[(size_t)MAXN * 512];   // ln1 out -> attn out -> mlp hidden -> gate/fuse hidden
__device__ __nv_bfloat16 g_fe[(size_t)MAXN * 256];   // feats bf16
__device__ __nv_bfloat16 g_wt[786432];
__device__ float g_key[MAXN];
__device__ int   g_idx[MAXN];
__device__ float g_gt [8 * DD];
__device__ float g_ggb[8 * DD];
__device__ float g_fb [8 * DD];
__device__ float g_stats[8 * 12];

// ---------------- fast math ----------------
__device__ __forceinline__ float fexp2_fast(float z) {
    z = fmaxf(z, -80.f);
    float n = rintf(z);
    float f = z - n;
    float p = 0.009618129f;
    p = p * f + 0.055504109f;
    p = p * f + 0.240226507f;
    p = p * f + 0.693147181f;
    p = p * f + 1.0f;
    return p * __int_as_float(((int)n + 127) << 23);
}
__device__ __forceinline__ float fexpf_fast(float x) {
    return fexp2_fast(x * 1.4426950408889634f);
}
__device__ __forceinline__ float frcp_fast(float d) {
    float y = __int_as_float(0x7ef311c3 - __float_as_int(d));
    y = y * (2.f - d * y);
    y = y * (2.f - d * y);
    y = y * (2.f - d * y);
    return y;
}
__device__ __forceinline__ uint32_t smem_u32(const void* p) {
    return (uint32_t)__cvta_generic_to_shared(p);
}
__device__ __forceinline__ float blocksum256(float v, float* red8) {
    #pragma unroll
    for (int off = 16; off; off >>= 1) v += __shfl_xor_sync(0xffffffffu, v, off);
    if ((threadIdx.x & 31) == 0) red8[threadIdx.x >> 5] = v;
    __syncthreads();
    float s = 0.f;
    #pragma unroll
    for (int i = 0; i < 8; i++) s += red8[i];
    return s;
}

// ---------------- prep: per-cloud stats + all weight conversions + gt zero ----------------
struct PrepArgs {
    const float* coord; float* stats; int Lc; int B;
    const float* wsrc[8]; __nv_bfloat16* wdst[8];
    int wK[8], wN[8], wt0[8];
    int totalWTiles;
    float* gt;
};
__global__ void __launch_bounds__(1024) prep_kernel(PrepArgs a) {
    __shared__ float red[1024];
    __shared__ float tt[32][33];
    int b = blockIdx.x, tid = threadIdx.x;
    if (b < a.B) {
        int c = b, Lc = a.Lc;
        float sum[3] = {0,0,0}, mn[3] = {1e30f,1e30f,1e30f}, mx[3] = {-1e30f,-1e30f,-1e30f};
        for (int i = tid; i < Lc; i += 1024) {
            const float* cp = a.coord + (size_t)(c * Lc + i) * 3;
            #pragma unroll
            for (int d = 0; d < 3; d++) {
                float v = cp[d];
                sum[d] += v; mn[d] = fminf(mn[d], v); mx[d] = fmaxf(mx[d], v);
            }
        }
        for (int d = 0; d < 3; d++) {
            red[tid] = sum[d]; __syncthreads();
            for (int s = 512; s > 0; s >>= 1) { if (tid < s) red[tid] += red[tid + s]; __syncthreads(); }
            float tot = red[0]; __syncthreads();
            red[tid] = mn[d]; __syncthreads();
            for (int s = 512; s > 0; s >>= 1) { if (tid < s) red[tid] = fminf(red[tid], red[tid + s]); __syncthreads(); }
            float tmn = red[0]; __syncthreads();
            red[tid] = mx[d]; __syncthreads();
            for (int s = 512; s > 0; s >>= 1) { if (tid < s) red[tid] = fmaxf(red[tid], red[tid + s]); __syncthreads(); }
            float tmx = red[0]; __syncthreads();
            if (tid == 0) {
                float mean = tot / (float)Lc;
                a.stats[c*12 + d]     = mean;
                a.stats[c*12 + 3 + d] = fmaxf(fmaxf(tmx - mean, mean - tmn), 1e-6f);
                a.stats[c*12 + 6 + d] = tmn;
                a.stats[c*12 + 9 + d] = 1.f / fmaxf(tmx - tmn, 1e-6f);
            }
            __syncthreads();
        }
    } else if (b < a.B + a.totalWTiles) {
        int t = b - a.B;
        int w = 0;
        #pragma unroll
        for (int q = 1; q < 8; q++) if (t >= a.wt0[q]) w = q;
        int lt = t - a.wt0[w];
        int tilesX = a.wN[w] >> 5;
        int bx = (lt % tilesX) << 5, by = (lt / tilesX) << 5;
        const float* src = a.wsrc[w];
        __nv_bfloat16* dst = a.wdst[w];
        int K = a.wK[w], Ncols = a.wN[w];
        int tx = tid & 31, ty = tid >> 5;
        tt[ty][tx] = src[(size_t)(by + ty) * Ncols + bx + tx];
        __syncthreads();
        dst[(size_t)(bx + ty) * K + by + tx] = __float2bfloat16(tt[tx][ty]);
    } else {
        a.gt[tid] = 0.f;
        a.gt[tid + 1024] = 0.f;
    }
}

// ---------------- PE + pre-LN + LN1 + key + feats->bf16 ----------------
__global__ void __launch_bounds__(256) pe_ln_key_kernel(
    const float* __restrict__ feats, const float* __restrict__ coord,
    const float* __restrict__ w1, const float* __restrict__ b1,
    const float* __restrict__ w2, const float* __restrict__ b2,
    const float* __restrict__ g, const float* __restrict__ beta,
    const float* __restrict__ n1g, const float* __restrict__ n1b,
    const float* __restrict__ stats,
    float* __restrict__ xout, __nv_bfloat16* __restrict__ hbf,
    __nv_bfloat16* __restrict__ febf,
    float* __restrict__ key, int* __restrict__ idx, int Lc)
{
    int i = blockIdx.x, tid = threadIdx.x;
    int c = i / Lc;
    __shared__ float hid[64];
    __shared__ float red8[8];
    const float* st = stats + c * 12;
    float c0 = coord[(size_t)i*3+0], c1 = coord[(size_t)i*3+1], c2 = coord[(size_t)i*3+2];
    if (tid < 64) {
        float n0 = (c0 - st[0]) / st[3];
        float n1 = (c1 - st[1]) / st[4];
        float n2 = (c2 - st[2]) / st[5];
        float hv = b1[tid] + n0 * w1[tid] + n1 * w1[64 + tid] + n2 * w1[128 + tid];
        hid[tid] = fmaxf(hv, 0.f);
    }
    if (tid == 0) {
        float k0 = (c0 - st[6]) * st[9];
        float k1 = (c1 - st[7]) * st[10];
        float k2 = (c2 - st[8]) * st[11];
        key[i] = k0 + 2.17f * k1 + 3.31f * k2;
        idx[i] = i;
    }
    __syncthreads();
    float fv = feats[(size_t)i * 256 + tid];
    febf[(size_t)i * 256 + tid] = __float2bfloat16(fv);
    float pe = b2[tid];
    #pragma unroll 8
    for (int h = 0; h < 64; h++) pe += hid[h] * w2[h * 256 + tid];
    float v = fv + pe;
    float mean = blocksum256(v, red8) * (1.f / 256.f);
    __syncthreads();
    float dv = v - mean;
    float var = blocksum256(dv * dv, red8) * (1.f / 256.f);
    float xv = dv * rsqrtf(var + 1e-5f) * g[tid] + beta[tid];
    xout[(size_t)i * 256 + tid] = xv;
    __syncthreads();
    float m2 = blocksum256(xv, red8) * (1.f / 256.f);
    __syncthreads();
    float d2 = xv - m2;
    float v2 = blocksum256(d2 * d2, red8) * (1.f / 256.f);
    hbf[(size_t)i * 256 + tid] = __float2bfloat16(d2 * rsqrtf(v2 + 1e-5f) * n1g[tid] + n1b[tid]);
}

// ---------------- hierarchical bitonic sort (CHUNK=16384) ----------------
#define CHUNK 16384
__global__ void __launch_bounds__(1024) sort_local(float* __restrict__ key, int* __restrict__ idx, int Lc) {
    extern __shared__ char smraw[];
    float* sk = (float*)smraw;
    int*   si = (int*)(smraw + CHUNK * 4);
    size_t gbase = (size_t)blockIdx.x * CHUNK;
    int lbase = (int)(gbase % (size_t)Lc);
    for (int t = threadIdx.x; t < CHUNK; t += 1024) { sk[t] = key[gbase + t]; si[t] = idx[gbase + t]; }
    __syncthreads();
    for (int k = 2; k <= CHUNK; k <<= 1) {
        for (int j = k >> 1; j > 0; j >>= 1) {
            #pragma unroll
            for (int it = 0; it < CHUNK / 2048; it++) {
                int t = threadIdx.x + it * 1024;
                int i = 2 * t - (t & (j - 1));
                int p = i + j;
                bool up = (((lbase + i) & k) == 0);
                float a = sk[i], b = sk[p];
                int ia = si[i], ib = si[p];
                bool sw = up ? (a > b || (a == b && ia > ib)) : (a < b || (a == b && ia < ib));
                if (sw) { sk[i] = b; sk[p] = a; si[i] = ib; si[p] = ia; }
            }
            __syncthreads();
        }
    }
    for (int t = threadIdx.x; t < CHUNK; t += 1024) { key[gbase + t] = sk[t]; idx[gbase + t] = si[t]; }
}

__global__ void __launch_bounds__(1024) merge_local(float* __restrict__ key, int* __restrict__ idx, int k, int Lc) {
    extern __shared__ char smraw[];
    float* sk = (float*)smraw;
    int*   si = (int*)(smraw + CHUNK * 4);
    size_t gbase = (size_t)blockIdx.x * CHUNK;
    int lbase = (int)(gbase % (size_t)Lc);
    for (int t = threadIdx.x; t < CHUNK; t += 1024) { sk[t] = key[gbase + t]; si[t] = idx[gbase + t]; }
    __syncthreads();
    for (int j = CHUNK / 2; j > 0; j >>= 1) {
        #pragma unroll
        for (int it = 0; it < CHUNK / 2048; it++) {
            int t = threadIdx.x + it * 1024;
            int i = 2 * t - (t & (j - 1));
            int p = i + j;
            bool up = (((lbase + i) & k) == 0);
            float a = sk[i], b = sk[p];
            int ia = si[i], ib = si[p];
            bool sw = up ? (a > b || (a == b && ia > ib)) : (a < b || (a == b && ia < ib));
            if (sw) { sk[i] = b; sk[p] = a; si[i] = ib; si[p] = ia; }
        }
        __syncthreads();
    }
    for (int t = threadIdx.x; t < CHUNK; t += 1024) { key[gbase + t] = sk[t]; idx[gbase + t] = si[t]; }
}

__global__ void __launch_bounds__(256) sort_global(float* __restrict__ key, int* __restrict__ idx, int k, int j, int Lc) {
    int c = blockIdx.y;
    size_t base = (size_t)c * Lc;
    int t = blockIdx.x * 256 + threadIdx.x;
    int i = 2 * t - (t & (j - 1));
    int p = i + j;
    bool up = ((i & k) == 0);
    float a = key[base + i], b = key[base + p];
    int ia = idx[base + i], ib = idx[base + p];
    bool sw = up ? (a > b || (a == b && ia > ib)) : (a < b || (a == b && ia < ib));
    if (sw) {
        key[base + i] = b; key[base + p] = a;
        idx[base + i] = ib; idx[base + p] = ia;
    }
}

// ---------------- LN -> bf16 ----------------
__global__ void __launch_bounds__(256) ln_bf(const float* __restrict__ x, const float* __restrict__ g,
                                             const float* __restrict__ b, __nv_bfloat16* __restrict__ y) {
    int row = blockIdx.x, tid = threadIdx.x;
    __shared__ float red8[8];
    float v = x[(size_t)row * 256 + tid];
    float mean = blocksum256(v, red8) * (1.f / 256.f);
    __syncthreads();
    float dv = v - mean;
    float var = blocksum256(dv * dv, red8) * (1.f / 256.f);
    y[(size_t)row * 256 + tid] = __float2bfloat16(dv * rsqrtf(var + 1e-5f) * g[tid] + b[tid]);
}

// ---------------- tensor-core GEMM ----------------
// epi: 0 none, 1 relu, 2 gelu, 3 sigmoid, 4 +resid[ridx], 5 resid + gate*val,
//      6 +resid[m]; write bf16 scattered to Cout[ridx[m]]; atomic gt column sums
#define GBM 128
#define GBN 128
#define GKT 32
#define STG_BYTES 20480

__global__ void __launch_bounds__(256) gemm_bf16(
    const __nv_bfloat16* __restrict__ A,
    const __nv_bfloat16* __restrict__ Bt,
    const float* __restrict__ bias,
    const float* __restrict__ resid,
    const float* __restrict__ gate,
    void* __restrict__ Cout,
    int M, int Ncols, int K, int cloudLen, int epi, int outBf16,
    const int* __restrict__ aidx, const int* __restrict__ ridx,
    float* __restrict__ gtp, int gtLc)
{
    extern __shared__ char smraw[];
    const int tid = threadIdx.x;
    const int lane = tid & 31;
    const int warp = tid >> 5;
    const int wm = warp >> 1, wn = warp & 1;
    const int m0 = blockIdx.y * GBM, n0 = blockIdx.x * GBN;

    float acc[2][8][4];
    #pragma unroll
    for (int i = 0; i < 2; i++)
        #pragma unroll
        for (int j = 0; j < 8; j++)
            #pragma unroll
            for (int q = 0; q < 4; q++) acc[i][j][q] = 0.f;

    const int ldrow0 = tid >> 2, ldc0 = tid & 3;
    const int ldrow1 = (tid + 256) >> 2, ldc1 = tid & 3;
    const size_t arow0 = (size_t)(aidx ? aidx[m0 + ldrow0] : (m0 + ldrow0)) * K;
    const size_t arow1 = (size_t)(aidx ? aidx[m0 + ldrow1] : (m0 + ldrow1)) * K;

    auto issue = [&](int s, int kt) {
        char* sA = smraw + s * STG_BYTES;
        char* sB = sA + 10240;
        {
            const __nv_bfloat16* gA = A + arow0 + kt * GKT + ldc0 * 8;
            uint32_t d = smem_u32(sA + ldrow0 * 80 + ldc0 * 16);
            asm volatile("cp.async.cg.shared.global [%0], [%1], 16;\n" :: "r"(d), "l"(gA));
            const __nv_bfloat16* gB = Bt + (size_t)(n0 + ldrow0) * K + kt * GKT + ldc0 * 8;
            uint32_t d2 = smem_u32(sB + ldrow0 * 80 + ldc0 * 16);
            asm volatile("cp.async.cg.shared.global [%0], [%1], 16;\n" :: "r"(d2), "l"(gB));
        }
        {
            const __nv_bfloat16* gA = A + arow1 + kt * GKT + ldc1 * 8;
            uint32_t d = smem_u32(sA + ldrow1 * 80 + ldc1 * 16);
            asm volatile("cp.async.cg.shared.global [%0], [%1], 16;\n" :: "r"(d), "l"(gA));
            const __nv_bfloat16* gB = Bt + (size_t)(n0 + ldrow1) * K + kt * GKT + ldc1 * 8;
            uint32_t d2 = smem_u32(sB + ldrow1 * 80 + ldc1 * 16);
            asm volatile("cp.async.cg.shared.global [%0], [%1], 16;\n" :: "r"(d2), "l"(gB));
        }
        asm volatile("cp.async.commit_group;\n");
    };

    const int nk = K / GKT;
    issue(0, 0);
    for (int kt = 0; kt < nk; kt++) {
        int s = kt & 1;
        if (kt + 1 < nk) {
            issue((kt + 1) & 1, kt + 1);
            asm volatile("cp.async.wait_group 1;\n");
        } else {
            asm volatile("cp.async.wait_group 0;\n");
        }
        __syncthreads();

        char* sA = smraw + s * STG_BYTES;
        char* sB = sA + 10240;
        #pragma unroll
        for (int kk = 0; kk < 2; kk++) {
            uint32_t af[2][4];
            #pragma unroll
            for (int i = 0; i < 2; i++) {
                int r = wm * 32 + i * 16 + (lane & 15);
                int c = kk * 2 + (lane >> 4);
                uint32_t addr = smem_u32(sA + r * 80 + c * 16);
                asm volatile("ldmatrix.sync.aligned.m8n8.x4.shared.b16 {%0,%1,%2,%3}, [%4];"
                             : "=r"(af[i][0]), "=r"(af[i][1]), "=r"(af[i][2]), "=r"(af[i][3])
                             : "r"(addr));
            }
            uint32_t bf[8][2];
            #pragma unroll
            for (int jp = 0; jp < 4; jp++) {
                int r = wn * 64 + jp * 16 + (lane & 15);
                int c = kk * 2 + (lane >> 4);
                uint32_t addr = smem_u32(sB + r * 80 + c * 16);
                uint32_t r0, r1, r2, r3;
                asm volatile("ldmatrix.sync.aligned.m8n8.x4.shared.b16 {%0,%1,%2,%3}, [%4];"
                             : "=r"(r0), "=r"(r1), "=r"(r2), "=r"(r3) : "r"(addr));
                bf[2*jp][0] = r0; bf[2*jp+1][0] = r1;
                bf[2*jp][1] = r2; bf[2*jp+1][1] = r3;
            }
            #pragma unroll
            for (int i = 0; i < 2; i++)
                #pragma unroll
                for (int j = 0; j < 8; j++) {
                    asm volatile("mma.sync.aligned.m16n8k16.row.col.f32.bf16.bf16.f32 "
                                 "{%0,%1,%2,%3}, {%4,%5,%6,%7}, {%8,%9}, {%0,%1,%2,%3};"
                                 : "+f"(acc[i][j][0]), "+f"(acc[i][j][1]),
                                   "+f"(acc[i][j][2]), "+f"(acc[i][j][3])
                                 : "r"(af[i][0]), "r"(af[i][1]), "r"(af[i][2]), "r"(af[i][3]),
                                   "r"(bf[j][0]), "r"(bf[j][1]));
                }
        }
        __syncthreads();
    }

    const int rbase = m0 + wm * 32 + (lane >> 2);
    const int cbase = n0 + wn * 64 + 2 * (lane & 3);
    float gta[8][2];
    #pragma unroll
    for (int j = 0; j < 8; j++) { gta[j][0] = 0.f; gta[j][1] = 0.f; }

    #pragma unroll
    for (int i = 0; i < 2; i++) {
        #pragma unroll
        for (int half = 0; half < 2; half++) {
            int m = rbase + i * 16 + half * 8;
            const float* bp = (cloudLen > 0) ? (bias + (size_t)(m / cloudLen) * Ncols) : bias;
            #pragma unroll
            for (int j = 0; j < 8; j++) {
                int n = cbase + j * 8;
                float v0 = acc[i][j][half * 2 + 0] + bp[n];
                float v1 = acc[i][j][half * 2 + 1] + bp[n + 1];
                size_t o = (size_t)m * Ncols + n;
                bool stored = false;
                switch (epi) {
                    case 1: v0 = fmaxf(v0, 0.f); v1 = fmaxf(v1, 0.f); break;
                    case 2:
                        v0 = 0.5f * v0 * (1.f + erff(v0 * 0.70710678118f));
                        v1 = 0.5f * v1 * (1.f + erff(v1 * 0.70710678118f));
                        break;
                    case 3:
                        v0 = frcp_fast(1.f + fexpf_fast(-v0));
                        v1 = frcp_fast(1.f + fexpf_fast(-v1));
                        break;
                    case 4: {
                        size_t ro = (size_t)(ridx ? ridx[m] : m) * Ncols + n;
                        float2 r = *(const float2*)(resid + ro);
                        v0 += r.x; v1 += r.y;
                    } break;
                    case 5: {
                        float2 r = *(const float2*)(resid + o);
                        float2 gg = *(const float2*)(gate + o);
                        v0 = r.x + gg.x * v0; v1 = r.y + gg.y * v1;
                    } break;
                    case 6: {
                        float2 r = *(const float2*)(resid + o);
                        v0 += r.x; v1 += r.y;
                        gta[j][0] += v0; gta[j][1] += v1;
                        size_t od = (size_t)ridx[m] * Ncols + n;
                        __nv_bfloat162 h;
                        h.x = __float2bfloat16(v0); h.y = __float2bfloat16(v1);
                        *(__nv_bfloat162*)((__nv_bfloat16*)Cout + od) = h;
                        stored = true;
                    } break;
                    default: break;
                }
                if (!stored) {
                    if (outBf16) {
                        __nv_bfloat162 h;
                        h.x = __float2bfloat16(v0); h.y = __float2bfloat16(v1);
                        *(__nv_bfloat162*)((__nv_bfloat16*)Cout + o) = h;
                    } else {
                        *(float2*)((float*)Cout + o) = make_float2(v0, v1);
                    }
                }
            }
        }
    }
    if (epi == 6) {
        int c = m0 / gtLc;
        #pragma unroll
        for (int j = 0; j < 8; j++) {
            float s0 = gta[j][0], s1 = gta[j][1];
            #pragma unroll
            for (int off = 4; off <= 16; off <<= 1) {
                s0 += __shfl_xor_sync(0xffffffffu, s0, off);
                s1 += __shfl_xor_sync(0xffffffffu, s1, off);
            }
            if ((lane >> 2) == 0) {
                int n = cbase + j * 8;
                atomicAdd(gtp + c * 256 + n, s0);
                atomicAdd(gtp + c * 256 + n + 1, s1);
            }
        }
    }
}

// ---------------- flash attention on tensor cores ----------------
#define FA_SMEM (20480 * 2 + 32 * 528)
__global__ void __launch_bounds__(256) fattn(const __nv_bfloat16* __restrict__ qkv,
                                             __nv_bfloat16* __restrict__ o) {
    extern __shared__ char sm[];
    char* sq = sm;
    char* sk = sm + 20480;
    char* svt = sm + 40960;
    const int p = blockIdx.x, h = blockIdx.y;
    const int tid = threadIdx.x;
    const int lane = tid & 31;
    const int w = tid >> 5;
    const size_t base = (size_t)p * 256;
    const float SC = 0.17677669529663687f * 1.4426950408889634f;

    {
        const uint4* qr = (const uint4*)(qkv + (base + tid) * 768 + h * 32);
        const uint4* kr = (const uint4*)(qkv + (base + tid) * 768 + 256 + h * 32);
        const uint4* vr = (const uint4*)(qkv + (base + tid) * 768 + 512 + h * 32);
        uint4* dq = (uint4*)(sq + tid * 80);
        uint4* dk = (uint4*)(sk + tid * 80);
        uint4 v0 = vr[0], v1 = vr[1], v2 = vr[2], v3 = vr[3];
        dq[0] = qr[0]; dq[1] = qr[1]; dq[2] = qr[2]; dq[3] = qr[3];
        dk[0] = kr[0]; dk[1] = kr[1]; dk[2] = kr[2]; dk[3] = kr[3];
        uint32_t vu[8] = {v0.x, v0.y, v0.z, v0.w, v1.x, v1.y, v1.z, v1.w};
        uint32_t vu2[8] = {v2.x, v2.y, v2.z, v2.w, v3.x, v3.y, v3.z, v3.w};
        #pragma unroll
        for (int e = 0; e < 8; e++) {
            ((__nv_bfloat16*)(svt + (2 * e + 0) * 528))[tid] = ((__nv_bfloat162*)&vu[e])->x;
            ((__nv_bfloat16*)(svt + (2 * e + 1) * 528))[tid] = ((__nv_bfloat162*)&vu[e])->y;
        }
        #pragma unroll
        for (int e = 0; e < 8; e++) {
            ((__nv_bfloat16*)(svt + (16 + 2 * e + 0) * 528))[tid] = ((__nv_bfloat162*)&vu2[e])->x;
            ((__nv_bfloat16*)(svt + (16 + 2 * e + 1) * 528))[tid] = ((__nv_bfloat162*)&vu2[e])->y;
        }
    }
    __syncthreads();

    const int m0w = w * 32;
    uint32_t qa[2][2][4];
    #pragma unroll
    for (int i = 0; i < 2; i++)
        #pragma unroll
        for (int kk = 0; kk < 2; kk++) {
            int r = m0w + i * 16 + (lane & 15);
            uint32_t addr = smem_u32(sq + r * 80 + kk * 32 + (lane >> 4) * 16);
            asm volatile("ldmatrix.sync.aligned.m8n8.x4.shared.b16 {%0,%1,%2,%3}, [%4];"
                         : "=r"(qa[i][kk][0]), "=r"(qa[i][kk][1]),
                           "=r"(qa[i][kk][2]), "=r"(qa[i][kk][3])
                         : "r"(addr));
        }

    float oacc[2][4][4];
    #pragma unroll
    for (int i = 0; i < 2; i++)
        #pragma unroll
        for (int d = 0; d < 4; d++)
            #pragma unroll
            for (int q = 0; q < 4; q++) oacc[i][d][q] = 0.f;
    float mrow[2][2] = {{-1e30f, -1e30f}, {-1e30f, -1e30f}};
    float lrow[2][2] = {{0.f, 0.f}, {0.f, 0.f}};

    for (int jc = 0; jc < 8; jc++) {
        uint32_t kb[2][4][2];
        #pragma unroll
        for (int jp = 0; jp < 2; jp++)
            #pragma unroll
            for (int kk = 0; kk < 2; kk++) {
                int r = jc * 32 + jp * 16 + (lane & 15);
                uint32_t addr = smem_u32(sk + r * 80 + kk * 32 + (lane >> 4) * 16);
                uint32_t r0, r1, r2, r3;
                asm volatile("ldmatrix.sync.aligned.m8n8.x4.shared.b16 {%0,%1,%2,%3}, [%4];"
                             : "=r"(r0), "=r"(r1), "=r"(r2), "=r"(r3) : "r"(addr));
                kb[kk][2*jp][0] = r0;   kb[kk][2*jp][1] = r2;
                kb[kk][2*jp+1][0] = r1; kb[kk][2*jp+1][1] = r3;
            }

        float sacc[2][4][4];
        #pragma unroll
        for (int i = 0; i < 2; i++)
            #pragma unroll
            for (int nt = 0; nt < 4; nt++)
                #pragma unroll
                for (int q = 0; q < 4; q++) sacc[i][nt][q] = 0.f;
        #pragma unroll
        for (int kk = 0; kk < 2; kk++)
            #pragma unroll
            for (int i = 0; i < 2; i++)
                #pragma unroll
                for (int nt = 0; nt < 4; nt++) {
                    asm volatile("mma.sync.aligned.m16n8k16.row.col.f32.bf16.bf16.f32 "
                                 "{%0,%1,%2,%3}, {%4,%5,%6,%7}, {%8,%9}, {%0,%1,%2,%3};"
                                 : "+f"(sacc[i][nt][0]), "+f"(sacc[i][nt][1]),
                                   "+f"(sacc[i][nt][2]), "+f"(sacc[i][nt][3])
                                 : "r"(qa[i][kk][0]), "r"(qa[i][kk][1]),
                                   "r"(qa[i][kk][2]), "r"(qa[i][kk][3]),
                                   "r"(kb[kk][nt][0]), "r"(kb[kk][nt][1]));
                }

        #pragma unroll
        for (int i = 0; i < 2; i++)
            #pragma unroll
            for (int nt = 0; nt < 4; nt++)
                #pragma unroll
                for (int q = 0; q < 4; q++) sacc[i][nt][q] *= SC;

        #pragma unroll
        for (int i = 0; i < 2; i++) {
            #pragma unroll
            for (int half = 0; half < 2; half++) {
                float mx = -1e30f;
                #pragma unroll
                for (int nt = 0; nt < 4; nt++) {
                    mx = fmaxf(mx, sacc[i][nt][half*2+0]);
                    mx = fmaxf(mx, sacc[i][nt][half*2+1]);
                }
                mx = fmaxf(mx, __shfl_xor_sync(0xffffffffu, mx, 1));
                mx = fmaxf(mx, __shfl_xor_sync(0xffffffffu, mx, 2));
                float newm = fmaxf(mrow[i][half], mx);
                float alpha = fexp2_fast(mrow[i][half] - newm);
                mrow[i][half] = newm;
                float rs = 0.f;
                #pragma unroll
                for (int nt = 0; nt < 4; nt++) {
                    float p0 = fexp2_fast(sacc[i][nt][half*2+0] - newm);
                    float p1 = fexp2_fast(sacc[i][nt][half*2+1] - newm);
                    sacc[i][nt][half*2+0] = p0;
                    sacc[i][nt][half*2+1] = p1;
                    rs += p0 + p1;
                }
                rs += __shfl_xor_sync(0xffffffffu, rs, 1);
                rs += __shfl_xor_sync(0xffffffffu, rs, 2);
                lrow[i][half] = lrow[i][half] * alpha + rs;
                #pragma unroll
                for (int dt = 0; dt < 4; dt++) {
                    oacc[i][dt][half*2+0] *= alpha;
                    oacc[i][dt][half*2+1] *= alpha;
                }
            }
        }

        uint32_t pa[2][2][4];
        #pragma unroll
        for (int i = 0; i < 2; i++)
            #pragma unroll
            for (int kk = 0; kk < 2; kk++) {
                int ntl = kk * 2, nth = kk * 2 + 1;
                __nv_bfloat162 b0 = __float22bfloat162_rn(make_float2(sacc[i][ntl][0], sacc[i][ntl][1]));
                __nv_bfloat162 b1 = __float22bfloat162_rn(make_float2(sacc[i][ntl][2], sacc[i][ntl][3]));
                __nv_bfloat162 b2 = __float22bfloat162_rn(make_float2(sacc[i][nth][0], sacc[i][nth][1]));
                __nv_bfloat162 b3 = __float22bfloat162_rn(make_float2(sacc[i][nth][2], sacc[i][nth][3]));
                pa[i][kk][0] = *(uint32_t*)&b0;
                pa[i][kk][1] = *(uint32_t*)&b1;
                pa[i][kk][2] = *(uint32_t*)&b2;
                pa[i][kk][3] = *(uint32_t*)&b3;
            }

        uint32_t vb[2][4][2];
        #pragma unroll
        for (int jp = 0; jp < 2; jp++)
            #pragma unroll
            for (int kk = 0; kk < 2; kk++) {
                int r = jp * 16 + (lane & 15);
                uint32_t addr = smem_u32(svt + r * 528 + jc * 64 + kk * 32 + (lane >> 4) * 16);
                uint32_t r0, r1, r2, r3;
                asm volatile("ldmatrix.sync.aligned.m8n8.x4.shared.b16 {%0,%1,%2,%3}, [%4];"
                             : "=r"(r0), "=r"(r1), "=r"(r2), "=r"(r3) : "r"(addr));
                vb[kk][2*jp][0] = r0;   vb[kk][2*jp][1] = r2;
                vb[kk][2*jp+1][0] = r1; vb[kk][2*jp+1][1] = r3;
            }

        #pragma unroll
        for (int kk = 0; kk < 2; kk++)
            #pragma unroll
            for (int i = 0; i < 2; i++)
                #pragma unroll
                for (int dt = 0; dt < 4; dt++) {
                    asm volatile("mma.sync.aligned.m16n8k16.row.col.f32.bf16.bf16.f32 "
                                 "{%0,%1,%2,%3}, {%4,%5,%6,%7}, {%8,%9}, {%0,%1,%2,%3};"
                                 : "+f"(oacc[i][dt][0]), "+f"(oacc[i][dt][1]),
                                   "+f"(oacc[i][dt][2]), "+f"(oacc[i][dt][3])
                                 : "r"(pa[i][kk][0]), "r"(pa[i][kk][1]),
                                   "r"(pa[i][kk][2]), "r"(pa[i][kk][3]),
                                   "r"(vb[kk][dt][0]), "r"(vb[kk][dt][1]));
                }
    }

    #pragma unroll
    for (int i = 0; i < 2; i++)
        #pragma unroll
        for (int half = 0; half < 2; half++) {
            float inv = 1.f / lrow[i][half];
            int row = m0w + i * 16 + half * 8 + (lane >> 2);
            #pragma unroll
            for (int dt = 0; dt < 4; dt++) {
                int col = h * 32 + dt * 8 + 2 * (lane & 3);
                __nv_bfloat162 hv;
                hv.x = __float2bfloat16(oacc[i][dt][half*2+0] * inv);
                hv.y = __float2bfloat16(oacc[i][dt][half*2+1] * inv);
                *(__nv_bfloat162*)(o + (base + row) * 256 + col) = hv;
            }
        }
}

// ---------------- fold gt into per-cloud biases ----------------
__global__ void cloudbias_kernel(const float* __restrict__ gtsum,
                                 const float* __restrict__ gg_w1, const float* __restrict__ gg_b1,
                                 const float* __restrict__ f_w1, const float* __restrict__ f_b1,
                                 float* __restrict__ ggb, float* __restrict__ fb, int Lc) {
    int c = blockIdx.x, j = threadIdx.x;
    float s1 = gg_b1[j], s2 = f_b1[j];
    float invL = 1.f / (float)Lc;
    for (int h = 0; h < 256; h++) {
        float gv = gtsum[c * 256 + h] * invL;
        s1 += gv * gg_w1[(size_t)(256 + h) * 256 + j];
        s2 += gv * f_w1[(size_t)(256 + h) * 256 + j];
    }
    ggb[c * 256 + j] = s1;
    fb[c * 256 + j] = s2;
}

// ---------------- launch ----------------
extern "C" void kernel_launch(void* const* d_in, const int* in_sizes, int n_in,
                              void* d_out, int out_size) {
    const float* feats = (const float*)d_in[0];
    const float* coord = (const float*)d_in[1];
    const float* pe_w1 = (const float*)d_in[3];
    const float* pe_b1 = (const float*)d_in[4];
    const float* pe_w2 = (const float*)d_in[5];
    const float* pe_b2 = (const float*)d_in[6];
    const float* pre_g = (const float*)d_in[7];
    const float* pre_b = (const float*)d_in[8];
    const float* n1_g  = (const float*)d_in[9];
    const float* n1_b  = (const float*)d_in[10];
    const float* wqkv  = (const float*)d_in[11];
    const float* bqkv  = (const float*)d_in[12];
    const float* wo    = (const float*)d_in[13];
    const float* bo    = (const float*)d_in[14];
    const float* n2_g  = (const float*)d_in[15];
    const float* n2_b  = (const float*)d_in[16];
    const float* m_w1  = (const float*)d_in[17];
    const float* m_b1  = (const float*)d_in[18];
    const float* m_w2  = (const float*)d_in[19];
    const float* m_b2  = (const float*)d_in[20];
    const float* gg_w1 = (const float*)d_in[21];
    const float* gg_b1 = (const float*)d_in[22];
    const float* gg_w2 = (const float*)d_in[23];
    const float* gg_b2 = (const float*)d_in[24];
    const float* f_w1  = (const float*)d_in[25];
    const float* f_b1  = (const float*)d_in[26];
    const float* f_w2  = (const float*)d_in[27];
    const float* f_b2  = (const float*)d_in[28];
    float* out = (float*)d_out;

    int N = in_sizes[0] / 256;
    int B = in_sizes[2];
    int Lc = N / B;
    int patches = N / 256;

    float *p_x, *p_xs, *p_key, *p_gt, *p_ggb, *p_fb, *p_stats;
    __nv_bfloat16 *p_ba, *p_bb, *p_fe, *p_wt;
    int* p_idx;
    cudaGetSymbolAddress((void**)&p_x, g_x);
    cudaGetSymbolAddress((void**)&p_xs, g_xs);
    cudaGetSymbolAddress((void**)&p_ba, g_ba);
    cudaGetSymbolAddress((void**)&p_bb, g_bb);
    cudaGetSymbolAddress((void**)&p_fe, g_fe);
    cudaGetSymbolAddress((void**)&p_wt, g_wt);
    cudaGetSymbolAddress((void**)&p_key, g_key);
    cudaGetSymbolAddress((void**)&p_idx, g_idx);
    cudaGetSymbolAddress((void**)&p_gt, g_gt);
    cudaGetSymbolAddress((void**)&p_ggb, g_ggb);
    cudaGetSymbolAddress((void**)&p_fb, g_fb);
    cudaGetSymbolAddress((void**)&p_stats, g_stats);

    __nv_bfloat16* wqkv_t = p_wt + 0;
    __nv_bfloat16* wo_t   = p_wt + 196608;
    __nv_bfloat16* mw1_t  = p_wt + 262144;
    __nv_bfloat16* mw2_t  = p_wt + 393216;
    __nv_bfloat16* ggw1_t = p_wt + 524288;
    __nv_bfloat16* ggw2_t = p_wt + 589824;
    __nv_bfloat16* fw1_t  = p_wt + 655360;
    __nv_bfloat16* fw2_t  = p_wt + 720896;

    cudaFuncSetAttribute(fattn, cudaFuncAttributeMaxDynamicSharedMemorySize, FA_SMEM);
    cudaFuncSetAttribute(sort_local, cudaFuncAttributeMaxDynamicSharedMemorySize, CHUNK * 8);
    cudaFuncSetAttribute(merge_local, cudaFuncAttributeMaxDynamicSharedMemorySize, CHUNK * 8);

    // prep: stats (B blocks) + weight tiles (768) + gt zero (1)
    PrepArgs pa;
    pa.coord = coord; pa.stats = p_stats; pa.Lc = Lc; pa.B = B;
    const float* ws[8] = {wqkv, wo, m_w1, m_w2, gg_w1, gg_w2, f_w1, f_w2};
    __nv_bfloat16* wd[8] = {wqkv_t, wo_t, mw1_t, mw2_t, ggw1_t, ggw2_t, fw1_t, fw2_t};
    int wK[8] = {256, 256, 256, 512, 256, 256, 256, 256};
    int wN[8] = {768, 256, 512, 256, 256, 256, 256, 256};
    int tiles = 0;
    for (int i = 0; i < 8; i++) {
        pa.wsrc[i] = ws[i]; pa.wdst[i] = wd[i];
        pa.wK[i] = wK[i]; pa.wN[i] = wN[i];
        pa.wt0[i] = tiles;
        tiles += (wK[i] / 32) * (wN[i] / 32);
    }
    pa.totalWTiles = tiles;
    pa.gt = p_gt;

    // launch 1: prep
    prep_kernel<<<B + tiles + 1, 1024>>>(pa);
    // launch 2: PE + pre-LN + LN1 + key + feats bf16
    pe_ln_key_kernel<<<N, 256>>>(feats, coord, pe_w1, pe_b1, pe_w2, pe_b2,
                                 pre_g, pre_b, n1_g, n1_b, p_stats,
                                 p_x, p_bb, p_fe, p_key, p_idx, Lc);
    // launches 3-5: sort
    sort_local<<<N / CHUNK, 1024, CHUNK * 8>>>(p_key, p_idx, Lc);
    for (int k = CHUNK * 2; k <= Lc; k <<= 1) {
        for (int j = k >> 1; j >= CHUNK; j >>= 1)
            sort_global<<<dim3(Lc / 512, B), 256>>>(p_key, p_idx, k, j, Lc);
        merge_local<<<N / CHUNK, 1024, CHUNK * 8>>>(p_key, p_idx, k, Lc);
    }
    // launch 6: qkv GEMM (A = unpermuted LN1 out, gathered by idx) -> ba bf16
    gemm_bf16<<<dim3(768/GBN, N/GBM), 256, 2*STG_BYTES>>>(p_bb, wqkv_t, bqkv, nullptr, nullptr,
                                                          p_ba, N, 768, 256, 0, 0, 1,
                                                          p_idx, nullptr, nullptr, 0);
    // launch 7: flash attention -> bb
    fattn<<<dim3(patches, 8), 256, FA_SMEM>>>(p_ba, p_bb);
    // launch 8: wo GEMM + gathered residual -> xs fp32 (serialized)
    gemm_bf16<<<dim3(256/GBN, N/GBM), 256, 2*STG_BYTES>>>(p_bb, wo_t, bo, p_x, nullptr,
                                                          p_xs, N, 256, 256, 0, 4, 0,
                                                          nullptr, p_idx, nullptr, 0);
    // launch 9: LN2 -> ba bf16
    ln_bf<<<N, 256>>>(p_xs, n2_g, n2_b, p_ba);
    // launch 10: MLP1 + gelu -> bb bf16
    gemm_bf16<<<dim3(512/GBN, N/GBM), 256, 2*STG_BYTES>>>(p_ba, mw1_t, m_b1, nullptr, nullptr,
                                                          p_bb, N, 512, 256, 0, 2, 1,
                                                          nullptr, nullptr, nullptr, 0);
    // launch 11: MLP2 + resid; scatter xo bf16 into ba; gt partial sums
    gemm_bf16<<<dim3(256/GBN, N/GBM), 256, 2*STG_BYTES>>>(p_bb, mw2_t, m_b2, p_xs, nullptr,
                                                          p_ba, N, 256, 512, 0, 6, 1,
                                                          nullptr, p_idx, p_gt, Lc);
    // launch 12: fold gt into per-cloud biases
    cloudbias_kernel<<<B, 256>>>(p_gt, gg_w1, gg_b1, f_w1, f_b1, p_ggb, p_fb, Lc);
    // launch 13: gate hidden -> bb bf16
    gemm_bf16<<<dim3(256/GBN, N/GBM), 256, 2*STG_BYTES>>>(p_fe, ggw1_t, p_ggb, nullptr, nullptr,
                                                          p_bb, N, 256, 256, Lc, 1, 1,
                                                          nullptr, nullptr, nullptr, 0);
    // launch 14: gate sigmoid -> p_x fp32
    gemm_bf16<<<dim3(256/GBN, N/GBM), 256, 2*STG_BYTES>>>(p_bb, ggw2_t, gg_b2, nullptr, nullptr,
                                                          p_x, N, 256, 256, 0, 3, 0,
                                                          nullptr, nullptr, nullptr, 0);
    // launch 15: fuse hidden -> bb bf16
    gemm_bf16<<<dim3(256/GBN, N/GBM), 256, 2*STG_BYTES>>>(p_ba, fw1_t, p_fb, nullptr, nullptr,
                                                          p_bb, N, 256, 256, Lc, 1, 1,
                                                          nullptr, nullptr, nullptr, 0);
    // launch 16: out = feats + gate * (hidden @ f_w2 + f_b2)
    gemm_bf16<<<dim3(256/GBN, N/GBM), 256, 2*STG_BYTES>>>(p_bb, fw2_t, f_b2, feats, p_x,
                                                          out, N, 256, 256, 0, 5, 0,
                                                          nullptr, nullptr, nullptr, 0);
}

// round 6
// speedup vs baseline: 3.7531x; 1.0087x over previous
#include <cuda_runtime.h>
#include <cuda_bf16.h>
#include <math.h>
#include <stdint.h>

// ---------------- static scratch ----------------
#define MAXN 131072
#define DD 256
__device__ float g_x  [(size_t)MAXN * DD];           // pre-LN out fp32 (orig order) -> gate fp32
__device__ float g_xs [(size_t)MAXN * DD];           // serialized residual stream fp32
__device__ __nv_bfloat16 g_ba[(size_t)MAXN * 768];   // qkv bf16 (orig order) -> ln2 out -> xo
__device__ __nv_bfloat16 g_bb[(size_t)MAXN * 512];   // ln1 out -> attn out -> mlp hidden -> gate|fuse hidden
__device__ __nv_bfloat16 g_fe[(size_t)MAXN * 256];   // feats bf16
__device__ __nv_bfloat16 g_wt[786432];
__device__ float g_key[MAXN];
__device__ int   g_idx[MAXN];
__device__ float g_gt [8 * DD];
__device__ float g_ggb[8 * DD];
__device__ float g_fb [8 * DD];
__device__ float g_stats[8 * 12];

// ---------------- fast math ----------------
__device__ __forceinline__ float fexp2_fast(float z) {
    z = fmaxf(z, -80.f);
    float n = rintf(z);
    float f = z - n;
    float p = 0.009618129f;
    p = p * f + 0.055504109f;
    p = p * f + 0.240226507f;
    p = p * f + 0.693147181f;
    p = p * f + 1.0f;
    return p * __int_as_float(((int)n + 127) << 23);
}
__device__ __forceinline__ float fexpf_fast(float x) {
    return fexp2_fast(x * 1.4426950408889634f);
}
__device__ __forceinline__ float frcp_fast(float d) {
    float y = __int_as_float(0x7ef311c3 - __float_as_int(d));
    y = y * (2.f - d * y);
    y = y * (2.f - d * y);
    y = y * (2.f - d * y);
    return y;
}
__device__ __forceinline__ uint32_t smem_u32(const void* p) {
    return (uint32_t)__cvta_generic_to_shared(p);
}
__device__ __forceinline__ float blocksum256(float v, float* red8) {
    #pragma unroll
    for (int off = 16; off; off >>= 1) v += __shfl_xor_sync(0xffffffffu, v, off);
    if ((threadIdx.x & 31) == 0) red8[threadIdx.x >> 5] = v;
    __syncthreads();
    float s = 0.f;
    #pragma unroll
    for (int i = 0; i < 8; i++) s += red8[i];
    return s;
}

// ---------------- prep ----------------
struct PrepArgs {
    const float* coord; float* stats; int Lc; int B;
    const float* wsrc[8]; __nv_bfloat16* wdst[8];
    int wK[8], wN[8], wt0[8];
    int totalWTiles;
    float* gt;
};
__global__ void __launch_bounds__(1024) prep_kernel(PrepArgs a) {
    __shared__ float red[1024];
    __shared__ float tt[32][33];
    int b = blockIdx.x, tid = threadIdx.x;
    if (b < a.B) {
        int c = b, Lc = a.Lc;
        float sum[3] = {0,0,0}, mn[3] = {1e30f,1e30f,1e30f}, mx[3] = {-1e30f,-1e30f,-1e30f};
        for (int i = tid; i < Lc; i += 1024) {
            const float* cp = a.coord + (size_t)(c * Lc + i) * 3;
            #pragma unroll
            for (int d = 0; d < 3; d++) {
                float v = cp[d];
                sum[d] += v; mn[d] = fminf(mn[d], v); mx[d] = fmaxf(mx[d], v);
            }
        }
        for (int d = 0; d < 3; d++) {
            red[tid] = sum[d]; __syncthreads();
            for (int s = 512; s > 0; s >>= 1) { if (tid < s) red[tid] += red[tid + s]; __syncthreads(); }
            float tot = red[0]; __syncthreads();
            red[tid] = mn[d]; __syncthreads();
            for (int s = 512; s > 0; s >>= 1) { if (tid < s) red[tid] = fminf(red[tid], red[tid + s]); __syncthreads(); }
            float tmn = red[0]; __syncthreads();
            red[tid] = mx[d]; __syncthreads();
            for (int s = 512; s > 0; s >>= 1) { if (tid < s) red[tid] = fmaxf(red[tid], red[tid + s]); __syncthreads(); }
            float tmx = red[0]; __syncthreads();
            if (tid == 0) {
                float mean = tot / (float)Lc;
                a.stats[c*12 + d]     = mean;
                a.stats[c*12 + 3 + d] = fmaxf(fmaxf(tmx - mean, mean - tmn), 1e-6f);
                a.stats[c*12 + 6 + d] = tmn;
                a.stats[c*12 + 9 + d] = 1.f / fmaxf(tmx - tmn, 1e-6f);
            }
            __syncthreads();
        }
    } else if (b < a.B + a.totalWTiles) {
        int t = b - a.B;
        int w = 0;
        #pragma unroll
        for (int q = 1; q < 8; q++) if (t >= a.wt0[q]) w = q;
        int lt = t - a.wt0[w];
        int tilesX = a.wN[w] >> 5;
        int bx = (lt % tilesX) << 5, by = (lt / tilesX) << 5;
        const float* src = a.wsrc[w];
        __nv_bfloat16* dst = a.wdst[w];
        int K = a.wK[w], Ncols = a.wN[w];
        int tx = tid & 31, ty = tid >> 5;
        tt[ty][tx] = src[(size_t)(by + ty) * Ncols + bx + tx];
        __syncthreads();
        dst[(size_t)(bx + ty) * K + by + tx] = __float2bfloat16(tt[tx][ty]);
    } else {
        a.gt[tid] = 0.f;
        a.gt[tid + 1024] = 0.f;
    }
}

// ---------------- PE + pre-LN + LN1 + key + feats->bf16 ----------------
__global__ void __launch_bounds__(256) pe_ln_key_kernel(
    const float* __restrict__ feats, const float* __restrict__ coord,
    const float* __restrict__ w1, const float* __restrict__ b1,
    const float* __restrict__ w2, const float* __restrict__ b2,
    const float* __restrict__ g, const float* __restrict__ beta,
    const float* __restrict__ n1g, const float* __restrict__ n1b,
    const float* __restrict__ stats,
    float* __restrict__ xout, __nv_bfloat16* __restrict__ hbf,
    __nv_bfloat16* __restrict__ febf,
    float* __restrict__ key, int* __restrict__ idx, int Lc)
{
    int i = blockIdx.x, tid = threadIdx.x;
    int c = i / Lc;
    __shared__ float hid[64];
    __shared__ float red8[8];
    const float* st = stats + c * 12;
    float c0 = coord[(size_t)i*3+0], c1 = coord[(size_t)i*3+1], c2 = coord[(size_t)i*3+2];
    if (tid < 64) {
        float n0 = (c0 - st[0]) / st[3];
        float n1 = (c1 - st[1]) / st[4];
        float n2 = (c2 - st[2]) / st[5];
        float hv = b1[tid] + n0 * w1[tid] + n1 * w1[64 + tid] + n2 * w1[128 + tid];
        hid[tid] = fmaxf(hv, 0.f);
    }
    if (tid == 0) {
        float k0 = (c0 - st[6]) * st[9];
        float k1 = (c1 - st[7]) * st[10];
        float k2 = (c2 - st[8]) * st[11];
        key[i] = k0 + 2.17f * k1 + 3.31f * k2;
        idx[i] = i;
    }
    __syncthreads();
    float fv = feats[(size_t)i * 256 + tid];
    febf[(size_t)i * 256 + tid] = __float2bfloat16(fv);
    float pe = b2[tid];
    #pragma unroll 8
    for (int h = 0; h < 64; h++) pe += hid[h] * w2[h * 256 + tid];
    float v = fv + pe;
    float mean = blocksum256(v, red8) * (1.f / 256.f);
    __syncthreads();
    float dv = v - mean;
    float var = blocksum256(dv * dv, red8) * (1.f / 256.f);
    float xv = dv * rsqrtf(var + 1e-5f) * g[tid] + beta[tid];
    xout[(size_t)i * 256 + tid] = xv;
    __syncthreads();
    float m2 = blocksum256(xv, red8) * (1.f / 256.f);
    __syncthreads();
    float d2 = xv - m2;
    float v2 = blocksum256(d2 * d2, red8) * (1.f / 256.f);
    hbf[(size_t)i * 256 + tid] = __float2bfloat16(d2 * rsqrtf(v2 + 1e-5f) * n1g[tid] + n1b[tid]);
}

// ---------------- hierarchical bitonic sort (CHUNK=16384) ----------------
#define CHUNK 16384
__global__ void __launch_bounds__(1024) sort_local(float* __restrict__ key, int* __restrict__ idx, int Lc) {
    extern __shared__ char smraw[];
    float* sk = (float*)smraw;
    int*   si = (int*)(smraw + CHUNK * 4);
    size_t gbase = (size_t)blockIdx.x * CHUNK;
    int lbase = (int)(gbase % (size_t)Lc);
    for (int t = threadIdx.x; t < CHUNK; t += 1024) { sk[t] = key[gbase + t]; si[t] = idx[gbase + t]; }
    __syncthreads();
    for (int k = 2; k <= CHUNK; k <<= 1) {
        for (int j = k >> 1; j > 0; j >>= 1) {
            #pragma unroll
            for (int it = 0; it < CHUNK / 2048; it++) {
                int t = threadIdx.x + it * 1024;
                int i = 2 * t - (t & (j - 1));
                int p = i + j;
                bool up = (((lbase + i) & k) == 0);
                float a = sk[i], b = sk[p];
                int ia = si[i], ib = si[p];
                bool sw = up ? (a > b || (a == b && ia > ib)) : (a < b || (a == b && ia < ib));
                if (sw) { sk[i] = b; sk[p] = a; si[i] = ib; si[p] = ia; }
            }
            __syncthreads();
        }
    }
    for (int t = threadIdx.x; t < CHUNK; t += 1024) { key[gbase + t] = sk[t]; idx[gbase + t] = si[t]; }
}

__global__ void __launch_bounds__(1024) merge_local(float* __restrict__ key, int* __restrict__ idx, int k, int Lc) {
    extern __shared__ char smraw[];
    float* sk = (float*)smraw;
    int*   si = (int*)(smraw + CHUNK * 4);
    size_t gbase = (size_t)blockIdx.x * CHUNK;
    int lbase = (int)(gbase % (size_t)Lc);
    for (int t = threadIdx.x; t < CHUNK; t += 1024) { sk[t] = key[gbase + t]; si[t] = idx[gbase + t]; }
    __syncthreads();
    for (int j = CHUNK / 2; j > 0; j >>= 1) {
        #pragma unroll
        for (int it = 0; it < CHUNK / 2048; it++) {
            int t = threadIdx.x + it * 1024;
            int i = 2 * t - (t & (j - 1));
            int p = i + j;
            bool up = (((lbase + i) & k) == 0);
            float a = sk[i], b = sk[p];
            int ia = si[i], ib = si[p];
            bool sw = up ? (a > b || (a == b && ia > ib)) : (a < b || (a == b && ia < ib));
            if (sw) { sk[i] = b; sk[p] = a; si[i] = ib; si[p] = ia; }
        }
        __syncthreads();
    }
    for (int t = threadIdx.x; t < CHUNK; t += 1024) { key[gbase + t] = sk[t]; idx[gbase + t] = si[t]; }
}

__global__ void __launch_bounds__(256) sort_global(float* __restrict__ key, int* __restrict__ idx, int k, int j, int Lc) {
    int c = blockIdx.y;
    size_t base = (size_t)c * Lc;
    int t = blockIdx.x * 256 + threadIdx.x;
    int i = 2 * t - (t & (j - 1));
    int p = i + j;
    bool up = ((i & k) == 0);
    float a = key[base + i], b = key[base + p];
    int ia = idx[base + i], ib = idx[base + p];
    bool sw = up ? (a > b || (a == b && ia > ib)) : (a < b || (a == b && ia < ib));
    if (sw) {
        key[base + i] = b; key[base + p] = a;
        idx[base + i] = ib; idx[base + p] = ia;
    }
}

// ---------------- LN -> bf16 ----------------
__global__ void __launch_bounds__(256) ln_bf(const float* __restrict__ x, const float* __restrict__ g,
                                             const float* __restrict__ b, __nv_bfloat16* __restrict__ y) {
    int row = blockIdx.x, tid = threadIdx.x;
    __shared__ float red8[8];
    float v = x[(size_t)row * 256 + tid];
    float mean = blocksum256(v, red8) * (1.f / 256.f);
    __syncthreads();
    float dv = v - mean;
    float var = blocksum256(dv * dv, red8) * (1.f / 256.f);
    y[(size_t)row * 256 + tid] = __float2bfloat16(dv * rsqrtf(var + 1e-5f) * g[tid] + b[tid]);
}

// ---------------- tensor-core GEMM (3-stage cp.async pipeline) ----------------
// epi: 0 none, 1 relu, 2 gelu, 3 sigmoid, 4 +resid[ridx], 5 resid + gate*val,
//      6 +resid[m]; write bf16 scattered to Cout[ridx[m]]; atomic gt column sums
#define GBM 128
#define GBN 128
#define GKT 32
#define STG_BYTES 20480
#define NSTAGE 3

__global__ void __launch_bounds__(256) gemm_bf16(
    const __nv_bfloat16* __restrict__ A_, const __nv_bfloat16* __restrict__ Bt_,
    const float* __restrict__ bias_,
    const float* __restrict__ resid, const float* __restrict__ gate,
    void* __restrict__ Cout_,
    int M, int Ncols, int K, int cloudLen, int epi, int outBf16,
    const int* __restrict__ ridx, float* __restrict__ gtp, int gtLc,
    const __nv_bfloat16* A2, const __nv_bfloat16* Bt2, const float* bias2, void* Cout2)
{
    extern __shared__ char smraw[];
    const __nv_bfloat16* A = A_;
    const __nv_bfloat16* Bt = Bt_;
    const float* bias = bias_;
    void* Cout = Cout_;
    if (blockIdx.z == 1) { A = A2; Bt = Bt2; bias = bias2; Cout = Cout2; }
    const int tid = threadIdx.x;
    const int lane = tid & 31;
    const int warp = tid >> 5;
    const int wm = warp >> 1, wn = warp & 1;
    const int m0 = blockIdx.y * GBM, n0 = blockIdx.x * GBN;

    float acc[2][8][4];
    #pragma unroll
    for (int i = 0; i < 2; i++)
        #pragma unroll
        for (int j = 0; j < 8; j++)
            #pragma unroll
            for (int q = 0; q < 4; q++) acc[i][j][q] = 0.f;

    const int ldrow0 = tid >> 2, ldc0 = tid & 3;
    const int ldrow1 = (tid + 256) >> 2, ldc1 = tid & 3;
    const size_t arow0 = (size_t)(m0 + ldrow0) * K;
    const size_t arow1 = (size_t)(m0 + ldrow1) * K;

    auto issue = [&](int s, int kt) {
        char* sA = smraw + s * STG_BYTES;
        char* sB = sA + 10240;
        {
            const __nv_bfloat16* gA = A + arow0 + kt * GKT + ldc0 * 8;
            uint32_t d = smem_u32(sA + ldrow0 * 80 + ldc0 * 16);
            asm volatile("cp.async.cg.shared.global [%0], [%1], 16;\n" :: "r"(d), "l"(gA));
            const __nv_bfloat16* gB = Bt + (size_t)(n0 + ldrow0) * K + kt * GKT + ldc0 * 8;
            uint32_t d2 = smem_u32(sB + ldrow0 * 80 + ldc0 * 16);
            asm volatile("cp.async.cg.shared.global [%0], [%1], 16;\n" :: "r"(d2), "l"(gB));
        }
        {
            const __nv_bfloat16* gA = A + arow1 + kt * GKT + ldc1 * 8;
            uint32_t d = smem_u32(sA + ldrow1 * 80 + ldc1 * 16);
            asm volatile("cp.async.cg.shared.global [%0], [%1], 16;\n" :: "r"(d), "l"(gA));
            const __nv_bfloat16* gB = Bt + (size_t)(n0 + ldrow1) * K + kt * GKT + ldc1 * 8;
            uint32_t d2 = smem_u32(sB + ldrow1 * 80 + ldc1 * 16);
            asm volatile("cp.async.cg.shared.global [%0], [%1], 16;\n" :: "r"(d2), "l"(gB));
        }
        asm volatile("cp.async.commit_group;\n");
    };

    const int nk = K / GKT;  // >= 8 always
    issue(0, 0);
    issue(1, 1);
    for (int kt = 0; kt < nk; kt++) {
        int s = kt % NSTAGE;
        if (kt + 2 < nk) {
            issue((kt + 2) % NSTAGE, kt + 2);
            asm volatile("cp.async.wait_group 2;\n");
        } else if (kt + 1 < nk) {
            asm volatile("cp.async.wait_group 1;\n");
        } else {
            asm volatile("cp.async.wait_group 0;\n");
        }
        __syncthreads();

        char* sA = smraw + s * STG_BYTES;
        char* sB = sA + 10240;
        #pragma unroll
        for (int kk = 0; kk < 2; kk++) {
            uint32_t af[2][4];
            #pragma unroll
            for (int i = 0; i < 2; i++) {
                int r = wm * 32 + i * 16 + (lane & 15);
                int c = kk * 2 + (lane >> 4);
                uint32_t addr = smem_u32(sA + r * 80 + c * 16);
                asm volatile("ldmatrix.sync.aligned.m8n8.x4.shared.b16 {%0,%1,%2,%3}, [%4];"
                             : "=r"(af[i][0]), "=r"(af[i][1]), "=r"(af[i][2]), "=r"(af[i][3])
                             : "r"(addr));
            }
            uint32_t bf[8][2];
            #pragma unroll
            for (int jp = 0; jp < 4; jp++) {
                int r = wn * 64 + jp * 16 + (lane & 15);
                int c = kk * 2 + (lane >> 4);
                uint32_t addr = smem_u32(sB + r * 80 + c * 16);
                uint32_t r0, r1, r2, r3;
                asm volatile("ldmatrix.sync.aligned.m8n8.x4.shared.b16 {%0,%1,%2,%3}, [%4];"
                             : "=r"(r0), "=r"(r1), "=r"(r2), "=r"(r3) : "r"(addr));
                bf[2*jp][0] = r0; bf[2*jp+1][0] = r1;
                bf[2*jp][1] = r2; bf[2*jp+1][1] = r3;
            }
            #pragma unroll
            for (int i = 0; i < 2; i++)
                #pragma unroll
                for (int j = 0; j < 8; j++) {
                    asm volatile("mma.sync.aligned.m16n8k16.row.col.f32.bf16.bf16.f32 "
                                 "{%0,%1,%2,%3}, {%4,%5,%6,%7}, {%8,%9}, {%0,%1,%2,%3};"
                                 : "+f"(acc[i][j][0]), "+f"(acc[i][j][1]),
                                   "+f"(acc[i][j][2]), "+f"(acc[i][j][3])
                                 : "r"(af[i][0]), "r"(af[i][1]), "r"(af[i][2]), "r"(af[i][3]),
                                   "r"(bf[j][0]), "r"(bf[j][1]));
                }
        }
        __syncthreads();
    }

    const int rbase = m0 + wm * 32 + (lane >> 2);
    const int cbase = n0 + wn * 64 + 2 * (lane & 3);
    float gta[8][2];
    #pragma unroll
    for (int j = 0; j < 8; j++) { gta[j][0] = 0.f; gta[j][1] = 0.f; }

    #pragma unroll
    for (int i = 0; i < 2; i++) {
        #pragma unroll
        for (int half = 0; half < 2; half++) {
            int m = rbase + i * 16 + half * 8;
            const float* bp = (cloudLen > 0) ? (bias + (size_t)(m / cloudLen) * Ncols) : bias;
            #pragma unroll
            for (int j = 0; j < 8; j++) {
                int n = cbase + j * 8;
                float v0 = acc[i][j][half * 2 + 0] + bp[n];
                float v1 = acc[i][j][half * 2 + 1] + bp[n + 1];
                size_t o = (size_t)m * Ncols + n;
                bool stored = false;
                switch (epi) {
                    case 1: v0 = fmaxf(v0, 0.f); v1 = fmaxf(v1, 0.f); break;
                    case 2:
                        v0 = 0.5f * v0 * (1.f + erff(v0 * 0.70710678118f));
                        v1 = 0.5f * v1 * (1.f + erff(v1 * 0.70710678118f));
                        break;
                    case 3:
                        v0 = frcp_fast(1.f + fexpf_fast(-v0));
                        v1 = frcp_fast(1.f + fexpf_fast(-v1));
                        break;
                    case 4: {
                        size_t ro = (size_t)(ridx ? ridx[m] : m) * Ncols + n;
                        float2 r = *(const float2*)(resid + ro);
                        v0 += r.x; v1 += r.y;
                    } break;
                    case 5: {
                        float2 r = *(const float2*)(resid + o);
                        float2 gg = *(const float2*)(gate + o);
                        v0 = r.x + gg.x * v0; v1 = r.y + gg.y * v1;
                    } break;
                    case 6: {
                        float2 r = *(const float2*)(resid + o);
                        v0 += r.x; v1 += r.y;
                        gta[j][0] += v0; gta[j][1] += v1;
                        size_t od = (size_t)ridx[m] * Ncols + n;
                        __nv_bfloat162 h;
                        h.x = __float2bfloat16(v0); h.y = __float2bfloat16(v1);
                        *(__nv_bfloat162*)((__nv_bfloat16*)Cout + od) = h;
                        stored = true;
                    } break;
                    default: break;
                }
                if (!stored) {
                    if (outBf16) {
                        __nv_bfloat162 h;
                        h.x = __float2bfloat16(v0); h.y = __float2bfloat16(v1);
                        *(__nv_bfloat162*)((__nv_bfloat16*)Cout + o) = h;
                    } else {
                        *(float2*)((float*)Cout + o) = make_float2(v0, v1);
                    }
                }
            }
        }
    }
    if (epi == 6) {
        int c = m0 / gtLc;
        #pragma unroll
        for (int j = 0; j < 8; j++) {
            float s0 = gta[j][0], s1 = gta[j][1];
            #pragma unroll
            for (int off = 4; off <= 16; off <<= 1) {
                s0 += __shfl_xor_sync(0xffffffffu, s0, off);
                s1 += __shfl_xor_sync(0xffffffffu, s1, off);
            }
            if ((lane >> 2) == 0) {
                int n = cbase + j * 8;
                atomicAdd(gtp + c * 256 + n, s0);
                atomicAdd(gtp + c * 256 + n + 1, s1);
            }
        }
    }
}

// ---------------- flash attention (gathers rows via sidx) ----------------
#define FA_SMEM (20480 * 2 + 32 * 528)
__global__ void __launch_bounds__(256) fattn(const __nv_bfloat16* __restrict__ qkv,
                                             const int* __restrict__ sidx,
                                             __nv_bfloat16* __restrict__ o) {
    extern __shared__ char sm[];
    char* sq = sm;
    char* sk = sm + 20480;
    char* svt = sm + 40960;
    const int p = blockIdx.x, h = blockIdx.y;
    const int tid = threadIdx.x;
    const int lane = tid & 31;
    const int w = tid >> 5;
    const size_t base = (size_t)p * 256;
    const float SC = 0.17677669529663687f * 1.4426950408889634f;

    {
        const size_t src = (size_t)sidx[base + tid] * 768;
        const uint4* qr = (const uint4*)(qkv + src + h * 32);
        const uint4* kr = (const uint4*)(qkv + src + 256 + h * 32);
        const uint4* vr = (const uint4*)(qkv + src + 512 + h * 32);
        uint4* dq = (uint4*)(sq + tid * 80);
        uint4* dk = (uint4*)(sk + tid * 80);
        uint4 v0 = vr[0], v1 = vr[1], v2 = vr[2], v3 = vr[3];
        dq[0] = qr[0]; dq[1] = qr[1]; dq[2] = qr[2]; dq[3] = qr[3];
        dk[0] = kr[0]; dk[1] = kr[1]; dk[2] = kr[2]; dk[3] = kr[3];
        uint32_t vu[8] = {v0.x, v0.y, v0.z, v0.w, v1.x, v1.y, v1.z, v1.w};
        uint32_t vu2[8] = {v2.x, v2.y, v2.z, v2.w, v3.x, v3.y, v3.z, v3.w};
        #pragma unroll
        for (int e = 0; e < 8; e++) {
            ((__nv_bfloat16*)(svt + (2 * e + 0) * 528))[tid] = ((__nv_bfloat162*)&vu[e])->x;
            ((__nv_bfloat16*)(svt + (2 * e + 1) * 528))[tid] = ((__nv_bfloat162*)&vu[e])->y;
        }
        #pragma unroll
        for (int e = 0; e < 8; e++) {
            ((__nv_bfloat16*)(svt + (16 + 2 * e + 0) * 528))[tid] = ((__nv_bfloat162*)&vu2[e])->x;
            ((__nv_bfloat16*)(svt + (16 + 2 * e + 1) * 528))[tid] = ((__nv_bfloat162*)&vu2[e])->y;
        }
    }
    __syncthreads();

    const int m0w = w * 32;
    uint32_t qa[2][2][4];
    #pragma unroll
    for (int i = 0; i < 2; i++)
        #pragma unroll
        for (int kk = 0; kk < 2; kk++) {
            int r = m0w + i * 16 + (lane & 15);
            uint32_t addr = smem_u32(sq + r * 80 + kk * 32 + (lane >> 4) * 16);
            asm volatile("ldmatrix.sync.aligned.m8n8.x4.shared.b16 {%0,%1,%2,%3}, [%4];"
                         : "=r"(qa[i][kk][0]), "=r"(qa[i][kk][1]),
                           "=r"(qa[i][kk][2]), "=r"(qa[i][kk][3])
                         : "r"(addr));
        }

    float oacc[2][4][4];
    #pragma unroll
    for (int i = 0; i < 2; i++)
        #pragma unroll
        for (int d = 0; d < 4; d++)
            #pragma unroll
            for (int q = 0; q < 4; q++) oacc[i][d][q] = 0.f;
    float mrow[2][2] = {{-1e30f, -1e30f}, {-1e30f, -1e30f}};
    float lrow[2][2] = {{0.f, 0.f}, {0.f, 0.f}};

    for (int jc = 0; jc < 8; jc++) {
        uint32_t kb[2][4][2];
        #pragma unroll
        for (int jp = 0; jp < 2; jp++)
            #pragma unroll
            for (int kk = 0; kk < 2; kk++) {
                int r = jc * 32 + jp * 16 + (lane & 15);
                uint32_t addr = smem_u32(sk + r * 80 + kk * 32 + (lane >> 4) * 16);
                uint32_t r0, r1, r2, r3;
                asm volatile("ldmatrix.sync.aligned.m8n8.x4.shared.b16 {%0,%1,%2,%3}, [%4];"
                             : "=r"(r0), "=r"(r1), "=r"(r2), "=r"(r3) : "r"(addr));
                kb[kk][2*jp][0] = r0;   kb[kk][2*jp][1] = r2;
                kb[kk][2*jp+1][0] = r1; kb[kk][2*jp+1][1] = r3;
            }

        float sacc[2][4][4];
        #pragma unroll
        for (int i = 0; i < 2; i++)
            #pragma unroll
            for (int nt = 0; nt < 4; nt++)
                #pragma unroll
                for (int q = 0; q < 4; q++) sacc[i][nt][q] = 0.f;
        #pragma unroll
        for (int kk = 0; kk < 2; kk++)
            #pragma unroll
            for (int i = 0; i < 2; i++)
                #pragma unroll
                for (int nt = 0; nt < 4; nt++) {
                    asm volatile("mma.sync.aligned.m16n8k16.row.col.f32.bf16.bf16.f32 "
                                 "{%0,%1,%2,%3}, {%4,%5,%6,%7}, {%8,%9}, {%0,%1,%2,%3};"
                                 : "+f"(sacc[i][nt][0]), "+f"(sacc[i][nt][1]),
                                   "+f"(sacc[i][nt][2]), "+f"(sacc[i][nt][3])
                                 : "r"(qa[i][kk][0]), "r"(qa[i][kk][1]),
                                   "r"(qa[i][kk][2]), "r"(qa[i][kk][3]),
                                   "r"(kb[kk][nt][0]), "r"(kb[kk][nt][1]));
                }

        #pragma unroll
        for (int i = 0; i < 2; i++)
            #pragma unroll
            for (int nt = 0; nt < 4; nt++)
                #pragma unroll
                for (int q = 0; q < 4; q++) sacc[i][nt][q] *= SC;

        #pragma unroll
        for (int i = 0; i < 2; i++) {
            #pragma unroll
            for (int half = 0; half < 2; half++) {
                float mx = -1e30f;
                #pragma unroll
                for (int nt = 0; nt < 4; nt++) {
                    mx = fmaxf(mx, sacc[i][nt][half*2+0]);
                    mx = fmaxf(mx, sacc[i][nt][half*2+1]);
                }
                mx = fmaxf(mx, __shfl_xor_sync(0xffffffffu, mx, 1));
                mx = fmaxf(mx, __shfl_xor_sync(0xffffffffu, mx, 2));
                float newm = fmaxf(mrow[i][half], mx);
                float alpha = fexp2_fast(mrow[i][half] - newm);
                mrow[i][half] = newm;
                float rs = 0.f;
                #pragma unroll
                for (int nt = 0; nt < 4; nt++) {
                    float p0 = fexp2_fast(sacc[i][nt][half*2+0] - newm);
                    float p1 = fexp2_fast(sacc[i][nt][half*2+1] - newm);
                    sacc[i][nt][half*2+0] = p0;
                    sacc[i][nt][half*2+1] = p1;
                    rs += p0 + p1;
                }
                rs += __shfl_xor_sync(0xffffffffu, rs, 1);
                rs += __shfl_xor_sync(0xffffffffu, rs, 2);
                lrow[i][half] = lrow[i][half] * alpha + rs;
                #pragma unroll
                for (int dt = 0; dt < 4; dt++) {
                    oacc[i][dt][half*2+0] *= alpha;
                    oacc[i][dt][half*2+1] *= alpha;
                }
            }
        }

        uint32_t pa[2][2][4];
        #pragma unroll
        for (int i = 0; i < 2; i++)
            #pragma unroll
            for (int kk = 0; kk < 2; kk++) {
                int ntl = kk * 2, nth = kk * 2 + 1;
                __nv_bfloat162 b0 = __float22bfloat162_rn(make_float2(sacc[i][ntl][0], sacc[i][ntl][1]));
                __nv_bfloat162 b1 = __float22bfloat162_rn(make_float2(sacc[i][ntl][2], sacc[i][ntl][3]));
                __nv_bfloat162 b2 = __float22bfloat162_rn(make_float2(sacc[i][nth][0], sacc[i][nth][1]));
                __nv_bfloat162 b3 = __float22bfloat162_rn(make_float2(sacc[i][nth][2], sacc[i][nth][3]));
                pa[i][kk][0] = *(uint32_t*)&b0;
                pa[i][kk][1] = *(uint32_t*)&b1;
                pa[i][kk][2] = *(uint32_t*)&b2;
                pa[i][kk][3] = *(uint32_t*)&b3;
            }

        uint32_t vb[2][4][2];
        #pragma unroll
        for (int jp = 0; jp < 2; jp++)
            #pragma unroll
            for (int kk = 0; kk < 2; kk++) {
                int r = jp * 16 + (lane & 15);
                uint32_t addr = smem_u32(svt + r * 528 + jc * 64 + kk * 32 + (lane >> 4) * 16);
                uint32_t r0, r1, r2, r3;
                asm volatile("ldmatrix.sync.aligned.m8n8.x4.shared.b16 {%0,%1,%2,%3}, [%4];"
                             : "=r"(r0), "=r"(r1), "=r"(r2), "=r"(r3) : "r"(addr));
                vb[kk][2*jp][0] = r0;   vb[kk][2*jp][1] = r2;
                vb[kk][2*jp+1][0] = r1; vb[kk][2*jp+1][1] = r3;
            }

        #pragma unroll
        for (int kk = 0; kk < 2; kk++)
            #pragma unroll
            for (int i = 0; i < 2; i++)
                #pragma unroll
                for (int dt = 0; dt < 4; dt++) {
                    asm volatile("mma.sync.aligned.m16n8k16.row.col.f32.bf16.bf16.f32 "
                                 "{%0,%1,%2,%3}, {%4,%5,%6,%7}, {%8,%9}, {%0,%1,%2,%3};"
                                 : "+f"(oacc[i][dt][0]), "+f"(oacc[i][dt][1]),
                                   "+f"(oacc[i][dt][2]), "+f"(oacc[i][dt][3])
                                 : "r"(pa[i][kk][0]), "r"(pa[i][kk][1]),
                                   "r"(pa[i][kk][2]), "r"(pa[i][kk][3]),
                                   "r"(vb[kk][dt][0]), "r"(vb[kk][dt][1]));
                }
    }

    #pragma unroll
    for (int i = 0; i < 2; i++)
        #pragma unroll
        for (int half = 0; half < 2; half++) {
            float inv = 1.f / lrow[i][half];
            int row = m0w + i * 16 + half * 8 + (lane >> 2);
            #pragma unroll
            for (int dt = 0; dt < 4; dt++) {
                int col = h * 32 + dt * 8 + 2 * (lane & 3);
                __nv_bfloat162 hv;
                hv.x = __float2bfloat16(oacc[i][dt][half*2+0] * inv);
                hv.y = __float2bfloat16(oacc[i][dt][half*2+1] * inv);
                *(__nv_bfloat162*)(o + (base + row) * 256 + col) = hv;
            }
        }
}

// ---------------- fold gt into per-cloud biases ----------------
__global__ void cloudbias_kernel(const float* __restrict__ gtsum,
                                 const float* __restrict__ gg_w1, const float* __restrict__ gg_b1,
                                 const float* __restrict__ f_w1, const float* __restrict__ f_b1,
                                 float* __restrict__ ggb, float* __restrict__ fb, int Lc) {
    int c = blockIdx.x, j = threadIdx.x;
    float s1 = gg_b1[j], s2 = f_b1[j];
    float invL = 1.f / (float)Lc;
    for (int h = 0; h < 256; h++) {
        float gv = gtsum[c * 256 + h] * invL;
        s1 += gv * gg_w1[(size_t)(256 + h) * 256 + j];
        s2 += gv * f_w1[(size_t)(256 + h) * 256 + j];
    }
    ggb[c * 256 + j] = s1;
    fb[c * 256 + j] = s2;
}

// ---------------- launch ----------------
extern "C" void kernel_launch(void* const* d_in, const int* in_sizes, int n_in,
                              void* d_out, int out_size) {
    const float* feats = (const float*)d_in[0];
    const float* coord = (const float*)d_in[1];
    const float* pe_w1 = (const float*)d_in[3];
    const float* pe_b1 = (const float*)d_in[4];
    const float* pe_w2 = (const float*)d_in[5];
    const float* pe_b2 = (const float*)d_in[6];
    const float* pre_g = (const float*)d_in[7];
    const float* pre_b = (const float*)d_in[8];
    const float* n1_g  = (const float*)d_in[9];
    const float* n1_b  = (const float*)d_in[10];
    const float* wqkv  = (const float*)d_in[11];
    const float* bqkv  = (const float*)d_in[12];
    const float* wo    = (const float*)d_in[13];
    const float* bo    = (const float*)d_in[14];
    const float* n2_g  = (const float*)d_in[15];
    const float* n2_b  = (const float*)d_in[16];
    const float* m_w1  = (const float*)d_in[17];
    const float* m_b1  = (const float*)d_in[18];
    const float* m_w2  = (const float*)d_in[19];
    const float* m_b2  = (const float*)d_in[20];
    const float* gg_w1 = (const float*)d_in[21];
    const float* gg_b1 = (const float*)d_in[22];
    const float* gg_w2 = (const float*)d_in[23];
    const float* gg_b2 = (const float*)d_in[24];
    const float* f_w1  = (const float*)d_in[25];
    const float* f_b1  = (const float*)d_in[26];
    const float* f_w2  = (const float*)d_in[27];
    const float* f_b2  = (const float*)d_in[28];
    float* out = (float*)d_out;

    int N = in_sizes[0] / 256;
    int B = in_sizes[2];
    int Lc = N / B;
    int patches = N / 256;

    float *p_x, *p_xs, *p_key, *p_gt, *p_ggb, *p_fb, *p_stats;
    __nv_bfloat16 *p_ba, *p_bb, *p_fe, *p_wt;
    int* p_idx;
    cudaGetSymbolAddress((void**)&p_x, g_x);
    cudaGetSymbolAddress((void**)&p_xs, g_xs);
    cudaGetSymbolAddress((void**)&p_ba, g_ba);
    cudaGetSymbolAddress((void**)&p_bb, g_bb);
    cudaGetSymbolAddress((void**)&p_fe, g_fe);
    cudaGetSymbolAddress((void**)&p_wt, g_wt);
    cudaGetSymbolAddress((void**)&p_key, g_key);
    cudaGetSymbolAddress((void**)&p_idx, g_idx);
    cudaGetSymbolAddress((void**)&p_gt, g_gt);
    cudaGetSymbolAddress((void**)&p_ggb, g_ggb);
    cudaGetSymbolAddress((void**)&p_fb, g_fb);
    cudaGetSymbolAddress((void**)&p_stats, g_stats);

    __nv_bfloat16* wqkv_t = p_wt + 0;
    __nv_bfloat16* wo_t   = p_wt + 196608;
    __nv_bfloat16* mw1_t  = p_wt + 262144;
    __nv_bfloat16* mw2_t  = p_wt + 393216;
    __nv_bfloat16* ggw1_t = p_wt + 524288;
    __nv_bfloat16* ggw2_t = p_wt + 589824;
    __nv_bfloat16* fw1_t  = p_wt + 655360;
    __nv_bfloat16* fw2_t  = p_wt + 720896;
    __nv_bfloat16* bb_lo = p_bb;
    __nv_bfloat16* bb_hi = p_bb + (size_t)N * 256;

    cudaFuncSetAttribute(fattn, cudaFuncAttributeMaxDynamicSharedMemorySize, FA_SMEM);
    cudaFuncSetAttribute(sort_local, cudaFuncAttributeMaxDynamicSharedMemorySize, CHUNK * 8);
    cudaFuncSetAttribute(merge_local, cudaFuncAttributeMaxDynamicSharedMemorySize, CHUNK * 8);
    cudaFuncSetAttribute(gemm_bf16, cudaFuncAttributeMaxDynamicSharedMemorySize, NSTAGE * STG_BYTES);

    PrepArgs pa;
    pa.coord = coord; pa.stats = p_stats; pa.Lc = Lc; pa.B = B;
    const float* ws[8] = {wqkv, wo, m_w1, m_w2, gg_w1, gg_w2, f_w1, f_w2};
    __nv_bfloat16* wd[8] = {wqkv_t, wo_t, mw1_t, mw2_t, ggw1_t, ggw2_t, fw1_t, fw2_t};
    int wK[8] = {256, 256, 256, 512, 256, 256, 256, 256};
    int wN[8] = {768, 256, 512, 256, 256, 256, 256, 256};
    int tiles = 0;
    for (int i = 0; i < 8; i++) {
        pa.wsrc[i] = ws[i]; pa.wdst[i] = wd[i];
        pa.wK[i] = wK[i]; pa.wN[i] = wN[i];
        pa.wt0[i] = tiles;
        tiles += (wK[i] / 32) * (wN[i] / 32);
    }
    pa.totalWTiles = tiles;
    pa.gt = p_gt;

    // 1: prep
    prep_kernel<<<B + tiles + 1, 1024>>>(pa);
    // 2: PE + pre-LN + LN1 + key (all original order)
    pe_ln_key_kernel<<<N, 256>>>(feats, coord, pe_w1, pe_b1, pe_w2, pe_b2,
                                 pre_g, pre_b, n1_g, n1_b, p_stats,
                                 p_x, p_bb, p_fe, p_key, p_idx, Lc);
    // 3: local sort
    sort_local<<<N / CHUNK, 1024, CHUNK * 8>>>(p_key, p_idx, Lc);
    // 4: qkv GEMM on UNPERMUTED LN1 out -> ba (original order)  [profiled launch]
    gemm_bf16<<<dim3(768/GBN, N/GBM), 256, NSTAGE*STG_BYTES>>>(
        p_bb, wqkv_t, bqkv, nullptr, nullptr, p_ba, N, 768, 256, 0, 0, 1,
        nullptr, nullptr, 0, nullptr, nullptr, nullptr, nullptr);
    // 5-6: finish the sort
    for (int k = CHUNK * 2; k <= Lc; k <<= 1) {
        for (int j = k >> 1; j >= CHUNK; j >>= 1)
            sort_global<<<dim3(Lc / 512, B), 256>>>(p_key, p_idx, k, j, Lc);
        merge_local<<<N / CHUNK, 1024, CHUNK * 8>>>(p_key, p_idx, k, Lc);
    }
    // 7: flash attention, gathering rows via idx -> bb (serialized order)
    fattn<<<dim3(patches, 8), 256, FA_SMEM>>>(p_ba, p_idx, p_bb);
    // 8: wo GEMM + gathered residual -> xs fp32 (serialized)
    gemm_bf16<<<dim3(256/GBN, N/GBM), 256, NSTAGE*STG_BYTES>>>(
        p_bb, wo_t, bo, p_x, nullptr, p_xs, N, 256, 256, 0, 4, 0,
        p_idx, nullptr, 0, nullptr, nullptr, nullptr, nullptr);
    // 9: LN2 -> ba bf16
    ln_bf<<<N, 256>>>(p_xs, n2_g, n2_b, p_ba);
    // 10: MLP1 + gelu -> bb (N x 512)
    gemm_bf16<<<dim3(512/GBN, N/GBM), 256, NSTAGE*STG_BYTES>>>(
        p_ba, mw1_t, m_b1, nullptr, nullptr, p_bb, N, 512, 256, 0, 2, 1,
        nullptr, nullptr, 0, nullptr, nullptr, nullptr, nullptr);
    // 11: MLP2 + resid; scatter xo bf16 into ba (original order); gt atomics
    gemm_bf16<<<dim3(256/GBN, N/GBM), 256, NSTAGE*STG_BYTES>>>(
        p_bb, mw2_t, m_b2, p_xs, nullptr, p_ba, N, 256, 512, 0, 6, 1,
        p_idx, p_gt, Lc, nullptr, nullptr, nullptr, nullptr);
    // 12: per-cloud biases
    cloudbias_kernel<<<B, 256>>>(p_gt, gg_w1, gg_b1, f_w1, f_b1, p_ggb, p_fb, Lc);
    // 13: batched hidden GEMMs (z=0 gate-hidden, z=1 fuse-hidden)
    gemm_bf16<<<dim3(256/GBN, N/GBM, 2), 256, NSTAGE*STG_BYTES>>>(
        p_fe, ggw1_t, p_ggb, nullptr, nullptr, bb_lo, N, 256, 256, Lc, 1, 1,
        nullptr, nullptr, 0, p_ba, fw1_t, p_fb, bb_hi);
    // 14: gate = sigmoid -> p_x fp32
    gemm_bf16<<<dim3(256/GBN, N/GBM), 256, NSTAGE*STG_BYTES>>>(
        bb_lo, ggw2_t, gg_b2, nullptr, nullptr, p_x, N, 256, 256, 0, 3, 0,
        nullptr, nullptr, 0, nullptr, nullptr, nullptr, nullptr);
    // 15: out = feats + gate * (fuse-hidden @ f_w2 + f_b2)
    gemm_bf16<<<dim3(256/GBN, N/GBM), 256, NSTAGE*STG_BYTES>>>(
        bb_hi, fw2_t, f_b2, feats, p_x, out, N, 256, 256, 0, 5, 0,
        nullptr, nullptr, 0, nullptr, nullptr, nullptr, nullptr);
}

// round 7
// speedup vs baseline: 3.9202x; 1.0445x over previous
#include <cuda_runtime.h>
#include <cuda_bf16.h>
#include <math.h>
#include <stdint.h>

// ---------------- static scratch ----------------
#define MAXN 131072
#define DD 256
__device__ float g_x  [(size_t)MAXN * DD];
__device__ float g_xs [(size_t)MAXN * DD];
__device__ __nv_bfloat16 g_ba[(size_t)MAXN * 768];
__device__ __nv_bfloat16 g_bb[(size_t)MAXN * 512];
__device__ __nv_bfloat16 g_fe[(size_t)MAXN * 256];
__device__ __nv_bfloat16 g_wt[786432];
__device__ float g_key[MAXN];
__device__ int   g_idx[MAXN];
__device__ float g_gt [8 * DD];
__device__ float g_ggb[8 * DD];
__device__ float g_fb [8 * DD];
__device__ float g_stats[8 * 12];

// ---------------- fast math ----------------
__device__ __forceinline__ float fexp2_fast(float z) {
    z = fmaxf(z, -80.f);
    float n = rintf(z);
    float f = z - n;
    float p = 0.009618129f;
    p = p * f + 0.055504109f;
    p = p * f + 0.240226507f;
    p = p * f + 0.693147181f;
    p = p * f + 1.0f;
    return p * __int_as_float(((int)n + 127) << 23);
}
__device__ __forceinline__ float fexpf_fast(float x) {
    return fexp2_fast(x * 1.4426950408889634f);
}
__device__ __forceinline__ float frcp_fast(float d) {
    float y = __int_as_float(0x7ef311c3 - __float_as_int(d));
    y = y * (2.f - d * y);
    y = y * (2.f - d * y);
    y = y * (2.f - d * y);
    return y;
}
__device__ __forceinline__ uint32_t smem_u32(const void* p) {
    return (uint32_t)__cvta_generic_to_shared(p);
}
__device__ __forceinline__ float blocksum256(float v, float* red8) {
    #pragma unroll
    for (int off = 16; off; off >>= 1) v += __shfl_xor_sync(0xffffffffu, v, off);
    if ((threadIdx.x & 31) == 0) red8[threadIdx.x >> 5] = v;
    __syncthreads();
    float s = 0.f;
    #pragma unroll
    for (int i = 0; i < 8; i++) s += red8[i];
    return s;
}

// ---------------- prep ----------------
struct PrepArgs {
    const float* coord; float* stats; int Lc; int B;
    const float* wsrc[8]; __nv_bfloat16* wdst[8];
    int wK[8], wN[8], wt0[8];
    int totalWTiles;
    float* gt;
};
__global__ void __launch_bounds__(1024) prep_kernel(PrepArgs a) {
    __shared__ float red[1024];
    __shared__ float tt[32][33];
    int b = blockIdx.x, tid = threadIdx.x;
    if (b < a.B) {
        int c = b, Lc = a.Lc;
        float sum[3] = {0,0,0}, mn[3] = {1e30f,1e30f,1e30f}, mx[3] = {-1e30f,-1e30f,-1e30f};
        for (int i = tid; i < Lc; i += 1024) {
            const float* cp = a.coord + (size_t)(c * Lc + i) * 3;
            #pragma unroll
            for (int d = 0; d < 3; d++) {
                float v = cp[d];
                sum[d] += v; mn[d] = fminf(mn[d], v); mx[d] = fmaxf(mx[d], v);
            }
        }
        for (int d = 0; d < 3; d++) {
            red[tid] = sum[d]; __syncthreads();
            for (int s = 512; s > 0; s >>= 1) { if (tid < s) red[tid] += red[tid + s]; __syncthreads(); }
            float tot = red[0]; __syncthreads();
            red[tid] = mn[d]; __syncthreads();
            for (int s = 512; s > 0; s >>= 1) { if (tid < s) red[tid] = fminf(red[tid], red[tid + s]); __syncthreads(); }
            float tmn = red[0]; __syncthreads();
            red[tid] = mx[d]; __syncthreads();
            for (int s = 512; s > 0; s >>= 1) { if (tid < s) red[tid] = fmaxf(red[tid], red[tid + s]); __syncthreads(); }
            float tmx = red[0]; __syncthreads();
            if (tid == 0) {
                float mean = tot / (float)Lc;
                a.stats[c*12 + d]     = mean;
                a.stats[c*12 + 3 + d] = fmaxf(fmaxf(tmx - mean, mean - tmn), 1e-6f);
                a.stats[c*12 + 6 + d] = tmn;
                a.stats[c*12 + 9 + d] = 1.f / fmaxf(tmx - tmn, 1e-6f);
            }
            __syncthreads();
        }
    } else if (b < a.B + a.totalWTiles) {
        int t = b - a.B;
        int w = 0;
        #pragma unroll
        for (int q = 1; q < 8; q++) if (t >= a.wt0[q]) w = q;
        int lt = t - a.wt0[w];
        int tilesX = a.wN[w] >> 5;
        int bx = (lt % tilesX) << 5, by = (lt / tilesX) << 5;
        const float* src = a.wsrc[w];
        __nv_bfloat16* dst = a.wdst[w];
        int K = a.wK[w], Ncols = a.wN[w];
        int tx = tid & 31, ty = tid >> 5;
        tt[ty][tx] = src[(size_t)(by + ty) * Ncols + bx + tx];
        __syncthreads();
        dst[(size_t)(bx + ty) * K + by + tx] = __float2bfloat16(tt[tx][ty]);
    } else {
        a.gt[tid] = 0.f;
        a.gt[tid + 1024] = 0.f;
    }
}

// ---------------- PE + pre-LN + LN1 + key + feats->bf16 ----------------
__global__ void __launch_bounds__(256) pe_ln_key_kernel(
    const float* __restrict__ feats, const float* __restrict__ coord,
    const float* __restrict__ w1, const float* __restrict__ b1,
    const float* __restrict__ w2, const float* __restrict__ b2,
    const float* __restrict__ g, const float* __restrict__ beta,
    const float* __restrict__ n1g, const float* __restrict__ n1b,
    const float* __restrict__ stats,
    float* __restrict__ xout, __nv_bfloat16* __restrict__ hbf,
    __nv_bfloat16* __restrict__ febf,
    float* __restrict__ key, int* __restrict__ idx, int Lc)
{
    int i = blockIdx.x, tid = threadIdx.x;
    int c = i / Lc;
    __shared__ float hid[64];
    __shared__ float red8[8];
    const float* st = stats + c * 12;
    float c0 = coord[(size_t)i*3+0], c1 = coord[(size_t)i*3+1], c2 = coord[(size_t)i*3+2];
    if (tid < 64) {
        float n0 = (c0 - st[0]) / st[3];
        float n1 = (c1 - st[1]) / st[4];
        float n2 = (c2 - st[2]) / st[5];
        float hv = b1[tid] + n0 * w1[tid] + n1 * w1[64 + tid] + n2 * w1[128 + tid];
        hid[tid] = fmaxf(hv, 0.f);
    }
    if (tid == 0) {
        float k0 = (c0 - st[6]) * st[9];
        float k1 = (c1 - st[7]) * st[10];
        float k2 = (c2 - st[8]) * st[11];
        key[i] = k0 + 2.17f * k1 + 3.31f * k2;
        idx[i] = i;
    }
    __syncthreads();
    float fv = feats[(size_t)i * 256 + tid];
    febf[(size_t)i * 256 + tid] = __float2bfloat16(fv);
    float pe = b2[tid];
    #pragma unroll 8
    for (int h = 0; h < 64; h++) pe += hid[h] * w2[h * 256 + tid];
    float v = fv + pe;
    float mean = blocksum256(v, red8) * (1.f / 256.f);
    __syncthreads();
    float dv = v - mean;
    float var = blocksum256(dv * dv, red8) * (1.f / 256.f);
    float xv = dv * rsqrtf(var + 1e-5f) * g[tid] + beta[tid];
    xout[(size_t)i * 256 + tid] = xv;
    __syncthreads();
    float m2 = blocksum256(xv, red8) * (1.f / 256.f);
    __syncthreads();
    float d2 = xv - m2;
    float v2 = blocksum256(d2 * d2, red8) * (1.f / 256.f);
    hbf[(size_t)i * 256 + tid] = __float2bfloat16(d2 * rsqrtf(v2 + 1e-5f) * n1g[tid] + n1b[tid]);
}

// ---------------- hierarchical bitonic sort (CHUNK=16384) ----------------
#define CHUNK 16384
__global__ void __launch_bounds__(1024) sort_local(float* __restrict__ key, int* __restrict__ idx, int Lc) {
    extern __shared__ char smraw[];
    float* sk = (float*)smraw;
    int*   si = (int*)(smraw + CHUNK * 4);
    size_t gbase = (size_t)blockIdx.x * CHUNK;
    int lbase = (int)(gbase % (size_t)Lc);
    for (int t = threadIdx.x; t < CHUNK; t += 1024) { sk[t] = key[gbase + t]; si[t] = idx[gbase + t]; }
    __syncthreads();
    for (int k = 2; k <= CHUNK; k <<= 1) {
        for (int j = k >> 1; j > 0; j >>= 1) {
            #pragma unroll
            for (int it = 0; it < CHUNK / 2048; it++) {
                int t = threadIdx.x + it * 1024;
                int i = 2 * t - (t & (j - 1));
                int p = i + j;
                bool up = (((lbase + i) & k) == 0);
                float a = sk[i], b = sk[p];
                int ia = si[i], ib = si[p];
                bool sw = up ? (a > b || (a == b && ia > ib)) : (a < b || (a == b && ia < ib));
                if (sw) { sk[i] = b; sk[p] = a; si[i] = ib; si[p] = ia; }
            }
            __syncthreads();
        }
    }
    for (int t = threadIdx.x; t < CHUNK; t += 1024) { key[gbase + t] = sk[t]; idx[gbase + t] = si[t]; }
}

__global__ void __launch_bounds__(1024) merge_local(float* __restrict__ key, int* __restrict__ idx, int k, int Lc) {
    extern __shared__ char smraw[];
    float* sk = (float*)smraw;
    int*   si = (int*)(smraw + CHUNK * 4);
    size_t gbase = (size_t)blockIdx.x * CHUNK;
    int lbase = (int)(gbase % (size_t)Lc);
    for (int t = threadIdx.x; t < CHUNK; t += 1024) { sk[t] = key[gbase + t]; si[t] = idx[gbase + t]; }
    __syncthreads();
    for (int j = CHUNK / 2; j > 0; j >>= 1) {
        #pragma unroll
        for (int it = 0; it < CHUNK / 2048; it++) {
            int t = threadIdx.x + it * 1024;
            int i = 2 * t - (t & (j - 1));
            int p = i + j;
            bool up = (((lbase + i) & k) == 0);
            float a = sk[i], b = sk[p];
            int ia = si[i], ib = si[p];
            bool sw = up ? (a > b || (a == b && ia > ib)) : (a < b || (a == b && ia < ib));
            if (sw) { sk[i] = b; sk[p] = a; si[i] = ib; si[p] = ia; }
        }
        __syncthreads();
    }
    for (int t = threadIdx.x; t < CHUNK; t += 1024) { key[gbase + t] = sk[t]; idx[gbase + t] = si[t]; }
}

__global__ void __launch_bounds__(256) sort_global(float* __restrict__ key, int* __restrict__ idx, int k, int j, int Lc) {
    int c = blockIdx.y;
    size_t base = (size_t)c * Lc;
    int t = blockIdx.x * 256 + threadIdx.x;
    int i = 2 * t - (t & (j - 1));
    int p = i + j;
    bool up = ((i & k) == 0);
    float a = key[base + i], b = key[base + p];
    int ia = idx[base + i], ib = idx[base + p];
    bool sw = up ? (a > b || (a == b && ia > ib)) : (a < b || (a == b && ia < ib));
    if (sw) {
        key[base + i] = b; key[base + p] = a;
        idx[base + i] = ib; idx[base + p] = ia;
    }
}

// ---------------- LN -> bf16 ----------------
__global__ void __launch_bounds__(256) ln_bf(const float* __restrict__ x, const float* __restrict__ g,
                                             const float* __restrict__ b, __nv_bfloat16* __restrict__ y) {
    int row = blockIdx.x, tid = threadIdx.x;
    __shared__ float red8[8];
    float v = x[(size_t)row * 256 + tid];
    float mean = blocksum256(v, red8) * (1.f / 256.f);
    __syncthreads();
    float dv = v - mean;
    float var = blocksum256(dv * dv, red8) * (1.f / 256.f);
    y[(size_t)row * 256 + tid] = __float2bfloat16(dv * rsqrtf(var + 1e-5f) * g[tid] + b[tid]);
}

// ---------------- tensor-core GEMM (templated K, 4-stage, 1 sync/iter) ----------------
// epi: 0 none, 1 relu, 2 gelu, 3 sigmoid, 4 +resid[ridx], 5 resid + gate*val,
//      6 +resid[m]; bf16 scatter to Cout[ridx[m]]; atomic gt column sums
#define GBM 128
#define GBN 128
#define GKT 32
#define STG_BYTES 20480
#define NSTAGE 4

template<int NK>
__global__ void __launch_bounds__(256) gemm_bf16(
    const __nv_bfloat16* __restrict__ A_, const __nv_bfloat16* __restrict__ Bt_,
    const float* __restrict__ bias_,
    const float* __restrict__ resid, const float* __restrict__ gate,
    void* __restrict__ Cout_,
    int M, int Ncols, int cloudLen, int epi, int outBf16,
    const int* __restrict__ ridx, float* __restrict__ gtp, int gtLc,
    const __nv_bfloat16* A2, const __nv_bfloat16* Bt2, const float* bias2, void* Cout2)
{
    constexpr int K = NK * GKT;
    extern __shared__ char smraw[];
    const __nv_bfloat16* A = A_;
    const __nv_bfloat16* Bt = Bt_;
    const float* bias = bias_;
    void* Cout = Cout_;
    if (blockIdx.z == 1) { A = A2; Bt = Bt2; bias = bias2; Cout = Cout2; }
    const int tid = threadIdx.x;
    const int lane = tid & 31;
    const int warp = tid >> 5;
    const int wm = warp >> 1, wn = warp & 1;
    const int m0 = blockIdx.y * GBM, n0 = blockIdx.x * GBN;

    float acc[2][8][4];
    #pragma unroll
    for (int i = 0; i < 2; i++)
        #pragma unroll
        for (int j = 0; j < 8; j++)
            #pragma unroll
            for (int q = 0; q < 4; q++) acc[i][j][q] = 0.f;

    // hoisted cp.async source rows / smem targets
    const int ldrow0 = tid >> 2, ldc0 = tid & 3;
    const int ldrow1 = (tid + 256) >> 2;
    const __nv_bfloat16* gA0 = A + (size_t)(m0 + ldrow0) * K + ldc0 * 8;
    const __nv_bfloat16* gA1 = A + (size_t)(m0 + ldrow1) * K + ldc0 * 8;
    const __nv_bfloat16* gB0 = Bt + (size_t)(n0 + ldrow0) * K + ldc0 * 8;
    const __nv_bfloat16* gB1 = Bt + (size_t)(n0 + ldrow1) * K + ldc0 * 8;
    const uint32_t smemBase = smem_u32(smraw);
    const uint32_t dA0 = smemBase + ldrow0 * 80 + ldc0 * 16;
    const uint32_t dA1 = smemBase + ldrow1 * 80 + ldc0 * 16;
    const uint32_t dB0 = dA0 + 10240;
    const uint32_t dB1 = dA1 + 10240;

    // hoisted ldmatrix offsets (relative to stage base)
    uint32_t aoff[2], boff[4];
    #pragma unroll
    for (int i = 0; i < 2; i++)
        aoff[i] = smemBase + (wm * 32 + i * 16 + (lane & 15)) * 80 + (lane >> 4) * 16;
    #pragma unroll
    for (int jp = 0; jp < 4; jp++)
        boff[jp] = smemBase + 10240 + (wn * 64 + jp * 16 + (lane & 15)) * 80 + (lane >> 4) * 16;

    auto issue = [&](int s, int kt) {
        uint32_t sb = s * STG_BYTES;
        int go = kt * GKT;
        asm volatile("cp.async.cg.shared.global [%0], [%1], 16;\n" :: "r"(dA0 + sb), "l"(gA0 + go));
        asm volatile("cp.async.cg.shared.global [%0], [%1], 16;\n" :: "r"(dB0 + sb), "l"(gB0 + go));
        asm volatile("cp.async.cg.shared.global [%0], [%1], 16;\n" :: "r"(dA1 + sb), "l"(gA1 + go));
        asm volatile("cp.async.cg.shared.global [%0], [%1], 16;\n" :: "r"(dB1 + sb), "l"(gB1 + go));
        asm volatile("cp.async.commit_group;\n");
    };

    issue(0, 0);
    issue(1, 1);
    #pragma unroll
    for (int kt = 0; kt < NK; kt++) {
        const int s = kt & (NSTAGE - 1);
        if (kt + 2 < NK) {
            issue((kt + 2) & (NSTAGE - 1), kt + 2);
            asm volatile("cp.async.wait_group 2;\n");
        } else if (kt + 1 < NK) {
            asm volatile("cp.async.wait_group 1;\n");
        } else {
            asm volatile("cp.async.wait_group 0;\n");
        }
        __syncthreads();

        const uint32_t sb = s * STG_BYTES;
        #pragma unroll
        for (int kk = 0; kk < 2; kk++) {
            uint32_t af[2][4];
            #pragma unroll
            for (int i = 0; i < 2; i++) {
                asm volatile("ldmatrix.sync.aligned.m8n8.x4.shared.b16 {%0,%1,%2,%3}, [%4];"
                             : "=r"(af[i][0]), "=r"(af[i][1]), "=r"(af[i][2]), "=r"(af[i][3])
                             : "r"(aoff[i] + sb + kk * 32));
            }
            uint32_t bf[8][2];
            #pragma unroll
            for (int jp = 0; jp < 4; jp++) {
                uint32_t r0, r1, r2, r3;
                asm volatile("ldmatrix.sync.aligned.m8n8.x4.shared.b16 {%0,%1,%2,%3}, [%4];"
                             : "=r"(r0), "=r"(r1), "=r"(r2), "=r"(r3)
                             : "r"(boff[jp] + sb + kk * 32));
                bf[2*jp][0] = r0; bf[2*jp+1][0] = r1;
                bf[2*jp][1] = r2; bf[2*jp+1][1] = r3;
            }
            #pragma unroll
            for (int i = 0; i < 2; i++)
                #pragma unroll
                for (int j = 0; j < 8; j++) {
                    asm volatile("mma.sync.aligned.m16n8k16.row.col.f32.bf16.bf16.f32 "
                                 "{%0,%1,%2,%3}, {%4,%5,%6,%7}, {%8,%9}, {%0,%1,%2,%3};"
                                 : "+f"(acc[i][j][0]), "+f"(acc[i][j][1]),
                                   "+f"(acc[i][j][2]), "+f"(acc[i][j][3])
                                 : "r"(af[i][0]), "r"(af[i][1]), "r"(af[i][2]), "r"(af[i][3]),
                                   "r"(bf[j][0]), "r"(bf[j][1]));
                }
        }
    }

    const int rbase = m0 + wm * 32 + (lane >> 2);
    const int cbase = n0 + wn * 64 + 2 * (lane & 3);
    float gta[8][2];
    #pragma unroll
    for (int j = 0; j < 8; j++) { gta[j][0] = 0.f; gta[j][1] = 0.f; }

    #pragma unroll
    for (int i = 0; i < 2; i++) {
        #pragma unroll
        for (int half = 0; half < 2; half++) {
            int m = rbase + i * 16 + half * 8;
            const float* bp = (cloudLen > 0) ? (bias + (size_t)(m / cloudLen) * Ncols) : bias;
            #pragma unroll
            for (int j = 0; j < 8; j++) {
                int n = cbase + j * 8;
                float v0 = acc[i][j][half * 2 + 0] + bp[n];
                float v1 = acc[i][j][half * 2 + 1] + bp[n + 1];
                size_t o = (size_t)m * Ncols + n;
                bool stored = false;
                switch (epi) {
                    case 1: v0 = fmaxf(v0, 0.f); v1 = fmaxf(v1, 0.f); break;
                    case 2:
                        v0 = 0.5f * v0 * (1.f + erff(v0 * 0.70710678118f));
                        v1 = 0.5f * v1 * (1.f + erff(v1 * 0.70710678118f));
                        break;
                    case 3:
                        v0 = frcp_fast(1.f + fexpf_fast(-v0));
                        v1 = frcp_fast(1.f + fexpf_fast(-v1));
                        break;
                    case 4: {
                        size_t ro = (size_t)(ridx ? ridx[m] : m) * Ncols + n;
                        float2 r = *(const float2*)(resid + ro);
                        v0 += r.x; v1 += r.y;
                    } break;
                    case 5: {
                        float2 r = *(const float2*)(resid + o);
                        float2 gg = *(const float2*)(gate + o);
                        v0 = r.x + gg.x * v0; v1 = r.y + gg.y * v1;
                    } break;
                    case 6: {
                        float2 r = *(const float2*)(resid + o);
                        v0 += r.x; v1 += r.y;
                        gta[j][0] += v0; gta[j][1] += v1;
                        size_t od = (size_t)ridx[m] * Ncols + n;
                        __nv_bfloat162 h;
                        h.x = __float2bfloat16(v0); h.y = __float2bfloat16(v1);
                        *(__nv_bfloat162*)((__nv_bfloat16*)Cout + od) = h;
                        stored = true;
                    } break;
                    default: break;
                }
                if (!stored) {
                    if (outBf16) {
                        __nv_bfloat162 h;
                        h.x = __float2bfloat16(v0); h.y = __float2bfloat16(v1);
                        *(__nv_bfloat162*)((__nv_bfloat16*)Cout + o) = h;
                    } else {
                        *(float2*)((float*)Cout + o) = make_float2(v0, v1);
                    }
                }
            }
        }
    }
    if (epi == 6) {
        int c = m0 / gtLc;
        #pragma unroll
        for (int j = 0; j < 8; j++) {
            float s0 = gta[j][0], s1 = gta[j][1];
            #pragma unroll
            for (int off = 4; off <= 16; off <<= 1) {
                s0 += __shfl_xor_sync(0xffffffffu, s0, off);
                s1 += __shfl_xor_sync(0xffffffffu, s1, off);
            }
            if ((lane >> 2) == 0) {
                int n = cbase + j * 8;
                atomicAdd(gtp + c * 256 + n, s0);
                atomicAdd(gtp + c * 256 + n + 1, s1);
            }
        }
    }
}

// ---------------- flash attention (gathers rows via sidx) ----------------
#define FA_SMEM (20480 * 2 + 32 * 528)
__global__ void __launch_bounds__(256) fattn(const __nv_bfloat16* __restrict__ qkv,
                                             const int* __restrict__ sidx,
                                             __nv_bfloat16* __restrict__ o) {
    extern __shared__ char sm[];
    char* sq = sm;
    char* sk = sm + 20480;
    char* svt = sm + 40960;
    const int p = blockIdx.x, h = blockIdx.y;
    const int tid = threadIdx.x;
    const int lane = tid & 31;
    const int w = tid >> 5;
    const size_t base = (size_t)p * 256;
    const float SC = 0.17677669529663687f * 1.4426950408889634f;

    {
        const size_t src = (size_t)sidx[base + tid] * 768;
        const uint4* qr = (const uint4*)(qkv + src + h * 32);
        const uint4* kr = (const uint4*)(qkv + src + 256 + h * 32);
        const uint4* vr = (const uint4*)(qkv + src + 512 + h * 32);
        uint4* dq = (uint4*)(sq + tid * 80);
        uint4* dk = (uint4*)(sk + tid * 80);
        uint4 v0 = vr[0], v1 = vr[1], v2 = vr[2], v3 = vr[3];
        dq[0] = qr[0]; dq[1] = qr[1]; dq[2] = qr[2]; dq[3] = qr[3];
        dk[0] = kr[0]; dk[1] = kr[1]; dk[2] = kr[2]; dk[3] = kr[3];
        uint32_t vu[8] = {v0.x, v0.y, v0.z, v0.w, v1.x, v1.y, v1.z, v1.w};
        uint32_t vu2[8] = {v2.x, v2.y, v2.z, v2.w, v3.x, v3.y, v3.z, v3.w};
        #pragma unroll
        for (int e = 0; e < 8; e++) {
            ((__nv_bfloat16*)(svt + (2 * e + 0) * 528))[tid] = ((__nv_bfloat162*)&vu[e])->x;
            ((__nv_bfloat16*)(svt + (2 * e + 1) * 528))[tid] = ((__nv_bfloat162*)&vu[e])->y;
        }
        #pragma unroll
        for (int e = 0; e < 8; e++) {
            ((__nv_bfloat16*)(svt + (16 + 2 * e + 0) * 528))[tid] = ((__nv_bfloat162*)&vu2[e])->x;
            ((__nv_bfloat16*)(svt + (16 + 2 * e + 1) * 528))[tid] = ((__nv_bfloat162*)&vu2[e])->y;
        }
    }
    __syncthreads();

    const int m0w = w * 32;
    uint32_t qa[2][2][4];
    #pragma unroll
    for (int i = 0; i < 2; i++)
        #pragma unroll
        for (int kk = 0; kk < 2; kk++) {
            int r = m0w + i * 16 + (lane & 15);
            uint32_t addr = smem_u32(sq + r * 80 + kk * 32 + (lane >> 4) * 16);
            asm volatile("ldmatrix.sync.aligned.m8n8.x4.shared.b16 {%0,%1,%2,%3}, [%4];"
                         : "=r"(qa[i][kk][0]), "=r"(qa[i][kk][1]),
                           "=r"(qa[i][kk][2]), "=r"(qa[i][kk][3])
                         : "r"(addr));
        }

    float oacc[2][4][4];
    #pragma unroll
    for (int i = 0; i < 2; i++)
        #pragma unroll
        for (int d = 0; d < 4; d++)
            #pragma unroll
            for (int q = 0; q < 4; q++) oacc[i][d][q] = 0.f;
    float mrow[2][2] = {{-1e30f, -1e30f}, {-1e30f, -1e30f}};
    float lrow[2][2] = {{0.f, 0.f}, {0.f, 0.f}};

    for (int jc = 0; jc < 8; jc++) {
        uint32_t kb[2][4][2];
        #pragma unroll
        for (int jp = 0; jp < 2; jp++)
            #pragma unroll
            for (int kk = 0; kk < 2; kk++) {
                int r = jc * 32 + jp * 16 + (lane & 15);
                uint32_t addr = smem_u32(sk + r * 80 + kk * 32 + (lane >> 4) * 16);
                uint32_t r0, r1, r2, r3;
                asm volatile("ldmatrix.sync.aligned.m8n8.x4.shared.b16 {%0,%1,%2,%3}, [%4];"
                             : "=r"(r0), "=r"(r1), "=r"(r2), "=r"(r3) : "r"(addr));
                kb[kk][2*jp][0] = r0;   kb[kk][2*jp][1] = r2;
                kb[kk][2*jp+1][0] = r1; kb[kk][2*jp+1][1] = r3;
            }

        float sacc[2][4][4];
        #pragma unroll
        for (int i = 0; i < 2; i++)
            #pragma unroll
            for (int nt = 0; nt < 4; nt++)
                #pragma unroll
                for (int q = 0; q < 4; q++) sacc[i][nt][q] = 0.f;
        #pragma unroll
        for (int kk = 0; kk < 2; kk++)
            #pragma unroll
            for (int i = 0; i < 2; i++)
                #pragma unroll
                for (int nt = 0; nt < 4; nt++) {
                    asm volatile("mma.sync.aligned.m16n8k16.row.col.f32.bf16.bf16.f32 "
                                 "{%0,%1,%2,%3}, {%4,%5,%6,%7}, {%8,%9}, {%0,%1,%2,%3};"
                                 : "+f"(sacc[i][nt][0]), "+f"(sacc[i][nt][1]),
                                   "+f"(sacc[i][nt][2]), "+f"(sacc[i][nt][3])
                                 : "r"(qa[i][kk][0]), "r"(qa[i][kk][1]),
                                   "r"(qa[i][kk][2]), "r"(qa[i][kk][3]),
                                   "r"(kb[kk][nt][0]), "r"(kb[kk][nt][1]));
                }

        #pragma unroll
        for (int i = 0; i < 2; i++)
            #pragma unroll
            for (int nt = 0; nt < 4; nt++)
                #pragma unroll
                for (int q = 0; q < 4; q++) sacc[i][nt][q] *= SC;

        #pragma unroll
        for (int i = 0; i < 2; i++) {
            #pragma unroll
            for (int half = 0; half < 2; half++) {
                float mx = -1e30f;
                #pragma unroll
                for (int nt = 0; nt < 4; nt++) {
                    mx = fmaxf(mx, sacc[i][nt][half*2+0]);
                    mx = fmaxf(mx, sacc[i][nt][half*2+1]);
                }
                mx = fmaxf(mx, __shfl_xor_sync(0xffffffffu, mx, 1));
                mx = fmaxf(mx, __shfl_xor_sync(0xffffffffu, mx, 2));
                float newm = fmaxf(mrow[i][half], mx);
                float alpha = fexp2_fast(mrow[i][half] - newm);
                mrow[i][half] = newm;
                float rs = 0.f;
                #pragma unroll
                for (int nt = 0; nt < 4; nt++) {
                    float p0 = fexp2_fast(sacc[i][nt][half*2+0] - newm);
                    float p1 = fexp2_fast(sacc[i][nt][half*2+1] - newm);
                    sacc[i][nt][half*2+0] = p0;
                    sacc[i][nt][half*2+1] = p1;
                    rs += p0 + p1;
                }
                rs += __shfl_xor_sync(0xffffffffu, rs, 1);
                rs += __shfl_xor_sync(0xffffffffu, rs, 2);
                lrow[i][half] = lrow[i][half] * alpha + rs;
                #pragma unroll
                for (int dt = 0; dt < 4; dt++) {
                    oacc[i][dt][half*2+0] *= alpha;
                    oacc[i][dt][half*2+1] *= alpha;
                }
            }
        }

        uint32_t pa[2][2][4];
        #pragma unroll
        for (int i = 0; i < 2; i++)
            #pragma unroll
            for (int kk = 0; kk < 2; kk++) {
                int ntl = kk * 2, nth = kk * 2 + 1;
                __nv_bfloat162 b0 = __float22bfloat162_rn(make_float2(sacc[i][ntl][0], sacc[i][ntl][1]));
                __nv_bfloat162 b1 = __float22bfloat162_rn(make_float2(sacc[i][ntl][2], sacc[i][ntl][3]));
                __nv_bfloat162 b2 = __float22bfloat162_rn(make_float2(sacc[i][nth][0], sacc[i][nth][1]));
                __nv_bfloat162 b3 = __float22bfloat162_rn(make_float2(sacc[i][nth][2], sacc[i][nth][3]));
                pa[i][kk][0] = *(uint32_t*)&b0;
                pa[i][kk][1] = *(uint32_t*)&b1;
                pa[i][kk][2] = *(uint32_t*)&b2;
                pa[i][kk][3] = *(uint32_t*)&b3;
            }

        uint32_t vb[2][4][2];
        #pragma unroll
        for (int jp = 0; jp < 2; jp++)
            #pragma unroll
            for (int kk = 0; kk < 2; kk++) {
                int r = jp * 16 + (lane & 15);
                uint32_t addr = smem_u32(svt + r * 528 + jc * 64 + kk * 32 + (lane >> 4) * 16);
                uint32_t r0, r1, r2, r3;
                asm volatile("ldmatrix.sync.aligned.m8n8.x4.shared.b16 {%0,%1,%2,%3}, [%4];"
                             : "=r"(r0), "=r"(r1), "=r"(r2), "=r"(r3) : "r"(addr));
                vb[kk][2*jp][0] = r0;   vb[kk][2*jp][1] = r2;
                vb[kk][2*jp+1][0] = r1; vb[kk][2*jp+1][1] = r3;
            }

        #pragma unroll
        for (int kk = 0; kk < 2; kk++)
            #pragma unroll
            for (int i = 0; i < 2; i++)
                #pragma unroll
                for (int dt = 0; dt < 4; dt++) {
                    asm volatile("mma.sync.aligned.m16n8k16.row.col.f32.bf16.bf16.f32 "
                                 "{%0,%1,%2,%3}, {%4,%5,%6,%7}, {%8,%9}, {%0,%1,%2,%3};"
                                 : "+f"(oacc[i][dt][0]), "+f"(oacc[i][dt][1]),
                                   "+f"(oacc[i][dt][2]), "+f"(oacc[i][dt][3])
                                 : "r"(pa[i][kk][0]), "r"(pa[i][kk][1]),
                                   "r"(pa[i][kk][2]), "r"(pa[i][kk][3]),
                                   "r"(vb[kk][dt][0]), "r"(vb[kk][dt][1]));
                }
    }

    #pragma unroll
    for (int i = 0; i < 2; i++)
        #pragma unroll
        for (int half = 0; half < 2; half++) {
            float inv = 1.f / lrow[i][half];
            int row = m0w + i * 16 + half * 8 + (lane >> 2);
            #pragma unroll
            for (int dt = 0; dt < 4; dt++) {
                int col = h * 32 + dt * 8 + 2 * (lane & 3);
                __nv_bfloat162 hv;
                hv.x = __float2bfloat16(oacc[i][dt][half*2+0] * inv);
                hv.y = __float2bfloat16(oacc[i][dt][half*2+1] * inv);
                *(__nv_bfloat162*)(o + (base + row) * 256 + col) = hv;
            }
        }
}

// ---------------- fold gt into per-cloud biases ----------------
__global__ void cloudbias_kernel(const float* __restrict__ gtsum,
                                 const float* __restrict__ gg_w1, const float* __restrict__ gg_b1,
                                 const float* __restrict__ f_w1, const float* __restrict__ f_b1,
                                 float* __restrict__ ggb, float* __restrict__ fb, int Lc) {
    int c = blockIdx.x, j = threadIdx.x;
    float s1 = gg_b1[j], s2 = f_b1[j];
    float invL = 1.f / (float)Lc;
    for (int h = 0; h < 256; h++) {
        float gv = gtsum[c * 256 + h] * invL;
        s1 += gv * gg_w1[(size_t)(256 + h) * 256 + j];
        s2 += gv * f_w1[(size_t)(256 + h) * 256 + j];
    }
    ggb[c * 256 + j] = s1;
    fb[c * 256 + j] = s2;
}

// ---------------- launch ----------------
extern "C" void kernel_launch(void* const* d_in, const int* in_sizes, int n_in,
                              void* d_out, int out_size) {
    const float* feats = (const float*)d_in[0];
    const float* coord = (const float*)d_in[1];
    const float* pe_w1 = (const float*)d_in[3];
    const float* pe_b1 = (const float*)d_in[4];
    const float* pe_w2 = (const float*)d_in[5];
    const float* pe_b2 = (const float*)d_in[6];
    const float* pre_g = (const float*)d_in[7];
    const float* pre_b = (const float*)d_in[8];
    const float* n1_g  = (const float*)d_in[9];
    const float* n1_b  = (const float*)d_in[10];
    const float* wqkv  = (const float*)d_in[11];
    const float* bqkv  = (const float*)d_in[12];
    const float* wo    = (const float*)d_in[13];
    const float* bo    = (const float*)d_in[14];
    const float* n2_g  = (const float*)d_in[15];
    const float* n2_b  = (const float*)d_in[16];
    const float* m_w1  = (const float*)d_in[17];
    const float* m_b1  = (const float*)d_in[18];
    const float* m_w2  = (const float*)d_in[19];
    const float* m_b2  = (const float*)d_in[20];
    const float* gg_w1 = (const float*)d_in[21];
    const float* gg_b1 = (const float*)d_in[22];
    const float* gg_w2 = (const float*)d_in[23];
    const float* gg_b2 = (const float*)d_in[24];
    const float* f_w1  = (const float*)d_in[25];
    const float* f_b1  = (const float*)d_in[26];
    const float* f_w2  = (const float*)d_in[27];
    const float* f_b2  = (const float*)d_in[28];
    float* out = (float*)d_out;

    int N = in_sizes[0] / 256;
    int B = in_sizes[2];
    int Lc = N / B;
    int patches = N / 256;

    float *p_x, *p_xs, *p_key, *p_gt, *p_ggb, *p_fb, *p_stats;
    __nv_bfloat16 *p_ba, *p_bb, *p_fe, *p_wt;
    int* p_idx;
    cudaGetSymbolAddress((void**)&p_x, g_x);
    cudaGetSymbolAddress((void**)&p_xs, g_xs);
    cudaGetSymbolAddress((void**)&p_ba, g_ba);
    cudaGetSymbolAddress((void**)&p_bb, g_bb);
    cudaGetSymbolAddress((void**)&p_fe, g_fe);
    cudaGetSymbolAddress((void**)&p_wt, g_wt);
    cudaGetSymbolAddress((void**)&p_key, g_key);
    cudaGetSymbolAddress((void**)&p_idx, g_idx);
    cudaGetSymbolAddress((void**)&p_gt, g_gt);
    cudaGetSymbolAddress((void**)&p_ggb, g_ggb);
    cudaGetSymbolAddress((void**)&p_fb, g_fb);
    cudaGetSymbolAddress((void**)&p_stats, g_stats);

    __nv_bfloat16* wqkv_t = p_wt + 0;
    __nv_bfloat16* wo_t   = p_wt + 196608;
    __nv_bfloat16* mw1_t  = p_wt + 262144;
    __nv_bfloat16* mw2_t  = p_wt + 393216;
    __nv_bfloat16* ggw1_t = p_wt + 524288;
    __nv_bfloat16* ggw2_t = p_wt + 589824;
    __nv_bfloat16* fw1_t  = p_wt + 655360;
    __nv_bfloat16* fw2_t  = p_wt + 720896;
    __nv_bfloat16* bb_lo = p_bb;
    __nv_bfloat16* bb_hi = p_bb + (size_t)N * 256;

    cudaFuncSetAttribute(fattn, cudaFuncAttributeMaxDynamicSharedMemorySize, FA_SMEM);
    cudaFuncSetAttribute(sort_local, cudaFuncAttributeMaxDynamicSharedMemorySize, CHUNK * 8);
    cudaFuncSetAttribute(merge_local, cudaFuncAttributeMaxDynamicSharedMemorySize, CHUNK * 8);
    cudaFuncSetAttribute(gemm_bf16<8>, cudaFuncAttributeMaxDynamicSharedMemorySize, NSTAGE * STG_BYTES);
    cudaFuncSetAttribute(gemm_bf16<16>, cudaFuncAttributeMaxDynamicSharedMemorySize, NSTAGE * STG_BYTES);

    PrepArgs pa;
    pa.coord = coord; pa.stats = p_stats; pa.Lc = Lc; pa.B = B;
    const float* ws[8] = {wqkv, wo, m_w1, m_w2, gg_w1, gg_w2, f_w1, f_w2};
    __nv_bfloat16* wd[8] = {wqkv_t, wo_t, mw1_t, mw2_t, ggw1_t, ggw2_t, fw1_t, fw2_t};
    int wK[8] = {256, 256, 256, 512, 256, 256, 256, 256};
    int wN[8] = {768, 256, 512, 256, 256, 256, 256, 256};
    int tiles = 0;
    for (int i = 0; i < 8; i++) {
        pa.wsrc[i] = ws[i]; pa.wdst[i] = wd[i];
        pa.wK[i] = wK[i]; pa.wN[i] = wN[i];
        pa.wt0[i] = tiles;
        tiles += (wK[i] / 32) * (wN[i] / 32);
    }
    pa.totalWTiles = tiles;
    pa.gt = p_gt;

    // 1: prep
    prep_kernel<<<B + tiles + 1, 1024>>>(pa);
    // 2: PE + pre-LN + LN1 + key (original order)
    pe_ln_key_kernel<<<N, 256>>>(feats, coord, pe_w1, pe_b1, pe_w2, pe_b2,
                                 pre_g, pre_b, n1_g, n1_b, p_stats,
                                 p_x, p_bb, p_fe, p_key, p_idx, Lc);
    // 3: local sort
    sort_local<<<N / CHUNK, 1024, CHUNK * 8>>>(p_key, p_idx, Lc);
    // 4: qkv GEMM (unpermuted) -> ba  [profiled launch]
    gemm_bf16<8><<<dim3(768/GBN, N/GBM), 256, NSTAGE*STG_BYTES>>>(
        p_bb, wqkv_t, bqkv, nullptr, nullptr, p_ba, N, 768, 0, 0, 1,
        nullptr, nullptr, 0, nullptr, nullptr, nullptr, nullptr);
    // 5-6: finish the sort
    for (int k = CHUNK * 2; k <= Lc; k <<= 1) {
        for (int j = k >> 1; j >= CHUNK; j >>= 1)
            sort_global<<<dim3(Lc / 512, B), 256>>>(p_key, p_idx, k, j, Lc);
        merge_local<<<N / CHUNK, 1024, CHUNK * 8>>>(p_key, p_idx, k, Lc);
    }
    // 7: flash attention (gather via idx) -> bb
    fattn<<<dim3(patches, 8), 256, FA_SMEM>>>(p_ba, p_idx, p_bb);
    // 8: wo GEMM + gathered residual -> xs fp32
    gemm_bf16<8><<<dim3(256/GBN, N/GBM), 256, NSTAGE*STG_BYTES>>>(
        p_bb, wo_t, bo, p_x, nullptr, p_xs, N, 256, 0, 4, 0,
        p_idx, nullptr, 0, nullptr, nullptr, nullptr, nullptr);
    // 9: LN2 -> ba bf16
    ln_bf<<<N, 256>>>(p_xs, n2_g, n2_b, p_ba);
    // 10: MLP1 + gelu -> bb
    gemm_bf16<8><<<dim3(512/GBN, N/GBM), 256, NSTAGE*STG_BYTES>>>(
        p_ba, mw1_t, m_b1, nullptr, nullptr, p_bb, N, 512, 0, 2, 1,
        nullptr, nullptr, 0, nullptr, nullptr, nullptr, nullptr);
    // 11: MLP2 + resid; scatter xo -> ba; gt atomics
    gemm_bf16<16><<<dim3(256/GBN, N/GBM), 256, NSTAGE*STG_BYTES>>>(
        p_bb, mw2_t, m_b2, p_xs, nullptr, p_ba, N, 256, 0, 6, 1,
        p_idx, p_gt, Lc, nullptr, nullptr, nullptr, nullptr);
    // 12: per-cloud biases
    cloudbias_kernel<<<B, 256>>>(p_gt, gg_w1, gg_b1, f_w1, f_b1, p_ggb, p_fb, Lc);
    // 13: batched hidden GEMMs (z=0 gate, z=1 fuse)
    gemm_bf16<8><<<dim3(256/GBN, N/GBM, 2), 256, NSTAGE*STG_BYTES>>>(
        p_fe, ggw1_t, p_ggb, nullptr, nullptr, bb_lo, N, 256, Lc, 1, 1,
        nullptr, nullptr, 0, p_ba, fw1_t, p_fb, bb_hi);
    // 14: gate sigmoid -> p_x fp32
    gemm_bf16<8><<<dim3(256/GBN, N/GBM), 256, NSTAGE*STG_BYTES>>>(
        bb_lo, ggw2_t, gg_b2, nullptr, nullptr, p_x, N, 256, 0, 3, 0,
        nullptr, nullptr, 0, nullptr, nullptr, nullptr, nullptr);
    // 15: out = feats + gate * fused
    gemm_bf16<8><<<dim3(256/GBN, N/GBM), 256, NSTAGE*STG_BYTES>>>(
        bb_hi, fw2_t, f_b2, feats, p_x, out, N, 256, 0, 5, 0,
        nullptr, nullptr, 0, nullptr, nullptr, nullptr, nullptr);
}

// round 9
// speedup vs baseline: 4.2136x; 1.0748x over previous
#include <cuda_runtime.h>
#include <cuda_bf16.h>
#include <math.h>
#include <stdint.h>

// ---------------- static scratch ----------------
#define MAXN 131072
#define DD 256
__device__ float g_x  [(size_t)MAXN * DD];
__device__ float g_xs [(size_t)MAXN * DD];
__device__ __nv_bfloat16 g_ba[(size_t)MAXN * 768];
__device__ __nv_bfloat16 g_bb[(size_t)MAXN * 512];
__device__ __nv_bfloat16 g_fe[(size_t)MAXN * 256];
__device__ __nv_bfloat16 g_wt[786432];
__device__ float g_key[MAXN];
__device__ int   g_idx[MAXN];
__device__ float g_gt [8 * DD];
__device__ float g_ggb[8 * DD];
__device__ float g_fb [8 * DD];
__device__ float g_stats[8 * 12];

// ---------------- fast math ----------------
__device__ __forceinline__ float fexp2_fast(float z) {
    z = fmaxf(z, -80.f);
    float n = rintf(z);
    float f = z - n;
    float p = 0.009618129f;
    p = p * f + 0.055504109f;
    p = p * f + 0.240226507f;
    p = p * f + 0.693147181f;
    p = p * f + 1.0f;
    return p * __int_as_float(((int)n + 127) << 23);
}
__device__ __forceinline__ float fexpf_fast(float x) {
    return fexp2_fast(x * 1.4426950408889634f);
}
__device__ __forceinline__ float frcp_fast(float d) {
    float y = __int_as_float(0x7ef311c3 - __float_as_int(d));
    y = y * (2.f - d * y);
    y = y * (2.f - d * y);
    y = y * (2.f - d * y);
    return y;
}
__device__ __forceinline__ uint32_t smem_u32(const void* p) {
    return (uint32_t)__cvta_generic_to_shared(p);
}
__device__ __forceinline__ float blocksum256(float v, float* red8) {
    #pragma unroll
    for (int off = 16; off; off >>= 1) v += __shfl_xor_sync(0xffffffffu, v, off);
    if ((threadIdx.x & 31) == 0) red8[threadIdx.x >> 5] = v;
    __syncthreads();
    float s = 0.f;
    #pragma unroll
    for (int i = 0; i < 8; i++) s += red8[i];
    return s;
}

// ---------------- prep ----------------
struct PrepArgs {
    const float* coord; float* stats; int Lc; int B;
    const float* wsrc[8]; __nv_bfloat16* wdst[8];
    int wK[8], wN[8], wt0[8];
    int totalWTiles;
    float* gt;
};
__global__ void __launch_bounds__(1024) prep_kernel(PrepArgs a) {
    __shared__ float red[1024];
    __shared__ float tt[32][33];
    int b = blockIdx.x, tid = threadIdx.x;
    if (b < a.B) {
        int c = b, Lc = a.Lc;
        float sum[3] = {0,0,0}, mn[3] = {1e30f,1e30f,1e30f}, mx[3] = {-1e30f,-1e30f,-1e30f};
        for (int i = tid; i < Lc; i += 1024) {
            const float* cp = a.coord + (size_t)(c * Lc + i) * 3;
            #pragma unroll
            for (int d = 0; d < 3; d++) {
                float v = cp[d];
                sum[d] += v; mn[d] = fminf(mn[d], v); mx[d] = fmaxf(mx[d], v);
            }
        }
        for (int d = 0; d < 3; d++) {
            red[tid] = sum[d]; __syncthreads();
            for (int s = 512; s > 0; s >>= 1) { if (tid < s) red[tid] += red[tid + s]; __syncthreads(); }
            float tot = red[0]; __syncthreads();
            red[tid] = mn[d]; __syncthreads();
            for (int s = 512; s > 0; s >>= 1) { if (tid < s) red[tid] = fminf(red[tid], red[tid + s]); __syncthreads(); }
            float tmn = red[0]; __syncthreads();
            red[tid] = mx[d]; __syncthreads();
            for (int s = 512; s > 0; s >>= 1) { if (tid < s) red[tid] = fmaxf(red[tid], red[tid + s]); __syncthreads(); }
            float tmx = red[0]; __syncthreads();
            if (tid == 0) {
                float mean = tot / (float)Lc;
                a.stats[c*12 + d]     = mean;
                a.stats[c*12 + 3 + d] = fmaxf(fmaxf(tmx - mean, mean - tmn), 1e-6f);
                a.stats[c*12 + 6 + d] = tmn;
                a.stats[c*12 + 9 + d] = 1.f / fmaxf(tmx - tmn, 1e-6f);
            }
            __syncthreads();
        }
    } else if (b < a.B + a.totalWTiles) {
        int t = b - a.B;
        int w = 0;
        #pragma unroll
        for (int q = 1; q < 8; q++) if (t >= a.wt0[q]) w = q;
        int lt = t - a.wt0[w];
        int tilesX = a.wN[w] >> 5;
        int bx = (lt % tilesX) << 5, by = (lt / tilesX) << 5;
        const float* src = a.wsrc[w];
        __nv_bfloat16* dst = a.wdst[w];
        int K = a.wK[w], Ncols = a.wN[w];
        int tx = tid & 31, ty = tid >> 5;
        tt[ty][tx] = src[(size_t)(by + ty) * Ncols + bx + tx];
        __syncthreads();
        dst[(size_t)(bx + ty) * K + by + tx] = __float2bfloat16(tt[tx][ty]);
    } else {
        a.gt[tid] = 0.f;
        a.gt[tid + 1024] = 0.f;
    }
}

// ---------------- PE + pre-LN + LN1 + key + feats->bf16 ----------------
__global__ void __launch_bounds__(256) pe_ln_key_kernel(
    const float* __restrict__ feats, const float* __restrict__ coord,
    const float* __restrict__ w1, const float* __restrict__ b1,
    const float* __restrict__ w2, const float* __restrict__ b2,
    const float* __restrict__ g, const float* __restrict__ beta,
    const float* __restrict__ n1g, const float* __restrict__ n1b,
    const float* __restrict__ stats,
    float* __restrict__ xout, __nv_bfloat16* __restrict__ hbf,
    __nv_bfloat16* __restrict__ febf,
    float* __restrict__ key, int* __restrict__ idx, int Lc)
{
    int i = blockIdx.x, tid = threadIdx.x;
    int c = i / Lc;
    __shared__ float hid[64];
    __shared__ float red8[8];
    const float* st = stats + c * 12;
    float c0 = coord[(size_t)i*3+0], c1 = coord[(size_t)i*3+1], c2 = coord[(size_t)i*3+2];
    if (tid < 64) {
        float n0 = (c0 - st[0]) / st[3];
        float n1 = (c1 - st[1]) / st[4];
        float n2 = (c2 - st[2]) / st[5];
        float hv = b1[tid] + n0 * w1[tid] + n1 * w1[64 + tid] + n2 * w1[128 + tid];
        hid[tid] = fmaxf(hv, 0.f);
    }
    if (tid == 0) {
        float k0 = (c0 - st[6]) * st[9];
        float k1 = (c1 - st[7]) * st[10];
        float k2 = (c2 - st[8]) * st[11];
        key[i] = k0 + 2.17f * k1 + 3.31f * k2;
        idx[i] = i;
    }
    __syncthreads();
    float fv = feats[(size_t)i * 256 + tid];
    febf[(size_t)i * 256 + tid] = __float2bfloat16(fv);
    float pe = b2[tid];
    #pragma unroll 8
    for (int h = 0; h < 64; h++) pe += hid[h] * w2[h * 256 + tid];
    float v = fv + pe;
    float mean = blocksum256(v, red8) * (1.f / 256.f);
    __syncthreads();
    float dv = v - mean;
    float var = blocksum256(dv * dv, red8) * (1.f / 256.f);
    float xv = dv * rsqrtf(var + 1e-5f) * g[tid] + beta[tid];
    xout[(size_t)i * 256 + tid] = xv;
    __syncthreads();
    float m2 = blocksum256(xv, red8) * (1.f / 256.f);
    __syncthreads();
    float d2 = xv - m2;
    float v2 = blocksum256(d2 * d2, red8) * (1.f / 256.f);
    hbf[(size_t)i * 256 + tid] = __float2bfloat16(d2 * rsqrtf(v2 + 1e-5f) * n1g[tid] + n1b[tid]);
}

// ---------------- hierarchical bitonic sort (CHUNK=4096, more parallel) ----------------
#define CHUNK 4096
__global__ void __launch_bounds__(1024) sort_local(float* __restrict__ key, int* __restrict__ idx, int Lc) {
    extern __shared__ char smraw[];
    float* sk = (float*)smraw;
    int*   si = (int*)(smraw + CHUNK * 4);
    size_t gbase = (size_t)blockIdx.x * CHUNK;
    int lbase = (int)(gbase % (size_t)Lc);
    for (int t = threadIdx.x; t < CHUNK; t += 1024) { sk[t] = key[gbase + t]; si[t] = idx[gbase + t]; }
    __syncthreads();
    for (int k = 2; k <= CHUNK; k <<= 1) {
        for (int j = k >> 1; j > 0; j >>= 1) {
            #pragma unroll
            for (int it = 0; it < CHUNK / 2048; it++) {
                int t = threadIdx.x + it * 1024;
                int i = 2 * t - (t & (j - 1));
                int p = i + j;
                bool up = (((lbase + i) & k) == 0);
                float a = sk[i], b = sk[p];
                int ia = si[i], ib = si[p];
                bool sw = up ? (a > b || (a == b && ia > ib)) : (a < b || (a == b && ia < ib));
                if (sw) { sk[i] = b; sk[p] = a; si[i] = ib; si[p] = ia; }
            }
            __syncthreads();
        }
    }
    for (int t = threadIdx.x; t < CHUNK; t += 1024) { key[gbase + t] = sk[t]; idx[gbase + t] = si[t]; }
}

__global__ void __launch_bounds__(1024) merge_local(float* __restrict__ key, int* __restrict__ idx, int k, int Lc) {
    extern __shared__ char smraw[];
    float* sk = (float*)smraw;
    int*   si = (int*)(smraw + CHUNK * 4);
    size_t gbase = (size_t)blockIdx.x * CHUNK;
    int lbase = (int)(gbase % (size_t)Lc);
    for (int t = threadIdx.x; t < CHUNK; t += 1024) { sk[t] = key[gbase + t]; si[t] = idx[gbase + t]; }
    __syncthreads();
    for (int j = CHUNK / 2; j > 0; j >>= 1) {
        #pragma unroll
        for (int it = 0; it < CHUNK / 2048; it++) {
            int t = threadIdx.x + it * 1024;
            int i = 2 * t - (t & (j - 1));
            int p = i + j;
            bool up = (((lbase + i) & k) == 0);
            float a = sk[i], b = sk[p];
            int ia = si[i], ib = si[p];
            bool sw = up ? (a > b || (a == b && ia > ib)) : (a < b || (a == b && ia < ib));
            if (sw) { sk[i] = b; sk[p] = a; si[i] = ib; si[p] = ia; }
        }
        __syncthreads();
    }
    for (int t = threadIdx.x; t < CHUNK; t += 1024) { key[gbase + t] = sk[t]; idx[gbase + t] = si[t]; }
}

__global__ void __launch_bounds__(256) sort_global(float* __restrict__ key, int* __restrict__ idx, int k, int j, int Lc) {
    int c = blockIdx.y;
    size_t base = (size_t)c * Lc;
    int t = blockIdx.x * 256 + threadIdx.x;
    int i = 2 * t - (t & (j - 1));
    int p = i + j;
    bool up = ((i & k) == 0);
    float a = key[base + i], b = key[base + p];
    int ia = idx[base + i], ib = idx[base + p];
    bool sw = up ? (a > b || (a == b && ia > ib)) : (a < b || (a == b && ia < ib));
    if (sw) {
        key[base + i] = b; key[base + p] = a;
        idx[base + i] = ib; idx[base + p] = ia;
    }
}

// ---------------- LN -> bf16 ----------------
__global__ void __launch_bounds__(256) ln_bf(const float* __restrict__ x, const float* __restrict__ g,
                                             const float* __restrict__ b, __nv_bfloat16* __restrict__ y) {
    int row = blockIdx.x, tid = threadIdx.x;
    __shared__ float red8[8];
    float v = x[(size_t)row * 256 + tid];
    float mean = blocksum256(v, red8) * (1.f / 256.f);
    __syncthreads();
    float dv = v - mean;
    float var = blocksum256(dv * dv, red8) * (1.f / 256.f);
    y[(size_t)row * 256 + tid] = __float2bfloat16(dv * rsqrtf(var + 1e-5f) * g[tid] + b[tid]);
}

// ---------------- tensor-core GEMM (templated K, 4-stage, 1 sync/iter) ----------------
// epi: 0 none, 1 relu, 2 gelu, 3 sigmoid, 4 +resid[ridx], 5 resid + gate*val,
//      6 +resid[m]; bf16 scatter to Cout[ridx[m]]; atomic gt column sums
#define GBM 128
#define GBN 128
#define GKT 32
#define STG_BYTES 20480
#define NSTAGE 4

template<int NK>
__global__ void __launch_bounds__(256) gemm_bf16(
    const __nv_bfloat16* __restrict__ A_, const __nv_bfloat16* __restrict__ Bt_,
    const float* __restrict__ bias_,
    const float* __restrict__ resid, const float* __restrict__ gate,
    void* __restrict__ Cout_,
    int M, int Ncols, int cloudLen, int epi, int outBf16,
    const int* __restrict__ ridx, float* __restrict__ gtp, int gtLc,
    const __nv_bfloat16* A2, const __nv_bfloat16* Bt2, const float* bias2, void* Cout2)
{
    constexpr int K = NK * GKT;
    extern __shared__ char smraw[];
    const __nv_bfloat16* A = A_;
    const __nv_bfloat16* Bt = Bt_;
    const float* bias = bias_;
    void* Cout = Cout_;
    if (blockIdx.z == 1) { A = A2; Bt = Bt2; bias = bias2; Cout = Cout2; }
    const int tid = threadIdx.x;
    const int lane = tid & 31;
    const int warp = tid >> 5;
    const int wm = warp >> 1, wn = warp & 1;
    const int m0 = blockIdx.y * GBM, n0 = blockIdx.x * GBN;

    float acc[2][8][4];
    #pragma unroll
    for (int i = 0; i < 2; i++)
        #pragma unroll
        for (int j = 0; j < 8; j++)
            #pragma unroll
            for (int q = 0; q < 4; q++) acc[i][j][q] = 0.f;

    const int ldrow0 = tid >> 2, ldc0 = tid & 3;
    const int ldrow1 = (tid + 256) >> 2;
    const __nv_bfloat16* gA0 = A + (size_t)(m0 + ldrow0) * K + ldc0 * 8;
    const __nv_bfloat16* gA1 = A + (size_t)(m0 + ldrow1) * K + ldc0 * 8;
    const __nv_bfloat16* gB0 = Bt + (size_t)(n0 + ldrow0) * K + ldc0 * 8;
    const __nv_bfloat16* gB1 = Bt + (size_t)(n0 + ldrow1) * K + ldc0 * 8;
    const uint32_t smemBase = smem_u32(smraw);
    const uint32_t dA0 = smemBase + ldrow0 * 80 + ldc0 * 16;
    const uint32_t dA1 = smemBase + ldrow1 * 80 + ldc0 * 16;
    const uint32_t dB0 = dA0 + 10240;
    const uint32_t dB1 = dA1 + 10240;

    uint32_t aoff[2], boff[4];
    #pragma unroll
    for (int i = 0; i < 2; i++)
        aoff[i] = smemBase + (wm * 32 + i * 16 + (lane & 15)) * 80 + (lane >> 4) * 16;
    #pragma unroll
    for (int jp = 0; jp < 4; jp++)
        boff[jp] = smemBase + 10240 + (wn * 64 + jp * 16 + (lane & 15)) * 80 + (lane >> 4) * 16;

    auto issue = [&](int s, int kt) {
        uint32_t sb = s * STG_BYTES;
        int go = kt * GKT;
        asm volatile("cp.async.cg.shared.global [%0], [%1], 16;\n" :: "r"(dA0 + sb), "l"(gA0 + go));
        asm volatile("cp.async.cg.shared.global [%0], [%1], 16;\n" :: "r"(dB0 + sb), "l"(gB0 + go));
        asm volatile("cp.async.cg.shared.global [%0], [%1], 16;\n" :: "r"(dA1 + sb), "l"(gA1 + go));
        asm volatile("cp.async.cg.shared.global [%0], [%1], 16;\n" :: "r"(dB1 + sb), "l"(gB1 + go));
        asm volatile("cp.async.commit_group;\n");
    };

    issue(0, 0);
    issue(1, 1);
    #pragma unroll
    for (int kt = 0; kt < NK; kt++) {
        const int s = kt & (NSTAGE - 1);
        if (kt + 2 < NK) {
            issue((kt + 2) & (NSTAGE - 1), kt + 2);
            asm volatile("cp.async.wait_group 2;\n");
        } else if (kt + 1 < NK) {
            asm volatile("cp.async.wait_group 1;\n");
        } else {
            asm volatile("cp.async.wait_group 0;\n");
        }
        __syncthreads();

        const uint32_t sb = s * STG_BYTES;
        #pragma unroll
        for (int kk = 0; kk < 2; kk++) {
            uint32_t af[2][4];
            #pragma unroll
            for (int i = 0; i < 2; i++) {
                asm volatile("ldmatrix.sync.aligned.m8n8.x4.shared.b16 {%0,%1,%2,%3}, [%4];"
                             : "=r"(af[i][0]), "=r"(af[i][1]), "=r"(af[i][2]), "=r"(af[i][3])
                             : "r"(aoff[i] + sb + kk * 32));
            }
            uint32_t bf[8][2];
            #pragma unroll
            for (int jp = 0; jp < 4; jp++) {
                uint32_t r0, r1, r2, r3;
                asm volatile("ldmatrix.sync.aligned.m8n8.x4.shared.b16 {%0,%1,%2,%3}, [%4];"
                             : "=r"(r0), "=r"(r1), "=r"(r2), "=r"(r3)
                             : "r"(boff[jp] + sb + kk * 32));
                bf[2*jp][0] = r0; bf[2*jp+1][0] = r1;
                bf[2*jp][1] = r2; bf[2*jp+1][1] = r3;
            }
            #pragma unroll
            for (int i = 0; i < 2; i++)
                #pragma unroll
                for (int j = 0; j < 8; j++) {
                    asm volatile("mma.sync.aligned.m16n8k16.row.col.f32.bf16.bf16.f32 "
                                 "{%0,%1,%2,%3}, {%4,%5,%6,%7}, {%8,%9}, {%0,%1,%2,%3};"
                                 : "+f"(acc[i][j][0]), "+f"(acc[i][j][1]),
                                   "+f"(acc[i][j][2]), "+f"(acc[i][j][3])
                                 : "r"(af[i][0]), "r"(af[i][1]), "r"(af[i][2]), "r"(af[i][3]),
                                   "r"(bf[j][0]), "r"(bf[j][1]));
                }
        }
    }

    const int rbase = m0 + wm * 32 + (lane >> 2);
    const int cbase = n0 + wn * 64 + 2 * (lane & 3);
    float gta[8][2];
    #pragma unroll
    for (int j = 0; j < 8; j++) { gta[j][0] = 0.f; gta[j][1] = 0.f; }

    #pragma unroll
    for (int i = 0; i < 2; i++) {
        #pragma unroll
        for (int half = 0; half < 2; half++) {
            int m = rbase + i * 16 + half * 8;
            const float* bp = (cloudLen > 0) ? (bias + (size_t)(m / cloudLen) * Ncols) : bias;
            #pragma unroll
            for (int j = 0; j < 8; j++) {
                int n = cbase + j * 8;
                float v0 = acc[i][j][half * 2 + 0] + bp[n];
                float v1 = acc[i][j][half * 2 + 1] + bp[n + 1];
                size_t o = (size_t)m * Ncols + n;
                bool stored = false;
                switch (epi) {
                    case 1: v0 = fmaxf(v0, 0.f); v1 = fmaxf(v1, 0.f); break;
                    case 2:
                        v0 = 0.5f * v0 * (1.f + erff(v0 * 0.70710678118f));
                        v1 = 0.5f * v1 * (1.f + erff(v1 * 0.70710678118f));
                        break;
                    case 3:
                        v0 = frcp_fast(1.f + fexpf_fast(-v0));
                        v1 = frcp_fast(1.f + fexpf_fast(-v1));
                        break;
                    case 4: {
                        size_t ro = (size_t)(ridx ? ridx[m] : m) * Ncols + n;
                        float2 r = *(const float2*)(resid + ro);
                        v0 += r.x; v1 += r.y;
                    } break;
                    case 5: {
                        float2 r = *(const float2*)(resid + o);
                        float2 gg = *(const float2*)(gate + o);
                        v0 = r.x + gg.x * v0; v1 = r.y + gg.y * v1;
                    } break;
                    case 6: {
                        float2 r = *(const float2*)(resid + o);
                        v0 += r.x; v1 += r.y;
                        gta[j][0] += v0; gta[j][1] += v1;
                        size_t od = (size_t)ridx[m] * Ncols + n;
                        __nv_bfloat162 h;
                        h.x = __float2bfloat16(v0); h.y = __float2bfloat16(v1);
                        *(__nv_bfloat162*)((__nv_bfloat16*)Cout + od) = h;
                        stored = true;
                    } break;
                    default: break;
                }
                if (!stored) {
                    if (outBf16) {
                        __nv_bfloat162 h;
                        h.x = __float2bfloat16(v0); h.y = __float2bfloat16(v1);
                        *(__nv_bfloat162*)((__nv_bfloat16*)Cout + o) = h;
                    } else {
                        *(float2*)((float*)Cout + o) = make_float2(v0, v1);
                    }
                }
            }
        }
    }
    if (epi == 6) {
        int c = m0 / gtLc;
        #pragma unroll
        for (int j = 0; j < 8; j++) {
            float s0 = gta[j][0], s1 = gta[j][1];
            #pragma unroll
            for (int off = 4; off <= 16; off <<= 1) {
                s0 += __shfl_xor_sync(0xffffffffu, s0, off);
                s1 += __shfl_xor_sync(0xffffffffu, s1, off);
            }
            if ((lane >> 2) == 0) {
                int n = cbase + j * 8;
                atomicAdd(gtp + c * 256 + n, s0);
                atomicAdd(gtp + c * 256 + n + 1, s1);
            }
        }
    }
}

// ---------------- flash attention (gathers rows via sidx) ----------------
#define FA_SMEM (20480 * 2 + 32 * 528)
__global__ void __launch_bounds__(256) fattn(const __nv_bfloat16* __restrict__ qkv,
                                             const int* __restrict__ sidx,
                                             __nv_bfloat16* __restrict__ o) {
    extern __shared__ char sm[];
    char* sq = sm;
    char* sk = sm + 20480;
    char* svt = sm + 40960;
    const int p = blockIdx.x, h = blockIdx.y;
    const int tid = threadIdx.x;
    const int lane = tid & 31;
    const int w = tid >> 5;
    const size_t base = (size_t)p * 256;
    const float SC = 0.17677669529663687f * 1.4426950408889634f;

    {
        const size_t src = (size_t)sidx[base + tid] * 768;
        const uint4* qr = (const uint4*)(qkv + src + h * 32);
        const uint4* kr = (const uint4*)(qkv + src + 256 + h * 32);
        const uint4* vr = (const uint4*)(qkv + src + 512 + h * 32);
        uint4* dq = (uint4*)(sq + tid * 80);
        uint4* dk = (uint4*)(sk + tid * 80);
        uint4 v0 = vr[0], v1 = vr[1], v2 = vr[2], v3 = vr[3];
        dq[0] = qr[0]; dq[1] = qr[1]; dq[2] = qr[2]; dq[3] = qr[3];
        dk[0] = kr[0]; dk[1] = kr[1]; dk[2] = kr[2]; dk[3] = kr[3];
        uint32_t vu[8] = {v0.x, v0.y, v0.z, v0.w, v1.x, v1.y, v1.z, v1.w};
        uint32_t vu2[8] = {v2.x, v2.y, v2.z, v2.w, v3.x, v3.y, v3.z, v3.w};
        #pragma unroll
        for (int e = 0; e < 8; e++) {
            ((__nv_bfloat16*)(svt + (2 * e + 0) * 528))[tid] = ((__nv_bfloat162*)&vu[e])->x;
            ((__nv_bfloat16*)(svt + (2 * e + 1) * 528))[tid] = ((__nv_bfloat162*)&vu[e])->y;
        }
        #pragma unroll
        for (int e = 0; e < 8; e++) {
            ((__nv_bfloat16*)(svt + (16 + 2 * e + 0) * 528))[tid] = ((__nv_bfloat162*)&vu2[e])->x;
            ((__nv_bfloat16*)(svt + (16 + 2 * e + 1) * 528))[tid] = ((__nv_bfloat162*)&vu2[e])->y;
        }
    }
    __syncthreads();

    const int m0w = w * 32;
    uint32_t qa[2][2][4];
    #pragma unroll
    for (int i = 0; i < 2; i++)
        #pragma unroll
        for (int kk = 0; kk < 2; kk++) {
            int r = m0w + i * 16 + (lane & 15);
            uint32_t addr = smem_u32(sq + r * 80 + kk * 32 + (lane >> 4) * 16);
            asm volatile("ldmatrix.sync.aligned.m8n8.x4.shared.b16 {%0,%1,%2,%3}, [%4];"
                         : "=r"(qa[i][kk][0]), "=r"(qa[i][kk][1]),
                           "=r"(qa[i][kk][2]), "=r"(qa[i][kk][3])
                         : "r"(addr));
        }

    float oacc[2][4][4];
    #pragma unroll
    for (int i = 0; i < 2; i++)
        #pragma unroll
        for (int d = 0; d < 4; d++)
            #pragma unroll
            for (int q = 0; q < 4; q++) oacc[i][d][q] = 0.f;
    float mrow[2][2] = {{-1e30f, -1e30f}, {-1e30f, -1e30f}};
    float lrow[2][2] = {{0.f, 0.f}, {0.f, 0.f}};

    for (int jc = 0; jc < 8; jc++) {
        uint32_t kb[2][4][2];
        #pragma unroll
        for (int jp = 0; jp < 2; jp++)
            #pragma unroll
            for (int kk = 0; kk < 2; kk++) {
                int r = jc * 32 + jp * 16 + (lane & 15);
                uint32_t addr = smem_u32(sk + r * 80 + kk * 32 + (lane >> 4) * 16);
                uint32_t r0, r1, r2, r3;
                asm volatile("ldmatrix.sync.aligned.m8n8.x4.shared.b16 {%0,%1,%2,%3}, [%4];"
                             : "=r"(r0), "=r"(r1), "=r"(r2), "=r"(r3) : "r"(addr));
                kb[kk][2*jp][0] = r0;   kb[kk][2*jp][1] = r2;
                kb[kk][2*jp+1][0] = r1; kb[kk][2*jp+1][1] = r3;
            }

        float sacc[2][4][4];
        #pragma unroll
        for (int i = 0; i < 2; i++)
            #pragma unroll
            for (int nt = 0; nt < 4; nt++)
                #pragma unroll
                for (int q = 0; q < 4; q++) sacc[i][nt][q] = 0.f;
        #pragma unroll
        for (int kk = 0; kk < 2; kk++)
            #pragma unroll
            for (int i = 0; i < 2; i++)
                #pragma unroll
                for (int nt = 0; nt < 4; nt++) {
                    asm volatile("mma.sync.aligned.m16n8k16.row.col.f32.bf16.bf16.f32 "
                                 "{%0,%1,%2,%3}, {%4,%5,%6,%7}, {%8,%9}, {%0,%1,%2,%3};"
                                 : "+f"(sacc[i][nt][0]), "+f"(sacc[i][nt][1]),
                                   "+f"(sacc[i][nt][2]), "+f"(sacc[i][nt][3])
                                 : "r"(qa[i][kk][0]), "r"(qa[i][kk][1]),
                                   "r"(qa[i][kk][2]), "r"(qa[i][kk][3]),
                                   "r"(kb[kk][nt][0]), "r"(kb[kk][nt][1]));
                }

        #pragma unroll
        for (int i = 0; i < 2; i++)
            #pragma unroll
            for (int nt = 0; nt < 4; nt++)
                #pragma unroll
                for (int q = 0; q < 4; q++) sacc[i][nt][q] *= SC;

        #pragma unroll
        for (int i = 0; i < 2; i++) {
            #pragma unroll
            for (int half = 0; half < 2; half++) {
                float mx = -1e30f;
                #pragma unroll
                for (int nt = 0; nt < 4; nt++) {
                    mx = fmaxf(mx, sacc[i][nt][half*2+0]);
                    mx = fmaxf(mx, sacc[i][nt][half*2+1]);
                }
                mx = fmaxf(mx, __shfl_xor_sync(0xffffffffu, mx, 1));
                mx = fmaxf(mx, __shfl_xor_sync(0xffffffffu, mx, 2));
                float newm = fmaxf(mrow[i][half], mx);
                float alpha = fexp2_fast(mrow[i][half] - newm);
                mrow[i][half] = newm;
                float rs = 0.f;
                #pragma unroll
                for (int nt = 0; nt < 4; nt++) {
                    float p0 = fexp2_fast(sacc[i][nt][half*2+0] - newm);
                    float p1 = fexp2_fast(sacc[i][nt][half*2+1] - newm);
                    sacc[i][nt][half*2+0] = p0;
                    sacc[i][nt][half*2+1] = p1;
                    rs += p0 + p1;
                }
                rs += __shfl_xor_sync(0xffffffffu, rs, 1);
                rs += __shfl_xor_sync(0xffffffffu, rs, 2);
                lrow[i][half] = lrow[i][half] * alpha + rs;
                #pragma unroll
                for (int dt = 0; dt < 4; dt++) {
                    oacc[i][dt][half*2+0] *= alpha;
                    oacc[i][dt][half*2+1] *= alpha;
                }
            }
        }

        uint32_t pa[2][2][4];
        #pragma unroll
        for (int i = 0; i < 2; i++)
            #pragma unroll
            for (int kk = 0; kk < 2; kk++) {
                int ntl = kk * 2, nth = kk * 2 + 1;
                __nv_bfloat162 b0 = __float22bfloat162_rn(make_float2(sacc[i][ntl][0], sacc[i][ntl][1]));
                __nv_bfloat162 b1 = __float22bfloat162_rn(make_float2(sacc[i][ntl][2], sacc[i][ntl][3]));
                __nv_bfloat162 b2 = __float22bfloat162_rn(make_float2(sacc[i][nth][0], sacc[i][nth][1]));
                __nv_bfloat162 b3 = __float22bfloat162_rn(make_float2(sacc[i][nth][2], sacc[i][nth][3]));
                pa[i][kk][0] = *(uint32_t*)&b0;
                pa[i][kk][1] = *(uint32_t*)&b1;
                pa[i][kk][2] = *(uint32_t*)&b2;
                pa[i][kk][3] = *(uint32_t*)&b3;
            }

        uint32_t vb[2][4][2];
        #pragma unroll
        for (int jp = 0; jp < 2; jp++)
            #pragma unroll
            for (int kk = 0; kk < 2; kk++) {
                int r = jp * 16 + (lane & 15);
                uint32_t addr = smem_u32(svt + r * 528 + jc * 64 + kk * 32 + (lane >> 4) * 16);
                uint32_t r0, r1, r2, r3;
                asm volatile("ldmatrix.sync.aligned.m8n8.x4.shared.b16 {%0,%1,%2,%3}, [%4];"
                             : "=r"(r0), "=r"(r1), "=r"(r2), "=r"(r3) : "r"(addr));
                vb[kk][2*jp][0] = r0;   vb[kk][2*jp][1] = r2;
                vb[kk][2*jp+1][0] = r1; vb[kk][2*jp+1][1] = r3;
            }

        #pragma unroll
        for (int kk = 0; kk < 2; kk++)
            #pragma unroll
            for (int i = 0; i < 2; i++)
                #pragma unroll
                for (int dt = 0; dt < 4; dt++) {
                    asm volatile("mma.sync.aligned.m16n8k16.row.col.f32.bf16.bf16.f32 "
                                 "{%0,%1,%2,%3}, {%4,%5,%6,%7}, {%8,%9}, {%0,%1,%2,%3};"
                                 : "+f"(oacc[i][dt][0]), "+f"(oacc[i][dt][1]),
                                   "+f"(oacc[i][dt][2]), "+f"(oacc[i][dt][3])
                                 : "r"(pa[i][kk][0]), "r"(pa[i][kk][1]),
                                   "r"(pa[i][kk][2]), "r"(pa[i][kk][3]),
                                   "r"(vb[kk][dt][0]), "r"(vb[kk][dt][1]));
                }
    }

    #pragma unroll
    for (int i = 0; i < 2; i++)
        #pragma unroll
        for (int half = 0; half < 2; half++) {
            float inv = 1.f / lrow[i][half];
            int row = m0w + i * 16 + half * 8 + (lane >> 2);
            #pragma unroll
            for (int dt = 0; dt < 4; dt++) {
                int col = h * 32 + dt * 8 + 2 * (lane & 3);
                __nv_bfloat162 hv;
                hv.x = __float2bfloat16(oacc[i][dt][half*2+0] * inv);
                hv.y = __float2bfloat16(oacc[i][dt][half*2+1] * inv);
                *(__nv_bfloat162*)(o + (base + row) * 256 + col) = hv;
            }
        }
}

// ---------------- fold gt into per-cloud biases ----------------
__global__ void cloudbias_kernel(const float* __restrict__ gtsum,
                                 const float* __restrict__ gg_w1, const float* __restrict__ gg_b1,
                                 const float* __restrict__ f_w1, const float* __restrict__ f_b1,
                                 float* __restrict__ ggb, float* __restrict__ fb, int Lc) {
    int c = blockIdx.x, j = threadIdx.x;
    float s1 = gg_b1[j], s2 = f_b1[j];
    float invL = 1.f / (float)Lc;
    for (int h = 0; h < 256; h++) {
        float gv = gtsum[c * 256 + h] * invL;
        s1 += gv * gg_w1[(size_t)(256 + h) * 256 + j];
        s2 += gv * f_w1[(size_t)(256 + h) * 256 + j];
    }
    ggb[c * 256 + j] = s1;
    fb[c * 256 + j] = s2;
}

// ---------------- launch ----------------
extern "C" void kernel_launch(void* const* d_in, const int* in_sizes, int n_in,
                              void* d_out, int out_size) {
    const float* feats = (const float*)d_in[0];
    const float* coord = (const float*)d_in[1];
    const float* pe_w1 = (const float*)d_in[3];
    const float* pe_b1 = (const float*)d_in[4];
    const float* pe_w2 = (const float*)d_in[5];
    const float* pe_b2 = (const float*)d_in[6];
    const float* pre_g = (const float*)d_in[7];
    const float* pre_b = (const float*)d_in[8];
    const float* n1_g  = (const float*)d_in[9];
    const float* n1_b  = (const float*)d_in[10];
    const float* wqkv  = (const float*)d_in[11];
    const float* bqkv  = (const float*)d_in[12];
    const float* wo    = (const float*)d_in[13];
    const float* bo    = (const float*)d_in[14];
    const float* n2_g  = (const float*)d_in[15];
    const float* n2_b  = (const float*)d_in[16];
    const float* m_w1  = (const float*)d_in[17];
    const float* m_b1  = (const float*)d_in[18];
    const float* m_w2  = (const float*)d_in[19];
    const float* m_b2  = (const float*)d_in[20];
    const float* gg_w1 = (const float*)d_in[21];
    const float* gg_b1 = (const float*)d_in[22];
    const float* gg_w2 = (const float*)d_in[23];
    const float* gg_b2 = (const float*)d_in[24];
    const float* f_w1  = (const float*)d_in[25];
    const float* f_b1  = (const float*)d_in[26];
    const float* f_w2  = (const float*)d_in[27];
    const float* f_b2  = (const float*)d_in[28];
    float* out = (float*)d_out;

    int N = in_sizes[0] / 256;
    int B = in_sizes[2];
    int Lc = N / B;
    int patches = N / 256;

    float *p_x, *p_xs, *p_key, *p_gt, *p_ggb, *p_fb, *p_stats;
    __nv_bfloat16 *p_ba, *p_bb, *p_fe, *p_wt;
    int* p_idx;
    cudaGetSymbolAddress((void**)&p_x, g_x);
    cudaGetSymbolAddress((void**)&p_xs, g_xs);
    cudaGetSymbolAddress((void**)&p_ba, g_ba);
    cudaGetSymbolAddress((void**)&p_bb, g_bb);
    cudaGetSymbolAddress((void**)&p_fe, g_fe);
    cudaGetSymbolAddress((void**)&p_wt, g_wt);
    cudaGetSymbolAddress((void**)&p_key, g_key);
    cudaGetSymbolAddress((void**)&p_idx, g_idx);
    cudaGetSymbolAddress((void**)&p_gt, g_gt);
    cudaGetSymbolAddress((void**)&p_ggb, g_ggb);
    cudaGetSymbolAddress((void**)&p_fb, g_fb);
    cudaGetSymbolAddress((void**)&p_stats, g_stats);

    __nv_bfloat16* wqkv_t = p_wt + 0;
    __nv_bfloat16* wo_t   = p_wt + 196608;
    __nv_bfloat16* mw1_t  = p_wt + 262144;
    __nv_bfloat16* mw2_t  = p_wt + 393216;
    __nv_bfloat16* ggw1_t = p_wt + 524288;
    __nv_bfloat16* ggw2_t = p_wt + 589824;
    __nv_bfloat16* fw1_t  = p_wt + 655360;
    __nv_bfloat16* fw2_t  = p_wt + 720896;
    __nv_bfloat16* bb_lo = p_bb;
    __nv_bfloat16* bb_hi = p_bb + (size_t)N * 256;

    // side stream + fork/join events for sort || qkv overlap (capture-safe pattern)
    static cudaStream_t s2 = nullptr;
    static cudaEvent_t ev1 = nullptr, ev2 = nullptr;
    if (!s2) {
        cudaStreamCreateWithFlags(&s2, cudaStreamNonBlocking);
        cudaEventCreateWithFlags(&ev1, cudaEventDisableTiming);
        cudaEventCreateWithFlags(&ev2, cudaEventDisableTiming);
    }

    cudaFuncSetAttribute(fattn, cudaFuncAttributeMaxDynamicSharedMemorySize, FA_SMEM);
    cudaFuncSetAttribute(gemm_bf16<8>, cudaFuncAttributeMaxDynamicSharedMemorySize, NSTAGE * STG_BYTES);
    cudaFuncSetAttribute(gemm_bf16<16>, cudaFuncAttributeMaxDynamicSharedMemorySize, NSTAGE * STG_BYTES);

    PrepArgs pa;
    pa.coord = coord; pa.stats = p_stats; pa.Lc = Lc; pa.B = B;
    const float* ws[8] = {wqkv, wo, m_w1, m_w2, gg_w1, gg_w2, f_w1, f_w2};
    __nv_bfloat16* wd[8] = {wqkv_t, wo_t, mw1_t, mw2_t, ggw1_t, ggw2_t, fw1_t, fw2_t};
    int wK[8] = {256, 256, 256, 512, 256, 256, 256, 256};
    int wN[8] = {768, 256, 512, 256, 256, 256, 256, 256};
    int tiles = 0;
    for (int i = 0; i < 8; i++) {
        pa.wsrc[i] = ws[i]; pa.wdst[i] = wd[i];
        pa.wK[i] = wK[i]; pa.wN[i] = wN[i];
        pa.wt0[i] = tiles;
        tiles += (wK[i] / 32) * (wN[i] / 32);
    }
    pa.totalWTiles = tiles;
    pa.gt = p_gt;

    // 1: prep
    prep_kernel<<<B + tiles + 1, 1024>>>(pa);
    // 2: PE + pre-LN + LN1 + key (original order)
    pe_ln_key_kernel<<<N, 256>>>(feats, coord, pe_w1, pe_b1, pe_w2, pe_b2,
                                 pre_g, pre_b, n1_g, n1_b, p_stats,
                                 p_x, p_bb, p_fe, p_key, p_idx, Lc);
    // fork: sort chain on s2, qkv GEMM on main — independent
    cudaEventRecord(ev1, 0);
    cudaStreamWaitEvent(s2, ev1, 0);
    // 3 (s2): local sort
    sort_local<<<N / CHUNK, 1024, CHUNK * 8, s2>>>(p_key, p_idx, Lc);
    // 4 (main): qkv GEMM (unpermuted) -> ba  [profiled launch]
    gemm_bf16<8><<<dim3(768/GBN, N/GBM), 256, NSTAGE*STG_BYTES>>>(
        p_bb, wqkv_t, bqkv, nullptr, nullptr, p_ba, N, 768, 0, 0, 1,
        nullptr, nullptr, 0, nullptr, nullptr, nullptr, nullptr);
    // (s2): finish the sort
    for (int k = CHUNK * 2; k <= Lc; k <<= 1) {
        for (int j = k >> 1; j >= CHUNK; j >>= 1)
            sort_global<<<dim3(Lc / 512, B), 256, 0, s2>>>(p_key, p_idx, k, j, Lc);
        merge_local<<<N / CHUNK, 1024, CHUNK * 8, s2>>>(p_key, p_idx, k, Lc);
    }
    cudaEventRecord(ev2, s2);
    cudaStreamWaitEvent(0, ev2, 0);
    // flash attention (gather via idx) -> bb
    fattn<<<dim3(patches, 8), 256, FA_SMEM>>>(p_ba, p_idx, p_bb);
    // wo GEMM + gathered residual -> xs fp32
    gemm_bf16<8><<<dim3(256/GBN, N/GBM), 256, NSTAGE*STG_BYTES>>>(
        p_bb, wo_t, bo, p_x, nullptr, p_xs, N, 256, 0, 4, 0,
        p_idx, nullptr, 0, nullptr, nullptr, nullptr, nullptr);
    // LN2 -> ba bf16
    ln_bf<<<N, 256>>>(p_xs, n2_g, n2_b, p_ba);
    // MLP1 + gelu -> bb
    gemm_bf16<8><<<dim3(512/GBN, N/GBM), 256, NSTAGE*STG_BYTES>>>(
        p_ba, mw1_t, m_b1, nullptr, nullptr, p_bb, N, 512, 0, 2, 1,
        nullptr, nullptr, 0, nullptr, nullptr, nullptr, nullptr);
    // MLP2 + resid; scatter xo -> ba; gt atomics
    gemm_bf16<16><<<dim3(256/GBN, N/GBM), 256, NSTAGE*STG_BYTES>>>(
        p_bb, mw2_t, m_b2, p_xs, nullptr, p_ba, N, 256, 0, 6, 1,
        p_idx, p_gt, Lc, nullptr, nullptr, nullptr, nullptr);
    // per-cloud biases
    cloudbias_kernel<<<B, 256>>>(p_gt, gg_w1, gg_b1, f_w1, f_b1, p_ggb, p_fb, Lc);
    // batched hidden GEMMs (z=0 gate, z=1 fuse)
    gemm_bf16<8><<<dim3(256/GBN, N/GBM, 2), 256, NSTAGE*STG_BYTES>>>(
        p_fe, ggw1_t, p_ggb, nullptr, nullptr, bb_lo, N, 256, Lc, 1, 1,
        nullptr, nullptr, 0, p_ba, fw1_t, p_fb, bb_hi);
    // gate sigmoid -> p_x fp32
    gemm_bf16<8><<<dim3(256/GBN, N/GBM), 256, NSTAGE*STG_BYTES>>>(
        bb_lo, ggw2_t, gg_b2, nullptr, nullptr, p_x, N, 256, 0, 3, 0,
        nullptr, nullptr, 0, nullptr, nullptr, nullptr, nullptr);
    // out = feats + gate * fused
    gemm_bf16<8><<<dim3(256/GBN, N/GBM), 256, NSTAGE*STG_BYTES>>>(
        bb_hi, fw2_t, f_b2, feats, p_x, out, N, 256, 0, 5, 0,
        nullptr, nullptr, 0, nullptr, nullptr, nullptr, nullptr);
}